// round 1
// baseline (speedup 1.0000x reference)
#include <cuda_runtime.h>
#include <math.h>

#define BATCH 128
#define NNODES 1024
#define NTRI 1023
#define T3 3069

// Persistent scratch (no cudaMalloc allowed). Node-major activations:
// [tower*128+b][node][C], node 0 is the zero node for act1/2/3.
__device__ float g_act0[(size_t)2*BATCH*NNODES*64];    //  64 MB
__device__ float g_act1[(size_t)2*BATCH*NNODES*256];   // 256 MB
__device__ float g_act2[(size_t)2*BATCH*NNODES*128];   // 128 MB
__device__ float g_act3[(size_t)2*BATCH*NNODES*64];    //  64 MB
__device__ float g_wrt1[256*192];   // [CK][O] transposed weights
__device__ float g_wrt2[128*768];
__device__ float g_wrt3[64*384];
__device__ float g_st1[2*BATCH*2];  // {mean, 1/(std+1e-5)} per (tower,b)
__device__ float g_st2[2*BATCH*2];
__device__ float g_st3[2*BATCH*2];

// ---------------------------------------------------------------------------
// Transpose raw input [b][C=64][N=1024] -> act0 [tower*128+b][N][64]
// ---------------------------------------------------------------------------
__global__ __launch_bounds__(256) void transpose_kernel(
    const float* __restrict__ d1, const float* __restrict__ d2,
    float* __restrict__ act0)
{
    __shared__ float tile[32][33];
    int tb = blockIdx.z;
    int tower = tb / BATCH, b = tb % BATCH;
    const float* src = (tower ? d2 : d1) + (size_t)b * 64 * NNODES; // [64][1024]
    float* dst = act0 + (size_t)tb * NNODES * 64;                   // [1024][64]
    int n0 = blockIdx.x * 32, c0 = blockIdx.y * 32;
    for (int i = threadIdx.y; i < 32; i += 8)
        tile[i][threadIdx.x] = src[(size_t)(c0 + i) * NNODES + n0 + threadIdx.x];
    __syncthreads();
    for (int i = threadIdx.y; i < 32; i += 8)
        dst[(size_t)(n0 + i) * 64 + c0 + threadIdx.x] = tile[threadIdx.x][i];
}

// ---------------------------------------------------------------------------
// Reorder conv weights: w[o][c][k] -> wrt[ck][o] with ck = k*C + c
// ---------------------------------------------------------------------------
__global__ void reorder_w(const float* __restrict__ w, float* __restrict__ wrt,
                          int O, int C)
{
    int i = blockIdx.x * blockDim.x + threadIdx.x;
    int CK = C * 3;
    if (i < O * CK) {
        int ck = i / O, o = i - ck * O;
        int k = ck / C, c = ck - k * C;
        wrt[i] = w[(o * C + c) * 3 + k];
    }
}

// ---------------------------------------------------------------------------
// Zero the "zero node" row (node 0) of act1/2/3 for every (tower, b)
// ---------------------------------------------------------------------------
__global__ void zero_rows(float* a1, float* a2, float* a3)
{
    int tb = blockIdx.x;
    for (int i = threadIdx.x; i < 256; i += blockDim.x) a1[(size_t)tb * NNODES * 256 + i] = 0.f;
    for (int i = threadIdx.x; i < 128; i += blockDim.x) a2[(size_t)tb * NNODES * 128 + i] = 0.f;
    for (int i = threadIdx.x; i <  64; i += blockDim.x) a3[(size_t)tb * NNODES *  64 + i] = 0.f;
}

// ---------------------------------------------------------------------------
// Gather-conv GEMM. Per block: one (tower,b), 32 triples, all O outputs.
//   out[o][m] = sum_ck wrt[ck][o] * g[m][ck],  g = gathered (optionally
//   LayerNorm+leakyReLU transformed) node rows.
// SMEM: g_s [32][3C] + w_s [64][O] (linear copy from pre-transposed weights).
// ---------------------------------------------------------------------------
template<int C, int O, bool LN>
__global__ __launch_bounds__(256) void conv_kernel(
    const float* __restrict__ actin,
    const int* __restrict__ idxA, const int* __restrict__ idxB,
    const float* __restrict__ wrt,      // [CK][O]
    const float* __restrict__ bias,     // [O]
    const float* __restrict__ stats,    // [2*BATCH][2] or unused
    float* __restrict__ actout)         // [2*BATCH][NNODES][O]
{
    constexpr int TM = 32;
    constexpr int CK = 3 * C;
    constexpr int KT = 64;
    constexpr int TOpt = O / 32;   // 8 / 4 / 2
    constexpr int TMpt = 4;        // each warp covers 4 triples

    extern __shared__ float smem[];
    float* g_s = smem;             // [TM][CK]
    float* w_s = smem + TM * CK;   // [KT][O]
    __shared__ int nodes[TM * 3];

    const int tid = threadIdx.x;
    const int m0 = blockIdx.x * TM;
    const int b = blockIdx.y;
    const int tower = blockIdx.z;
    const int tb = tower * BATCH + b;

    const int* idx = (tower ? idxB : idxA) + b * T3;
    const float* ain = actin + (size_t)tb * NNODES * C;

    float mean = 0.f, inv = 0.f;
    if (LN) { mean = stats[tb * 2]; inv = stats[tb * 2 + 1]; }

    if (tid < TM * 3) {
        int t = m0 * 3 + tid;
        nodes[tid] = (t < T3) ? idx[t] : 0;
    }
    __syncthreads();

    // Gather (coalesced row copies) with fused LN + leakyReLU
    constexpr int C4 = C / 4;
    for (int e = tid; e < TM * 3 * C4; e += 256) {
        int r = e / C4, c4 = e - r * C4;
        float4 v = reinterpret_cast<const float4*>(ain + (size_t)nodes[r] * C)[c4];
        if (LN) {
            v.x = (v.x - mean) * inv; v.x = v.x > 0.f ? v.x : 0.01f * v.x;
            v.y = (v.y - mean) * inv; v.y = v.y > 0.f ? v.y : 0.01f * v.y;
            v.z = (v.z - mean) * inv; v.z = v.z > 0.f ? v.z : 0.01f * v.z;
            v.w = (v.w - mean) * inv; v.w = v.w > 0.f ? v.w : 0.01f * v.w;
        }
        reinterpret_cast<float4*>(g_s)[e] = v;
    }

    float acc[TOpt][TMpt];
#pragma unroll
    for (int i = 0; i < TOpt; i++)
#pragma unroll
        for (int j = 0; j < TMpt; j++) acc[i][j] = 0.f;

    const int lane = tid & 31;
    const int warp = tid >> 5;
    const float* grow = g_s + (warp * TMpt) * CK;

    for (int ck0 = 0; ck0 < CK; ck0 += KT) {
        __syncthreads();
        {
            const float4* wsrc4 = reinterpret_cast<const float4*>(wrt + (size_t)ck0 * O);
            float4* wdst4 = reinterpret_cast<float4*>(w_s);
            for (int e = tid; e < KT * O / 4; e += 256) wdst4[e] = wsrc4[e];
        }
        __syncthreads();
#pragma unroll 8
        for (int kk = 0; kk < KT; kk++) {
            float gv[TMpt];
#pragma unroll
            for (int j = 0; j < TMpt; j++) gv[j] = grow[j * CK + ck0 + kk];
            const float* wrow = w_s + kk * O + lane;
#pragma unroll
            for (int i = 0; i < TOpt; i++) {
                float wv = wrow[32 * i];
#pragma unroll
                for (int j = 0; j < TMpt; j++)
                    acc[i][j] = fmaf(wv, gv[j], acc[i][j]);
            }
        }
    }

    float* aout = actout + (size_t)tb * NNODES * O;
#pragma unroll
    for (int j = 0; j < TMpt; j++) {
        int mt = m0 + warp * TMpt + j;
        if (mt < NTRI) {
#pragma unroll
            for (int i = 0; i < TOpt; i++) {
                int o = lane + 32 * i;
                aout[(size_t)(mt + 1) * O + o] = acc[i][j] + bias[o];
            }
        }
    }
}

// ---------------------------------------------------------------------------
// Per-(tower,b) mean / 1/(unbiased std + 1e-5) over [NNODES][O]
// ---------------------------------------------------------------------------
__global__ __launch_bounds__(256) void stats_kernel(
    const float* __restrict__ act, float* __restrict__ stats, int O)
{
    int tb = blockIdx.x;
    const float4* a = reinterpret_cast<const float4*>(act + (size_t)tb * NNODES * O);
    int n4 = NNODES * O / 4;
    double s = 0.0, ss = 0.0;
    for (int i = threadIdx.x; i < n4; i += 256) {
        float4 v = a[i];
        s += (double)v.x + (double)v.y + (double)v.z + (double)v.w;
        ss += (double)v.x * v.x + (double)v.y * v.y + (double)v.z * v.z + (double)v.w * v.w;
    }
    __shared__ double sh[512];
    sh[threadIdx.x] = s;
    sh[256 + threadIdx.x] = ss;
    __syncthreads();
    for (int off = 128; off > 0; off >>= 1) {
        if (threadIdx.x < off) {
            sh[threadIdx.x] += sh[threadIdx.x + off];
            sh[256 + threadIdx.x] += sh[256 + threadIdx.x + off];
        }
        __syncthreads();
    }
    if (threadIdx.x == 0) {
        double n = (double)NNODES * O;
        double mean = sh[0] / n;
        double var = (sh[256] - sh[0] * sh[0] / n) / (n - 1.0);
        if (var < 0.0) var = 0.0;
        stats[tb * 2] = (float)mean;
        stats[tb * 2 + 1] = (float)(1.0 / (sqrt(var) + 1e-5));
    }
}

// ---------------------------------------------------------------------------
// Final: LN(act3) -> channel max over nodes -> FC1(lrelu) -> FC2 ->
//        sigmoid(y_tower0 - y_tower1). One block per batch element.
// ---------------------------------------------------------------------------
__global__ __launch_bounds__(256) void final_kernel(
    const float* __restrict__ act3, const float* __restrict__ stats3,
    const float* __restrict__ wfc1, const float* __restrict__ bfc1,
    const float* __restrict__ wfc2, const float* __restrict__ bfc2,
    float* __restrict__ out)
{
    int b = blockIdx.x;
    int tid = threadIdx.x;
    __shared__ float mx[4][64];
    __shared__ float h[32];
    __shared__ float yy[2];

    for (int tower = 0; tower < 2; tower++) {
        int tb = tower * BATCH + b;
        float mean = stats3[tb * 2], inv = stats3[tb * 2 + 1];
        const float* a = act3 + (size_t)tb * NNODES * 64;
        int c = tid & 63, grp = tid >> 6;
        float m = -1e30f;
        for (int n = grp; n < NNODES; n += 4) {
            float v = (a[(size_t)n * 64 + c] - mean) * inv;
            m = fmaxf(m, v);
        }
        mx[grp][c] = m;
        __syncthreads();
        if (tid < 64) {
            mx[0][tid] = fmaxf(fmaxf(mx[0][tid], mx[1][tid]),
                               fmaxf(mx[2][tid], mx[3][tid]));
        }
        __syncthreads();
        if (tid < 32) {
            float sAcc = bfc1[tid];
            for (int c2 = 0; c2 < 64; c2++) sAcc = fmaf(mx[0][c2], wfc1[tid * 64 + c2], sAcc);
            h[tid] = sAcc > 0.f ? sAcc : 0.01f * sAcc;
        }
        __syncthreads();
        if (tid == 0) {
            float sAcc = bfc2[0];
            for (int i = 0; i < 32; i++) sAcc = fmaf(h[i], wfc2[i], sAcc);
            yy[tower] = sAcc;
        }
        __syncthreads();
    }
    if (tid == 0) {
        float d = yy[0] - yy[1];
        out[b] = 1.f / (1.f + expf(-d));
    }
}

// ---------------------------------------------------------------------------
extern "C" void kernel_launch(void* const* d_in, const int* in_sizes, int n_in,
                              void* d_out, int out_size)
{
    const float* data1 = (const float*)d_in[0];
    const int*   idx1  = (const int*)d_in[1];
    const float* data2 = (const float*)d_in[2];
    const int*   idx2  = (const int*)d_in[3];
    const float* w1 = (const float*)d_in[4];
    const float* b1 = (const float*)d_in[5];
    const float* w2 = (const float*)d_in[6];
    const float* b2 = (const float*)d_in[7];
    const float* w3 = (const float*)d_in[8];
    const float* b3 = (const float*)d_in[9];
    const float* wfc1 = (const float*)d_in[10];
    const float* bfc1 = (const float*)d_in[11];
    const float* wfc2 = (const float*)d_in[12];
    const float* bfc2 = (const float*)d_in[13];
    float* out = (float*)d_out;

    float *act0, *act1, *act2, *act3, *wrt1, *wrt2, *wrt3, *st1, *st2, *st3;
    cudaGetSymbolAddress((void**)&act0, g_act0);
    cudaGetSymbolAddress((void**)&act1, g_act1);
    cudaGetSymbolAddress((void**)&act2, g_act2);
    cudaGetSymbolAddress((void**)&act3, g_act3);
    cudaGetSymbolAddress((void**)&wrt1, g_wrt1);
    cudaGetSymbolAddress((void**)&wrt2, g_wrt2);
    cudaGetSymbolAddress((void**)&wrt3, g_wrt3);
    cudaGetSymbolAddress((void**)&st1, g_st1);
    cudaGetSymbolAddress((void**)&st2, g_st2);
    cudaGetSymbolAddress((void**)&st3, g_st3);

    // Dynamic SMEM opt-in (>48KB)
    cudaFuncSetAttribute(conv_kernel<64, 256, false>,
                         cudaFuncAttributeMaxDynamicSharedMemorySize, 90112);
    cudaFuncSetAttribute(conv_kernel<256, 128, true>,
                         cudaFuncAttributeMaxDynamicSharedMemorySize, 131072);
    cudaFuncSetAttribute(conv_kernel<128, 64, true>,
                         cudaFuncAttributeMaxDynamicSharedMemorySize, 65536);

    transpose_kernel<<<dim3(32, 2, 256), dim3(32, 8)>>>(data1, data2, act0);
    reorder_w<<<(256 * 192 + 255) / 256, 256>>>(w1, wrt1, 256, 64);
    reorder_w<<<(128 * 768 + 255) / 256, 256>>>(w2, wrt2, 128, 256);
    reorder_w<<<(64 * 384 + 255) / 256, 256>>>(w3, wrt3, 64, 128);
    zero_rows<<<256, 256>>>(act1, act2, act3);

    conv_kernel<64, 256, false><<<dim3(32, BATCH, 2), 256, 90112>>>(
        act0, idx1, idx2, wrt1, b1, st1 /*unused*/, act1);
    stats_kernel<<<256, 256>>>(act1, st1, 256);

    conv_kernel<256, 128, true><<<dim3(32, BATCH, 2), 256, 131072>>>(
        act1, idx1, idx2, wrt2, b2, st1, act2);
    stats_kernel<<<256, 256>>>(act2, st2, 128);

    conv_kernel<128, 64, true><<<dim3(32, BATCH, 2), 256, 65536>>>(
        act2, idx1, idx2, wrt3, b3, st2, act3);
    stats_kernel<<<256, 256>>>(act3, st3, 64);

    final_kernel<<<BATCH, 256>>>(act3, st3, wfc1, bfc1, wfc2, bfc2, out);
}

// round 2
// speedup vs baseline: 1.1547x; 1.1547x over previous
#include <cuda_runtime.h>
#include <math.h>

#define BATCH 128
#define NNODES 1024
#define NTRI 1023
#define T3 3069

// Persistent scratch (no cudaMalloc allowed). Node-major activations:
// [tower*128+b][node][C], node 0 is the shared zero node for act1/2/3.
__device__ float g_act0[(size_t)2*BATCH*NNODES*64];    //  64 MB
__device__ float g_act1[(size_t)2*BATCH*NNODES*256];   // 256 MB
__device__ float g_act2[(size_t)2*BATCH*NNODES*128];   // 128 MB
__device__ float g_act3[(size_t)2*BATCH*NNODES*64];    //  64 MB
__device__ float g_wrt1[256*192];   // [CK][O] transposed weights
__device__ float g_wrt2[128*768];
__device__ float g_wrt3[64*384];
__device__ float g_st1[2*BATCH*2];  // {mean, 1/(std+1e-5)} per (tower,b)
__device__ float g_st2[2*BATCH*2];
__device__ float g_st3[2*BATCH*2];

// ---- packed f32x2 helpers (FFMA2 exists only via PTX) ----------------------
__device__ __forceinline__ unsigned long long pack2(float x, float y) {
    unsigned long long r;
    asm("mov.b64 %0, {%1, %2};" : "=l"(r) : "f"(x), "f"(y));
    return r;
}
__device__ __forceinline__ void fma_f32x2(unsigned long long& d,
                                          unsigned long long a,
                                          unsigned long long b) {
    asm("fma.rn.f32x2 %0, %1, %2, %0;" : "+l"(d) : "l"(a), "l"(b));
}
__device__ __forceinline__ float2 unpack2(unsigned long long v) {
    float2 f;
    asm("mov.b64 {%0, %1}, %2;" : "=f"(f.x), "=f"(f.y) : "l"(v));
    return f;
}

// ---------------------------------------------------------------------------
// Transpose raw input [b][C=64][N=1024] -> act0 [tower*128+b][N][64]
// ---------------------------------------------------------------------------
__global__ __launch_bounds__(256) void transpose_kernel(
    const float* __restrict__ d1, const float* __restrict__ d2,
    float* __restrict__ act0)
{
    __shared__ float tile[32][33];
    int tb = blockIdx.z;
    int tower = tb / BATCH, b = tb % BATCH;
    const float* src = (tower ? d2 : d1) + (size_t)b * 64 * NNODES; // [64][1024]
    float* dst = act0 + (size_t)tb * NNODES * 64;                   // [1024][64]
    int n0 = blockIdx.x * 32, c0 = blockIdx.y * 32;
    for (int i = threadIdx.y; i < 32; i += 8)
        tile[i][threadIdx.x] = src[(size_t)(c0 + i) * NNODES + n0 + threadIdx.x];
    __syncthreads();
    for (int i = threadIdx.y; i < 32; i += 8)
        dst[(size_t)(n0 + i) * 64 + c0 + threadIdx.x] = tile[threadIdx.x][i];
}

// ---------------------------------------------------------------------------
// Reorder conv weights: w[o][c][k] -> wrt[ck][o] with ck = k*C + c
// ---------------------------------------------------------------------------
__global__ void reorder_w(const float* __restrict__ w, float* __restrict__ wrt,
                          int O, int C)
{
    int i = blockIdx.x * blockDim.x + threadIdx.x;
    int CK = C * 3;
    if (i < O * CK) {
        int ck = i / O, o = i - ck * O;
        int k = ck / C, c = ck - k * C;
        wrt[i] = w[(o * C + c) * 3 + k];
    }
}

// ---------------------------------------------------------------------------
// Zero the "zero node" row (node 0) of act1/2/3 for every (tower, b)
// ---------------------------------------------------------------------------
__global__ void zero_rows(float* a1, float* a2, float* a3)
{
    int tb = blockIdx.x;
    for (int i = threadIdx.x; i < 256; i += blockDim.x) a1[(size_t)tb * NNODES * 256 + i] = 0.f;
    for (int i = threadIdx.x; i < 128; i += blockDim.x) a2[(size_t)tb * NNODES * 128 + i] = 0.f;
    for (int i = threadIdx.x; i <  64; i += blockDim.x) a3[(size_t)tb * NNODES *  64 + i] = 0.f;
}

// ---------------------------------------------------------------------------
// Gather-conv GEMM with packed f32x2 accumulation.
// Per block: one (tower,b), 32 triples, all O outputs.
//   out[o][m] = sum_ck wrt[ck][o] * g[m][ck]
// Each lane owns output pairs o = 64*i + 2*lane (i < O/64) for 4 triples.
// ---------------------------------------------------------------------------
template<int C, int O, bool LN>
__global__ __launch_bounds__(256) void conv_kernel(
    const float* __restrict__ actin,
    const int* __restrict__ idxA, const int* __restrict__ idxB,
    const float* __restrict__ wrt,      // [CK][O]
    const float* __restrict__ bias,     // [O]
    const float* __restrict__ stats,    // [2*BATCH][2] or unused
    float* __restrict__ actout)         // [2*BATCH][NNODES][O]
{
    constexpr int TM = 32;
    constexpr int CK = 3 * C;
    constexpr int KT = 64;
    constexpr int TO2 = O / 64;    // packed output pairs per lane: 4 / 2 / 1
    constexpr int TMpt = 4;        // triples per warp

    extern __shared__ float smem[];
    float* g_s = smem;             // [TM][CK]
    float* w_s = smem + TM * CK;   // [KT][O]
    __shared__ int nodes[TM * 3];

    const int tid = threadIdx.x;
    const int m0 = blockIdx.x * TM;
    const int b = blockIdx.y;
    const int tower = blockIdx.z;
    const int tb = tower * BATCH + b;

    const int* idx = (tower ? idxB : idxA) + b * T3;
    const float* ain = actin + (size_t)tb * NNODES * C;

    float mean = 0.f, inv = 0.f;
    if (LN) { mean = stats[tb * 2]; inv = stats[tb * 2 + 1]; }

    if (tid < TM * 3) {
        int t = m0 * 3 + tid;
        nodes[tid] = (t < T3) ? idx[t] : 0;
    }
    __syncthreads();

    // Gather (coalesced row copies) with fused LN + leakyReLU
    constexpr int C4 = C / 4;
    for (int e = tid; e < TM * 3 * C4; e += 256) {
        int r = e / C4, c4 = e - r * C4;
        float4 v = reinterpret_cast<const float4*>(ain + (size_t)nodes[r] * C)[c4];
        if (LN) {
            v.x = (v.x - mean) * inv; v.x = v.x > 0.f ? v.x : 0.01f * v.x;
            v.y = (v.y - mean) * inv; v.y = v.y > 0.f ? v.y : 0.01f * v.y;
            v.z = (v.z - mean) * inv; v.z = v.z > 0.f ? v.z : 0.01f * v.z;
            v.w = (v.w - mean) * inv; v.w = v.w > 0.f ? v.w : 0.01f * v.w;
        }
        reinterpret_cast<float4*>(g_s)[e] = v;
    }

    unsigned long long acc[TO2][TMpt];
#pragma unroll
    for (int i = 0; i < TO2; i++)
#pragma unroll
        for (int j = 0; j < TMpt; j++) acc[i][j] = 0ull;

    const int lane = tid & 31;
    const int warp = tid >> 5;
    const float* grow = g_s + (warp * TMpt) * CK;

    for (int ck0 = 0; ck0 < CK; ck0 += KT) {
        __syncthreads();
        {
            const float4* wsrc4 = reinterpret_cast<const float4*>(wrt + (size_t)ck0 * O);
            float4* wdst4 = reinterpret_cast<float4*>(w_s);
#pragma unroll 4
            for (int e = tid; e < KT * O / 4; e += 256) wdst4[e] = wsrc4[e];
        }
        __syncthreads();
#pragma unroll 8
        for (int kk = 0; kk < KT; kk++) {
            unsigned long long gvv[TMpt];
#pragma unroll
            for (int j = 0; j < TMpt; j++) {
                float g = grow[j * CK + ck0 + kk];
                gvv[j] = pack2(g, g);
            }
            const float* wrow = w_s + kk * O + 2 * lane;
#pragma unroll
            for (int i = 0; i < TO2; i++) {
                unsigned long long wp =
                    *reinterpret_cast<const unsigned long long*>(wrow + 64 * i);
#pragma unroll
                for (int j = 0; j < TMpt; j++)
                    fma_f32x2(acc[i][j], wp, gvv[j]);
            }
        }
    }

    // Bias pairs for this lane
    float2 bv[TO2];
#pragma unroll
    for (int i = 0; i < TO2; i++) {
        int o = 64 * i + 2 * lane;
        bv[i] = *reinterpret_cast<const float2*>(bias + o);
    }

    float* aout = actout + (size_t)tb * NNODES * O;
#pragma unroll
    for (int j = 0; j < TMpt; j++) {
        int mt = m0 + warp * TMpt + j;
        if (mt < NTRI) {
#pragma unroll
            for (int i = 0; i < TO2; i++) {
                int o = 64 * i + 2 * lane;
                float2 v = unpack2(acc[i][j]);
                v.x += bv[i].x;
                v.y += bv[i].y;
                *reinterpret_cast<float2*>(aout + (size_t)(mt + 1) * O + o) = v;
            }
        }
    }
}

// ---------------------------------------------------------------------------
// Per-(tower,b) mean / 1/(unbiased std + 1e-5) over [NNODES][O]
// ---------------------------------------------------------------------------
__global__ __launch_bounds__(256) void stats_kernel(
    const float* __restrict__ act, float* __restrict__ stats, int O)
{
    int tb = blockIdx.x;
    const float4* a = reinterpret_cast<const float4*>(act + (size_t)tb * NNODES * O);
    int n4 = NNODES * O / 4;
    double s = 0.0, ss = 0.0;
    for (int i = threadIdx.x; i < n4; i += 256) {
        float4 v = a[i];
        s += (double)v.x + (double)v.y + (double)v.z + (double)v.w;
        ss += (double)v.x * v.x + (double)v.y * v.y + (double)v.z * v.z + (double)v.w * v.w;
    }
    __shared__ double sh[512];
    sh[threadIdx.x] = s;
    sh[256 + threadIdx.x] = ss;
    __syncthreads();
    for (int off = 128; off > 0; off >>= 1) {
        if (threadIdx.x < off) {
            sh[threadIdx.x] += sh[threadIdx.x + off];
            sh[256 + threadIdx.x] += sh[256 + threadIdx.x + off];
        }
        __syncthreads();
    }
    if (threadIdx.x == 0) {
        double n = (double)NNODES * O;
        double mean = sh[0] / n;
        double var = (sh[256] - sh[0] * sh[0] / n) / (n - 1.0);
        if (var < 0.0) var = 0.0;
        stats[tb * 2] = (float)mean;
        stats[tb * 2 + 1] = (float)(1.0 / (sqrt(var) + 1e-5));
    }
}

// ---------------------------------------------------------------------------
// Final: LN(act3) -> channel max over nodes -> FC1(lrelu) -> FC2 ->
//        sigmoid(y_tower0 - y_tower1). One block per batch element.
// ---------------------------------------------------------------------------
__global__ __launch_bounds__(256) void final_kernel(
    const float* __restrict__ act3, const float* __restrict__ stats3,
    const float* __restrict__ wfc1, const float* __restrict__ bfc1,
    const float* __restrict__ wfc2, const float* __restrict__ bfc2,
    float* __restrict__ out)
{
    int b = blockIdx.x;
    int tid = threadIdx.x;
    __shared__ float mx[4][64];
    __shared__ float h[32];
    __shared__ float yy[2];

    for (int tower = 0; tower < 2; tower++) {
        int tb = tower * BATCH + b;
        float mean = stats3[tb * 2], inv = stats3[tb * 2 + 1];
        const float* a = act3 + (size_t)tb * NNODES * 64;
        int c = tid & 63, grp = tid >> 6;
        float m = -1e30f;
        for (int n = grp; n < NNODES; n += 4) {
            float v = (a[(size_t)n * 64 + c] - mean) * inv;
            m = fmaxf(m, v);
        }
        mx[grp][c] = m;
        __syncthreads();
        if (tid < 64) {
            mx[0][tid] = fmaxf(fmaxf(mx[0][tid], mx[1][tid]),
                               fmaxf(mx[2][tid], mx[3][tid]));
        }
        __syncthreads();
        if (tid < 32) {
            float sAcc = bfc1[tid];
            for (int c2 = 0; c2 < 64; c2++) sAcc = fmaf(mx[0][c2], wfc1[tid * 64 + c2], sAcc);
            h[tid] = sAcc > 0.f ? sAcc : 0.01f * sAcc;
        }
        __syncthreads();
        if (tid == 0) {
            float sAcc = bfc2[0];
            for (int i = 0; i < 32; i++) sAcc = fmaf(h[i], wfc2[i], sAcc);
            yy[tower] = sAcc;
        }
        __syncthreads();
    }
    if (tid == 0) {
        float d = yy[0] - yy[1];
        out[b] = 1.f / (1.f + expf(-d));
    }
}

// ---------------------------------------------------------------------------
extern "C" void kernel_launch(void* const* d_in, const int* in_sizes, int n_in,
                              void* d_out, int out_size)
{
    const float* data1 = (const float*)d_in[0];
    const int*   idx1  = (const int*)d_in[1];
    const float* data2 = (const float*)d_in[2];
    const int*   idx2  = (const int*)d_in[3];
    const float* w1 = (const float*)d_in[4];
    const float* b1 = (const float*)d_in[5];
    const float* w2 = (const float*)d_in[6];
    const float* b2 = (const float*)d_in[7];
    const float* w3 = (const float*)d_in[8];
    const float* b3 = (const float*)d_in[9];
    const float* wfc1 = (const float*)d_in[10];
    const float* bfc1 = (const float*)d_in[11];
    const float* wfc2 = (const float*)d_in[12];
    const float* bfc2 = (const float*)d_in[13];
    float* out = (float*)d_out;

    float *act0, *act1, *act2, *act3, *wrt1, *wrt2, *wrt3, *st1, *st2, *st3;
    cudaGetSymbolAddress((void**)&act0, g_act0);
    cudaGetSymbolAddress((void**)&act1, g_act1);
    cudaGetSymbolAddress((void**)&act2, g_act2);
    cudaGetSymbolAddress((void**)&act3, g_act3);
    cudaGetSymbolAddress((void**)&wrt1, g_wrt1);
    cudaGetSymbolAddress((void**)&wrt2, g_wrt2);
    cudaGetSymbolAddress((void**)&wrt3, g_wrt3);
    cudaGetSymbolAddress((void**)&st1, g_st1);
    cudaGetSymbolAddress((void**)&st2, g_st2);
    cudaGetSymbolAddress((void**)&st3, g_st3);

    // Dynamic SMEM opt-in (>48KB)
    cudaFuncSetAttribute(conv_kernel<64, 256, false>,
                         cudaFuncAttributeMaxDynamicSharedMemorySize, 90112);
    cudaFuncSetAttribute(conv_kernel<256, 128, true>,
                         cudaFuncAttributeMaxDynamicSharedMemorySize, 131072);
    cudaFuncSetAttribute(conv_kernel<128, 64, true>,
                         cudaFuncAttributeMaxDynamicSharedMemorySize, 65536);

    transpose_kernel<<<dim3(32, 2, 256), dim3(32, 8)>>>(data1, data2, act0);
    reorder_w<<<(256 * 192 + 255) / 256, 256>>>(w1, wrt1, 256, 64);
    reorder_w<<<(128 * 768 + 255) / 256, 256>>>(w2, wrt2, 128, 256);
    reorder_w<<<(64 * 384 + 255) / 256, 256>>>(w3, wrt3, 64, 128);
    zero_rows<<<256, 256>>>(act1, act2, act3);

    conv_kernel<64, 256, false><<<dim3(32, BATCH, 2), 256, 90112>>>(
        act0, idx1, idx2, wrt1, b1, st1 /*unused*/, act1);
    stats_kernel<<<256, 256>>>(act1, st1, 256);

    conv_kernel<256, 128, true><<<dim3(32, BATCH, 2), 256, 131072>>>(
        act1, idx1, idx2, wrt2, b2, st1, act2);
    stats_kernel<<<256, 256>>>(act2, st2, 128);

    conv_kernel<128, 64, true><<<dim3(32, BATCH, 2), 256, 65536>>>(
        act2, idx1, idx2, wrt3, b3, st2, act3);
    stats_kernel<<<256, 256>>>(act3, st3, 64);

    final_kernel<<<BATCH, 256>>>(act3, st3, wfc1, bfc1, wfc2, bfc2, out);
}

// round 3
// speedup vs baseline: 1.1550x; 1.0003x over previous
#include <cuda_runtime.h>
#include <math.h>

#define BATCH 128
#define NNODES 1024
#define NTRI 1023
#define T3 3069

typedef unsigned long long u64;

// Persistent scratch. Node-major activations: [tower*128+b][node][C],
// node 0 is the shared zero node for act1/2/3.
__device__ float g_act0[(size_t)2*BATCH*NNODES*64];    //  64 MB
__device__ float g_act1[(size_t)2*BATCH*NNODES*256];   // 256 MB
__device__ float g_act2[(size_t)2*BATCH*NNODES*128];   // 128 MB
__device__ float g_act3[(size_t)2*BATCH*NNODES*64];    //  64 MB
__device__ float g_wrt1[256*192];   // [O][CK] weights, ck = k*C + c
__device__ float g_wrt2[128*768];
__device__ float g_wrt3[64*384];
__device__ float g_st1[2*BATCH*2];  // {mean, 1/(std+1e-5)} per (tower,b)
__device__ float g_st2[2*BATCH*2];
__device__ float g_st3[2*BATCH*2];

// ---- packed f32x2 helpers ---------------------------------------------------
__device__ __forceinline__ void fma_f32x2(u64& d, u64 a, u64 b) {
    asm("fma.rn.f32x2 %0, %1, %2, %0;" : "+l"(d) : "l"(a), "l"(b));
}
__device__ __forceinline__ float2 unpack2(u64 v) {
    float2 f;
    asm("mov.b64 {%0, %1}, %2;" : "=f"(f.x), "=f"(f.y) : "l"(v));
    return f;
}

// ---------------------------------------------------------------------------
// Transpose raw input [b][C=64][N=1024] -> act0 [tower*128+b][N][64]
// ---------------------------------------------------------------------------
__global__ __launch_bounds__(256) void transpose_kernel(
    const float* __restrict__ d1, const float* __restrict__ d2,
    float* __restrict__ act0)
{
    __shared__ float tile[32][33];
    int tb = blockIdx.z;
    int tower = tb / BATCH, b = tb % BATCH;
    const float* src = (tower ? d2 : d1) + (size_t)b * 64 * NNODES; // [64][1024]
    float* dst = act0 + (size_t)tb * NNODES * 64;                   // [1024][64]
    int n0 = blockIdx.x * 32, c0 = blockIdx.y * 32;
    for (int i = threadIdx.y; i < 32; i += 8)
        tile[i][threadIdx.x] = src[(size_t)(c0 + i) * NNODES + n0 + threadIdx.x];
    __syncthreads();
    for (int i = threadIdx.y; i < 32; i += 8)
        dst[(size_t)(n0 + i) * 64 + c0 + threadIdx.x] = tile[threadIdx.x][i];
}

// ---------------------------------------------------------------------------
// Reorder conv weights: w[o][c][k] -> wrt[o][ck] with ck = k*C + c
// ---------------------------------------------------------------------------
__global__ void reorder_w(const float* __restrict__ w, float* __restrict__ wrt,
                          int O, int C)
{
    int i = blockIdx.x * blockDim.x + threadIdx.x;
    int CK = C * 3;
    if (i < O * CK) {
        int o = i / CK, ck = i - o * CK;
        int k = ck / C, c = ck - k * C;
        wrt[i] = w[(o * C + c) * 3 + k];
    }
}

// ---------------------------------------------------------------------------
// Zero the "zero node" row (node 0) of act1/2/3 for every (tower, b)
// ---------------------------------------------------------------------------
__global__ void zero_rows(float* a1, float* a2, float* a3)
{
    int tb = blockIdx.x;
    for (int i = threadIdx.x; i < 256; i += blockDim.x) a1[(size_t)tb * NNODES * 256 + i] = 0.f;
    for (int i = threadIdx.x; i < 128; i += blockDim.x) a2[(size_t)tb * NNODES * 128 + i] = 0.f;
    for (int i = threadIdx.x; i <  64; i += blockDim.x) a3[(size_t)tb * NNODES *  64 + i] = 0.f;
}

// ---------------------------------------------------------------------------
// Gather-conv GEMM, K-paired f32x2 accumulation, k-tiled smem.
//   acc[i][j].{x,y} accumulate even/odd kk partial sums; summed in epilogue.
// Block: one (tower,b), TM=64 triples, all O outputs, 512 threads (16 warps),
// each warp covers TMpt=4 triples, each lane outputs o = lane + 32*i.
// ---------------------------------------------------------------------------
template<int C, int O>
__global__ __launch_bounds__(512, 1) void conv_kernel(
    const float* __restrict__ actin,
    const int* __restrict__ idxA, const int* __restrict__ idxB,
    const float* __restrict__ wrt,      // [O][CK]
    const float* __restrict__ bias,     // [O]
    const float* __restrict__ stats,    // {mean, inv} per tb (prev layer)
    float* __restrict__ actout)         // [2*BATCH][NNODES][O]
{
    constexpr int TM = 64;
    constexpr int CK = 3 * C;
    constexpr int KT = 64;              // k-tile (within a single kernel tap)
    constexpr int WST = KT + 2;         // w row stride (words): 8B-aligned, conflict-free
    constexpr int TO = O / 32;          // outputs per lane: 8 / 4 / 2
    constexpr int TMpt = 4;
    constexpr int NT = CK / KT;
    constexpr bool LN = (C != 64);      // first layer (C=64) has no input LN

    extern __shared__ float smem[];
    float* g_s = smem;                  // [TM][KT]
    float* w_s = smem + TM * KT;        // [O][WST]
    __shared__ int nodes[TM * 3];

    const int tid = threadIdx.x;
    const int m0 = blockIdx.x * TM;
    const int tb = blockIdx.z * BATCH + blockIdx.y;

    const int* idx = (blockIdx.z ? idxB : idxA) + blockIdx.y * T3;
    const float* ain = actin + (size_t)tb * NNODES * C;

    float mean = 0.f, inv = 0.f;
    if (LN) { mean = stats[tb * 2]; inv = stats[tb * 2 + 1]; }

    if (tid < TM * 3) {
        int t = m0 * 3 + tid;
        nodes[tid] = (t < T3) ? idx[t] : 0;
    }

    u64 acc[TO][TMpt];
#pragma unroll
    for (int i = 0; i < TO; i++)
#pragma unroll
        for (int j = 0; j < TMpt; j++) acc[i][j] = 0ull;

    const int lane = tid & 31;
    const int warp = tid >> 5;
    const float* grow0 = g_s + (warp * TMpt) * KT;

    constexpr int KT4 = KT / 4;
    constexpr int KT2 = KT / 2;

    for (int t = 0; t < NT; t++) {
        const int ck0 = t * KT;
        const int k = ck0 / C;
        const int cbase = ck0 - k * C;
        __syncthreads();
        // --- load w tile [O][KT] (u64 copies, coalesced gmem, clean STS) ---
#pragma unroll 4
        for (int e = tid; e < O * KT2; e += 512) {
            int o = e / KT2, q2 = e - o * KT2;
            u64 v = *reinterpret_cast<const u64*>(wrt + (size_t)o * CK + ck0 + 2 * q2);
            *reinterpret_cast<u64*>(w_s + o * WST + 2 * q2) = v;
        }
        // --- gather g tile [TM][KT] with fused LN + leakyReLU ---
#pragma unroll
        for (int e = tid; e < TM * KT4; e += 512) {
            int r = e / KT4, q = e - r * KT4;
            int node = nodes[r * 3 + k];
            float4 v = *reinterpret_cast<const float4*>(ain + (size_t)node * C + cbase + 4 * q);
            if (LN) {
                v.x = (v.x - mean) * inv; v.x = v.x > 0.f ? v.x : 0.01f * v.x;
                v.y = (v.y - mean) * inv; v.y = v.y > 0.f ? v.y : 0.01f * v.y;
                v.z = (v.z - mean) * inv; v.z = v.z > 0.f ? v.z : 0.01f * v.z;
                v.w = (v.w - mean) * inv; v.w = v.w > 0.f ? v.w : 0.01f * v.w;
            }
            reinterpret_cast<float4*>(g_s)[e] = v;
        }
        __syncthreads();
        // --- mainloop: K-paired FFMA2, no packs ---
#pragma unroll 4
        for (int kk = 0; kk < KT; kk += 2) {
            u64 gp[TMpt];
#pragma unroll
            for (int j = 0; j < TMpt; j++)
                gp[j] = *reinterpret_cast<const u64*>(grow0 + j * KT + kk);
#pragma unroll
            for (int i = 0; i < TO; i++) {
                u64 wp = *reinterpret_cast<const u64*>(w_s + (lane + 32 * i) * WST + kk);
#pragma unroll
                for (int j = 0; j < TMpt; j++)
                    fma_f32x2(acc[i][j], wp, gp[j]);
            }
        }
    }

    float* aout = actout + (size_t)tb * NNODES * O;
#pragma unroll
    for (int j = 0; j < TMpt; j++) {
        int mt = m0 + warp * TMpt + j;
        if (mt < NTRI) {
#pragma unroll
            for (int i = 0; i < TO; i++) {
                int o = lane + 32 * i;
                float2 v = unpack2(acc[i][j]);
                aout[(size_t)(mt + 1) * O + o] = v.x + v.y + bias[o];
            }
        }
    }
}

// ---------------------------------------------------------------------------
// Per-(tower,b) mean / 1/(unbiased std + 1e-5) over [NNODES][O]
// ---------------------------------------------------------------------------
__global__ __launch_bounds__(256) void stats_kernel(
    const float* __restrict__ act, float* __restrict__ stats, int O)
{
    int tb = blockIdx.x;
    const float4* a = reinterpret_cast<const float4*>(act + (size_t)tb * NNODES * O);
    int n4 = NNODES * O / 4;
    double s = 0.0, ss = 0.0;
    for (int i = threadIdx.x; i < n4; i += 256) {
        float4 v = a[i];
        s += (double)v.x + (double)v.y + (double)v.z + (double)v.w;
        ss += (double)v.x * v.x + (double)v.y * v.y + (double)v.z * v.z + (double)v.w * v.w;
    }
    __shared__ double sh[512];
    sh[threadIdx.x] = s;
    sh[256 + threadIdx.x] = ss;
    __syncthreads();
    for (int off = 128; off > 0; off >>= 1) {
        if (threadIdx.x < off) {
            sh[threadIdx.x] += sh[threadIdx.x + off];
            sh[256 + threadIdx.x] += sh[256 + threadIdx.x + off];
        }
        __syncthreads();
    }
    if (threadIdx.x == 0) {
        double n = (double)NNODES * O;
        double mean = sh[0] / n;
        double var = (sh[256] - sh[0] * sh[0] / n) / (n - 1.0);
        if (var < 0.0) var = 0.0;
        stats[tb * 2] = (float)mean;
        stats[tb * 2 + 1] = (float)(1.0 / (sqrt(var) + 1e-5));
    }
}

// ---------------------------------------------------------------------------
// Final: LN(act3) -> channel max over nodes -> FC1(lrelu) -> FC2 ->
//        sigmoid(y_tower0 - y_tower1). One block per batch element.
// ---------------------------------------------------------------------------
__global__ __launch_bounds__(256) void final_kernel(
    const float* __restrict__ act3, const float* __restrict__ stats3,
    const float* __restrict__ wfc1, const float* __restrict__ bfc1,
    const float* __restrict__ wfc2, const float* __restrict__ bfc2,
    float* __restrict__ out)
{
    int b = blockIdx.x;
    int tid = threadIdx.x;
    __shared__ float mx[4][64];
    __shared__ float h[32];
    __shared__ float yy[2];

    for (int tower = 0; tower < 2; tower++) {
        int tb = tower * BATCH + b;
        float mean = stats3[tb * 2], inv = stats3[tb * 2 + 1];
        const float* a = act3 + (size_t)tb * NNODES * 64;
        int c = tid & 63, grp = tid >> 6;
        float m = -1e30f;
        for (int n = grp; n < NNODES; n += 4) {
            float v = (a[(size_t)n * 64 + c] - mean) * inv;
            m = fmaxf(m, v);
        }
        mx[grp][c] = m;
        __syncthreads();
        if (tid < 64) {
            mx[0][tid] = fmaxf(fmaxf(mx[0][tid], mx[1][tid]),
                               fmaxf(mx[2][tid], mx[3][tid]));
        }
        __syncthreads();
        if (tid < 32) {
            float sAcc = bfc1[tid];
            for (int c2 = 0; c2 < 64; c2++) sAcc = fmaf(mx[0][c2], wfc1[tid * 64 + c2], sAcc);
            h[tid] = sAcc > 0.f ? sAcc : 0.01f * sAcc;
        }
        __syncthreads();
        if (tid == 0) {
            float sAcc = bfc2[0];
            for (int i = 0; i < 32; i++) sAcc = fmaf(h[i], wfc2[i], sAcc);
            yy[tower] = sAcc;
        }
        __syncthreads();
    }
    if (tid == 0) {
        float d = yy[0] - yy[1];
        out[b] = 1.f / (1.f + expf(-d));
    }
}

// ---------------------------------------------------------------------------
extern "C" void kernel_launch(void* const* d_in, const int* in_sizes, int n_in,
                              void* d_out, int out_size)
{
    const float* data1 = (const float*)d_in[0];
    const int*   idx1  = (const int*)d_in[1];
    const float* data2 = (const float*)d_in[2];
    const int*   idx2  = (const int*)d_in[3];
    const float* w1 = (const float*)d_in[4];
    const float* b1 = (const float*)d_in[5];
    const float* w2 = (const float*)d_in[6];
    const float* b2 = (const float*)d_in[7];
    const float* w3 = (const float*)d_in[8];
    const float* b3 = (const float*)d_in[9];
    const float* wfc1 = (const float*)d_in[10];
    const float* bfc1 = (const float*)d_in[11];
    const float* wfc2 = (const float*)d_in[12];
    const float* bfc2 = (const float*)d_in[13];
    float* out = (float*)d_out;

    float *act0, *act1, *act2, *act3, *wrt1, *wrt2, *wrt3, *st1, *st2, *st3;
    cudaGetSymbolAddress((void**)&act0, g_act0);
    cudaGetSymbolAddress((void**)&act1, g_act1);
    cudaGetSymbolAddress((void**)&act2, g_act2);
    cudaGetSymbolAddress((void**)&act3, g_act3);
    cudaGetSymbolAddress((void**)&wrt1, g_wrt1);
    cudaGetSymbolAddress((void**)&wrt2, g_wrt2);
    cudaGetSymbolAddress((void**)&wrt3, g_wrt3);
    cudaGetSymbolAddress((void**)&st1, g_st1);
    cudaGetSymbolAddress((void**)&st2, g_st2);
    cudaGetSymbolAddress((void**)&st3, g_st3);

    // smem bytes: g TM*KT*4 = 16384, w O*(KT+2)*4
    const int smem1 = 16384 + 256 * 66 * 4;  // 83968
    const int smem2 = 16384 + 128 * 66 * 4;  // 50176
    const int smem3 = 16384 +  64 * 66 * 4;  // 33280
    cudaFuncSetAttribute(conv_kernel<64, 256>,
                         cudaFuncAttributeMaxDynamicSharedMemorySize, smem1);
    cudaFuncSetAttribute(conv_kernel<256, 128>,
                         cudaFuncAttributeMaxDynamicSharedMemorySize, smem2);
    cudaFuncSetAttribute(conv_kernel<128, 64>,
                         cudaFuncAttributeMaxDynamicSharedMemorySize, smem3);

    transpose_kernel<<<dim3(32, 2, 256), dim3(32, 8)>>>(data1, data2, act0);
    reorder_w<<<(256 * 192 + 255) / 256, 256>>>(w1, wrt1, 256, 64);
    reorder_w<<<(128 * 768 + 255) / 256, 256>>>(w2, wrt2, 128, 256);
    reorder_w<<<(64 * 384 + 255) / 256, 256>>>(w3, wrt3, 64, 128);
    zero_rows<<<256, 256>>>(act1, act2, act3);

    conv_kernel<64, 256><<<dim3(16, BATCH, 2), 512, smem1>>>(
        act0, idx1, idx2, wrt1, b1, st1 /*unused*/, act1);
    stats_kernel<<<256, 256>>>(act1, st1, 256);

    conv_kernel<256, 128><<<dim3(16, BATCH, 2), 512, smem2>>>(
        act1, idx1, idx2, wrt2, b2, st1, act2);
    stats_kernel<<<256, 256>>>(act2, st2, 128);

    conv_kernel<128, 64><<<dim3(16, BATCH, 2), 512, smem3>>>(
        act2, idx1, idx2, wrt3, b3, st2, act3);
    stats_kernel<<<256, 256>>>(act3, st3, 64);

    final_kernel<<<BATCH, 256>>>(act3, st3, wfc1, bfc1, wfc2, bfc2, out);
}

// round 4
// speedup vs baseline: 1.4683x; 1.2713x over previous
#include <cuda_runtime.h>
#include <math.h>

#define BATCH 128
#define NNODES 1024
#define NTRI 1023
#define T3 3069

typedef unsigned long long u64;

// Persistent scratch. Node-major activations: [tower*128+b][node][C],
// node 0 is the shared zero node for act1/2/3.
__device__ float g_act0[(size_t)2*BATCH*NNODES*64];    //  64 MB
__device__ float g_act1[(size_t)2*BATCH*NNODES*256];   // 256 MB
__device__ float g_act2[(size_t)2*BATCH*NNODES*128];   // 128 MB
__device__ float g_act3[(size_t)2*BATCH*NNODES*64];    //  64 MB
__device__ float g_wrt1[256*192];   // [O][CK] weights, ck = k*C + c
__device__ float g_wrt2[128*768];
__device__ float g_wrt3[64*384];
__device__ float g_part[2*BATCH*16*2]; // per-block {sum, sumsq} partials
__device__ float g_st1[2*BATCH*2];  // {mean, 1/(std+1e-5)} per (tower,b)
__device__ float g_st2[2*BATCH*2];
__device__ float g_st3[2*BATCH*2];

// ---- packed f32x2 helpers ---------------------------------------------------
__device__ __forceinline__ void fma_f32x2(u64& d, u64 a, u64 b) {
    asm("fma.rn.f32x2 %0, %1, %2, %0;" : "+l"(d) : "l"(a), "l"(b));
}
__device__ __forceinline__ float2 unpack2(u64 v) {
    float2 f;
    asm("mov.b64 {%0, %1}, %2;" : "=f"(f.x), "=f"(f.y) : "l"(v));
    return f;
}

// ---------------------------------------------------------------------------
// Transpose raw input [b][C=64][N=1024] -> act0 [tower*128+b][N][64]
// ---------------------------------------------------------------------------
__global__ __launch_bounds__(256) void transpose_kernel(
    const float* __restrict__ d1, const float* __restrict__ d2,
    float* __restrict__ act0)
{
    __shared__ float tile[32][33];
    int tb = blockIdx.z;
    int tower = tb / BATCH, b = tb % BATCH;
    const float* src = (tower ? d2 : d1) + (size_t)b * 64 * NNODES; // [64][1024]
    float* dst = act0 + (size_t)tb * NNODES * 64;                   // [1024][64]
    int n0 = blockIdx.x * 32, c0 = blockIdx.y * 32;
    for (int i = threadIdx.y; i < 32; i += 8)
        tile[i][threadIdx.x] = src[(size_t)(c0 + i) * NNODES + n0 + threadIdx.x];
    __syncthreads();
    for (int i = threadIdx.y; i < 32; i += 8)
        dst[(size_t)(n0 + i) * 64 + c0 + threadIdx.x] = tile[threadIdx.x][i];
}

// ---------------------------------------------------------------------------
// Reorder conv weights: w[o][c][k] -> wrt[o][ck] with ck = k*C + c
// ---------------------------------------------------------------------------
__global__ void reorder_w(const float* __restrict__ w, float* __restrict__ wrt,
                          int O, int C)
{
    int i = blockIdx.x * blockDim.x + threadIdx.x;
    int CK = C * 3;
    if (i < O * CK) {
        int o = i / CK, ck = i - o * CK;
        int k = ck / C, c = ck - k * C;
        wrt[i] = w[(o * C + c) * 3 + k];
    }
}

// ---------------------------------------------------------------------------
// Zero the "zero node" row (node 0) of act1/2/3 for every (tower, b)
// ---------------------------------------------------------------------------
__global__ void zero_rows(float* a1, float* a2, float* a3)
{
    int tb = blockIdx.x;
    for (int i = threadIdx.x; i < 256; i += blockDim.x) a1[(size_t)tb * NNODES * 256 + i] = 0.f;
    for (int i = threadIdx.x; i < 128; i += blockDim.x) a2[(size_t)tb * NNODES * 128 + i] = 0.f;
    for (int i = threadIdx.x; i <  64; i += blockDim.x) a3[(size_t)tb * NNODES *  64 + i] = 0.f;
}

// ---------------------------------------------------------------------------
// Gather-conv GEMM, K-paired f32x2 accumulation, k-tiled smem, fused
// per-block {sum, sumsq} partial stats (fp32) written to part[].
// Block: one (tower,b), TM=64 triples, all O outputs, 512 threads (16 warps).
// ---------------------------------------------------------------------------
template<int C, int O>
__global__ __launch_bounds__(512, 1) void conv_kernel(
    const float* __restrict__ actin,
    const int* __restrict__ idxA, const int* __restrict__ idxB,
    const float* __restrict__ wrt,      // [O][CK]
    const float* __restrict__ bias,     // [O]
    const float* __restrict__ stats,    // {mean, inv} per tb (prev layer)
    float* __restrict__ actout,         // [2*BATCH][NNODES][O]
    float* __restrict__ part)           // [2*BATCH][16][2]
{
    constexpr int TM = 64;
    constexpr int CK = 3 * C;
    constexpr int KT = 64;              // k-tile (within a single kernel tap)
    constexpr int WST = KT + 2;         // w row stride (words)
    constexpr int TO = O / 32;          // outputs per lane: 8 / 4 / 2
    constexpr int TMpt = 4;
    constexpr int NT = CK / KT;
    constexpr bool LN = (C != 64);      // first layer (C=64) has no input LN

    extern __shared__ float smem[];
    float* g_s = smem;                  // [TM][KT]
    float* w_s = smem + TM * KT;        // [O][WST]
    __shared__ int nodes[TM * 3];
    __shared__ float red[32];

    const int tid = threadIdx.x;
    const int m0 = blockIdx.x * TM;
    const int tb = blockIdx.z * BATCH + blockIdx.y;

    const int* idx = (blockIdx.z ? idxB : idxA) + blockIdx.y * T3;
    const float* ain = actin + (size_t)tb * NNODES * C;

    float mean = 0.f, inv = 0.f;
    if (LN) { mean = stats[tb * 2]; inv = stats[tb * 2 + 1]; }

    if (tid < TM * 3) {
        int t = m0 * 3 + tid;
        nodes[tid] = (t < T3) ? idx[t] : 0;
    }

    u64 acc[TO][TMpt];
#pragma unroll
    for (int i = 0; i < TO; i++)
#pragma unroll
        for (int j = 0; j < TMpt; j++) acc[i][j] = 0ull;

    const int lane = tid & 31;
    const int warp = tid >> 5;
    const float* grow0 = g_s + (warp * TMpt) * KT;

    constexpr int KT4 = KT / 4;
    constexpr int KT2 = KT / 2;

    for (int t = 0; t < NT; t++) {
        const int ck0 = t * KT;
        const int k = ck0 / C;
        const int cbase = ck0 - k * C;
        __syncthreads();
        // --- load w tile [O][KT] ---
#pragma unroll 4
        for (int e = tid; e < O * KT2; e += 512) {
            int o = e / KT2, q2 = e - o * KT2;
            u64 v = *reinterpret_cast<const u64*>(wrt + (size_t)o * CK + ck0 + 2 * q2);
            *reinterpret_cast<u64*>(w_s + o * WST + 2 * q2) = v;
        }
        // --- gather g tile [TM][KT] with fused LN + leakyReLU ---
#pragma unroll
        for (int e = tid; e < TM * KT4; e += 512) {
            int r = e / KT4, q = e - r * KT4;
            int node = nodes[r * 3 + k];
            float4 v = *reinterpret_cast<const float4*>(ain + (size_t)node * C + cbase + 4 * q);
            if (LN) {
                v.x = (v.x - mean) * inv; v.x = v.x > 0.f ? v.x : 0.01f * v.x;
                v.y = (v.y - mean) * inv; v.y = v.y > 0.f ? v.y : 0.01f * v.y;
                v.z = (v.z - mean) * inv; v.z = v.z > 0.f ? v.z : 0.01f * v.z;
                v.w = (v.w - mean) * inv; v.w = v.w > 0.f ? v.w : 0.01f * v.w;
            }
            reinterpret_cast<float4*>(g_s)[e] = v;
        }
        __syncthreads();
        // --- mainloop: K-paired FFMA2 ---
#pragma unroll 4
        for (int kk = 0; kk < KT; kk += 2) {
            u64 gp[TMpt];
#pragma unroll
            for (int j = 0; j < TMpt; j++)
                gp[j] = *reinterpret_cast<const u64*>(grow0 + j * KT + kk);
#pragma unroll
            for (int i = 0; i < TO; i++) {
                u64 wp = *reinterpret_cast<const u64*>(w_s + (lane + 32 * i) * WST + kk);
#pragma unroll
                for (int j = 0; j < TMpt; j++)
                    fma_f32x2(acc[i][j], wp, gp[j]);
            }
        }
    }

    // Epilogue: store + fp32 partial stats
    float ls = 0.f, lss = 0.f;
    float* aout = actout + (size_t)tb * NNODES * O;
#pragma unroll
    for (int j = 0; j < TMpt; j++) {
        int mt = m0 + warp * TMpt + j;
        if (mt < NTRI) {
#pragma unroll
            for (int i = 0; i < TO; i++) {
                int o = lane + 32 * i;
                float2 p = unpack2(acc[i][j]);
                float v = p.x + p.y + bias[o];
                aout[(size_t)(mt + 1) * O + o] = v;
                ls += v;
                lss = fmaf(v, v, lss);
            }
        }
    }
    // warp reduce
#pragma unroll
    for (int off = 16; off > 0; off >>= 1) {
        ls  += __shfl_xor_sync(0xffffffffu, ls,  off);
        lss += __shfl_xor_sync(0xffffffffu, lss, off);
    }
    if (lane == 0) { red[warp] = ls; red[16 + warp] = lss; }
    __syncthreads();
    if (tid == 0) {
        float s = 0.f, ss = 0.f;
#pragma unroll
        for (int wv = 0; wv < 16; wv++) { s += red[wv]; ss += red[16 + wv]; }
        float* pp = part + ((size_t)tb * 16 + blockIdx.x) * 2;
        pp[0] = s; pp[1] = ss;
    }
}

// ---------------------------------------------------------------------------
// Finalize stats: reduce 16 partials per (tower,b) -> {mean, 1/(std+1e-5)}
// One block of 256 threads; thread t handles tb = t. n = 1024*O (zero node
// contributes nothing to the partials).
// ---------------------------------------------------------------------------
__global__ __launch_bounds__(256) void finalize_stats(
    const float* __restrict__ part, float* __restrict__ stats, int O)
{
    int tb = threadIdx.x;
    double s = 0.0, ss = 0.0;
#pragma unroll
    for (int i = 0; i < 16; i++) {
        s += (double)part[((size_t)tb * 16 + i) * 2];
        ss += (double)part[((size_t)tb * 16 + i) * 2 + 1];
    }
    double n = 1024.0 * O;
    double mean = s / n;
    double var = (ss - s * s / n) / (n - 1.0);
    if (var < 0.0) var = 0.0;
    stats[tb * 2] = (float)mean;
    stats[tb * 2 + 1] = (float)(1.0 / (sqrt(var) + 1e-5));
}

// ---------------------------------------------------------------------------
// Final: LN(act3) -> channel max over nodes -> FC1(lrelu) -> FC2 ->
//        sigmoid(y_tower0 - y_tower1). One block per batch element.
// ---------------------------------------------------------------------------
__global__ __launch_bounds__(256) void final_kernel(
    const float* __restrict__ act3, const float* __restrict__ stats3,
    const float* __restrict__ wfc1, const float* __restrict__ bfc1,
    const float* __restrict__ wfc2, const float* __restrict__ bfc2,
    float* __restrict__ out)
{
    int b = blockIdx.x;
    int tid = threadIdx.x;
    __shared__ float mx[4][64];
    __shared__ float h[32];
    __shared__ float yy[2];

    for (int tower = 0; tower < 2; tower++) {
        int tb = tower * BATCH + b;
        float mean = stats3[tb * 2], inv = stats3[tb * 2 + 1];
        const float* a = act3 + (size_t)tb * NNODES * 64;
        int c = tid & 63, grp = tid >> 6;
        float m = -1e30f;
        for (int n = grp; n < NNODES; n += 4) {
            float v = (a[(size_t)n * 64 + c] - mean) * inv;
            m = fmaxf(m, v);
        }
        mx[grp][c] = m;
        __syncthreads();
        if (tid < 64) {
            mx[0][tid] = fmaxf(fmaxf(mx[0][tid], mx[1][tid]),
                               fmaxf(mx[2][tid], mx[3][tid]));
        }
        __syncthreads();
        if (tid < 32) {
            float sAcc = bfc1[tid];
            for (int c2 = 0; c2 < 64; c2++) sAcc = fmaf(mx[0][c2], wfc1[tid * 64 + c2], sAcc);
            h[tid] = sAcc > 0.f ? sAcc : 0.01f * sAcc;
        }
        __syncthreads();
        if (tid == 0) {
            float sAcc = bfc2[0];
            for (int i = 0; i < 32; i++) sAcc = fmaf(h[i], wfc2[i], sAcc);
            yy[tower] = sAcc;
        }
        __syncthreads();
    }
    if (tid == 0) {
        float d = yy[0] - yy[1];
        out[b] = 1.f / (1.f + expf(-d));
    }
}

// ---------------------------------------------------------------------------
extern "C" void kernel_launch(void* const* d_in, const int* in_sizes, int n_in,
                              void* d_out, int out_size)
{
    const float* data1 = (const float*)d_in[0];
    const int*   idx1  = (const int*)d_in[1];
    const float* data2 = (const float*)d_in[2];
    const int*   idx2  = (const int*)d_in[3];
    const float* w1 = (const float*)d_in[4];
    const float* b1 = (const float*)d_in[5];
    const float* w2 = (const float*)d_in[6];
    const float* b2 = (const float*)d_in[7];
    const float* w3 = (const float*)d_in[8];
    const float* b3 = (const float*)d_in[9];
    const float* wfc1 = (const float*)d_in[10];
    const float* bfc1 = (const float*)d_in[11];
    const float* wfc2 = (const float*)d_in[12];
    const float* bfc2 = (const float*)d_in[13];
    float* out = (float*)d_out;

    float *act0, *act1, *act2, *act3, *wrt1, *wrt2, *wrt3, *part, *st1, *st2, *st3;
    cudaGetSymbolAddress((void**)&act0, g_act0);
    cudaGetSymbolAddress((void**)&act1, g_act1);
    cudaGetSymbolAddress((void**)&act2, g_act2);
    cudaGetSymbolAddress((void**)&act3, g_act3);
    cudaGetSymbolAddress((void**)&wrt1, g_wrt1);
    cudaGetSymbolAddress((void**)&wrt2, g_wrt2);
    cudaGetSymbolAddress((void**)&wrt3, g_wrt3);
    cudaGetSymbolAddress((void**)&part, g_part);
    cudaGetSymbolAddress((void**)&st1, g_st1);
    cudaGetSymbolAddress((void**)&st2, g_st2);
    cudaGetSymbolAddress((void**)&st3, g_st3);

    // smem bytes: g TM*KT*4 = 16384, w O*(KT+2)*4
    const int smem1 = 16384 + 256 * 66 * 4;  // 83968
    const int smem2 = 16384 + 128 * 66 * 4;  // 50176
    const int smem3 = 16384 +  64 * 66 * 4;  // 33280
    cudaFuncSetAttribute(conv_kernel<64, 256>,
                         cudaFuncAttributeMaxDynamicSharedMemorySize, smem1);
    cudaFuncSetAttribute(conv_kernel<256, 128>,
                         cudaFuncAttributeMaxDynamicSharedMemorySize, smem2);
    cudaFuncSetAttribute(conv_kernel<128, 64>,
                         cudaFuncAttributeMaxDynamicSharedMemorySize, smem3);

    // Launch order keeps conv1 in ncu's captured slot (#4).
    transpose_kernel<<<dim3(32, 2, 256), dim3(32, 8)>>>(data1, data2, act0);
    reorder_w<<<(256 * 192 + 255) / 256, 256>>>(w1, wrt1, 256, 64);
    zero_rows<<<256, 256>>>(act1, act2, act3);

    conv_kernel<64, 256><<<dim3(16, BATCH, 2), 512, smem1>>>(
        act0, idx1, idx2, wrt1, b1, st1 /*unused*/, act1, part);
    finalize_stats<<<1, 256>>>(part, st1, 256);
    reorder_w<<<(128 * 768 + 255) / 256, 256>>>(w2, wrt2, 128, 256);

    conv_kernel<256, 128><<<dim3(16, BATCH, 2), 512, smem2>>>(
        act1, idx1, idx2, wrt2, b2, st1, act2, part);
    finalize_stats<<<1, 256>>>(part, st2, 128);
    reorder_w<<<(64 * 384 + 255) / 256, 256>>>(w3, wrt3, 64, 128);

    conv_kernel<128, 64><<<dim3(16, BATCH, 2), 512, smem3>>>(
        act2, idx1, idx2, wrt3, b3, st2, act3, part);
    finalize_stats<<<1, 256>>>(part, st3, 64);

    final_kernel<<<BATCH, 256>>>(act3, st3, wfc1, bfc1, wfc2, bfc2, out);
}

// round 5
// speedup vs baseline: 1.6207x; 1.1038x over previous
#include <cuda_runtime.h>
#include <math.h>

#define BATCH 128
#define NNODES 1024
#define NTRI 1023
#define T3 3069

typedef unsigned long long u64;

// Persistent scratch. Node-major activations: [tower*128+b][node][C],
// node 0 is the shared zero node for act1/2/3.
__device__ float g_act0[(size_t)2*BATCH*NNODES*64];    //  64 MB
__device__ float g_act1[(size_t)2*BATCH*NNODES*256];   // 256 MB
__device__ float g_act2[(size_t)2*BATCH*NNODES*128];   // 128 MB
__device__ float g_act3[(size_t)2*BATCH*NNODES*64];    //  64 MB
__device__ float g_wrt1[256*192];   // [O][CK] weights, ck = k*C + c
__device__ float g_wrt2[128*768];
__device__ float g_wrt3[64*384];
__device__ float g_part[2*BATCH*16*2]; // per-block {sum, sumsq} partials
__device__ float g_st1[2*BATCH*2];  // {mean, 1/(std+1e-5)} per (tower,b)
__device__ float g_st2[2*BATCH*2];
__device__ float g_st3[2*BATCH*2];

// ---- packed f32x2 helpers ---------------------------------------------------
__device__ __forceinline__ void fma_f32x2(u64& d, u64 a, u64 b) {
    asm("fma.rn.f32x2 %0, %1, %2, %0;" : "+l"(d) : "l"(a), "l"(b));
}
__device__ __forceinline__ float2 unpack2(u64 v) {
    float2 f;
    asm("mov.b64 {%0, %1}, %2;" : "=f"(f.x), "=f"(f.y) : "l"(v));
    return f;
}

// ---------------------------------------------------------------------------
// Transpose raw input [b][C=64][N=1024] -> act0 [tower*128+b][N][64]
// ---------------------------------------------------------------------------
__global__ __launch_bounds__(256) void transpose_kernel(
    const float* __restrict__ d1, const float* __restrict__ d2,
    float* __restrict__ act0)
{
    __shared__ float tile[32][33];
    int tb = blockIdx.z;
    int tower = tb / BATCH, b = tb % BATCH;
    const float* src = (tower ? d2 : d1) + (size_t)b * 64 * NNODES; // [64][1024]
    float* dst = act0 + (size_t)tb * NNODES * 64;                   // [1024][64]
    int n0 = blockIdx.x * 32, c0 = blockIdx.y * 32;
    for (int i = threadIdx.y; i < 32; i += 8)
        tile[i][threadIdx.x] = src[(size_t)(c0 + i) * NNODES + n0 + threadIdx.x];
    __syncthreads();
    for (int i = threadIdx.y; i < 32; i += 8)
        dst[(size_t)(n0 + i) * 64 + c0 + threadIdx.x] = tile[threadIdx.x][i];
}

// ---------------------------------------------------------------------------
// Reorder conv weights: w[o][c][k] -> wrt[o][ck] with ck = k*C + c
// ---------------------------------------------------------------------------
__global__ void reorder_w(const float* __restrict__ w, float* __restrict__ wrt,
                          int O, int C)
{
    int i = blockIdx.x * blockDim.x + threadIdx.x;
    int CK = C * 3;
    if (i < O * CK) {
        int o = i / CK, ck = i - o * CK;
        int k = ck / C, c = ck - k * C;
        wrt[i] = w[(o * C + c) * 3 + k];
    }
}

// ---------------------------------------------------------------------------
// Zero the "zero node" row (node 0) of act1/2/3 for every (tower, b)
// ---------------------------------------------------------------------------
__global__ void zero_rows(float* a1, float* a2, float* a3)
{
    int tb = blockIdx.x;
    for (int i = threadIdx.x; i < 256; i += blockDim.x) a1[(size_t)tb * NNODES * 256 + i] = 0.f;
    for (int i = threadIdx.x; i < 128; i += blockDim.x) a2[(size_t)tb * NNODES * 128 + i] = 0.f;
    for (int i = threadIdx.x; i <  64; i += blockDim.x) a3[(size_t)tb * NNODES *  64 + i] = 0.f;
}

// ---------------------------------------------------------------------------
// Gather-conv GEMM. TM=128 triples/block, 16 warps x TMpt=8 triples.
// O split into OCH chunks of Oc=O/OCH (TO=Oc/32 outputs per lane).
// Both operands read as LDS.128 (4 k-values), K-paired f32x2 accumulation.
// Fused per-block {sum, sumsq} fp32 partial stats.
// ---------------------------------------------------------------------------
template<int C, int O, int OCH>
__global__ __launch_bounds__(512, 1) void conv_kernel(
    const float* __restrict__ actin,
    const int* __restrict__ idxA, const int* __restrict__ idxB,
    const float* __restrict__ wrt,      // [O][CK]
    const float* __restrict__ bias,     // [O]
    const float* __restrict__ stats,    // {mean, inv} per tb (prev layer)
    float* __restrict__ actout,         // [2*BATCH][NNODES][O]
    float* __restrict__ part)           // [2*BATCH][16][2]
{
    constexpr int TM = 128;
    constexpr int CK = 3 * C;
    constexpr int KT = 64;              // k-tile
    constexpr int Oc = O / OCH;
    constexpr int WST = KT + 4;         // 68 words: =4 mod 32 -> LDS.128 conflict-free
    constexpr int TO = Oc / 32;         // 4 / 4 / 2
    constexpr int TMpt = 8;
    constexpr int NT = CK / KT;
    constexpr bool LN = (C != 64);

    extern __shared__ float smem[];
    float* g_s = smem;                  // [TM][KT]
    float* w_s = smem + TM * KT;        // [Oc][WST]
    __shared__ int nodes[TM * 3];
    __shared__ float red[32];

    const int tid = threadIdx.x;
    const int och = blockIdx.x % OCH;
    const int m0 = (blockIdx.x / OCH) * TM;
    const int tb = blockIdx.z * BATCH + blockIdx.y;

    const int* idx = (blockIdx.z ? idxB : idxA) + blockIdx.y * T3;
    const float* ain = actin + (size_t)tb * NNODES * C;

    float mean = 0.f, inv = 0.f;
    if (LN) { mean = stats[tb * 2]; inv = stats[tb * 2 + 1]; }

    if (tid < TM * 3) {
        int t = m0 * 3 + tid;
        nodes[tid] = (t < T3) ? idx[t] : 0;
    }

    u64 acc[TO][TMpt];
#pragma unroll
    for (int i = 0; i < TO; i++)
#pragma unroll
        for (int j = 0; j < TMpt; j++) acc[i][j] = 0ull;

    const int lane = tid & 31;
    const int warp = tid >> 5;
    const float* grow0 = g_s + (warp * TMpt) * KT;

    constexpr int KT4 = KT / 4;
    constexpr int KT2 = KT / 2;

    for (int t = 0; t < NT; t++) {
        const int ck0 = t * KT;
        const int k = ck0 / C;
        const int cbase = ck0 - k * C;
        __syncthreads();
        // --- load w tile [Oc][KT] for this o-chunk ---
#pragma unroll 4
        for (int e = tid; e < Oc * KT2; e += 512) {
            int o = e / KT2, q2 = e - o * KT2;
            u64 v = *reinterpret_cast<const u64*>(
                wrt + (size_t)(och * Oc + o) * CK + ck0 + 2 * q2);
            *reinterpret_cast<u64*>(w_s + o * WST + 2 * q2) = v;
        }
        // --- gather g tile [TM][KT] with fused LN + leakyReLU ---
#pragma unroll 4
        for (int e = tid; e < TM * KT4; e += 512) {
            int r = e / KT4, q = e - r * KT4;
            int node = nodes[r * 3 + k];
            float4 v = *reinterpret_cast<const float4*>(ain + (size_t)node * C + cbase + 4 * q);
            if (LN) {
                v.x = (v.x - mean) * inv; v.x = v.x > 0.f ? v.x : 0.01f * v.x;
                v.y = (v.y - mean) * inv; v.y = v.y > 0.f ? v.y : 0.01f * v.y;
                v.z = (v.z - mean) * inv; v.z = v.z > 0.f ? v.z : 0.01f * v.z;
                v.w = (v.w - mean) * inv; v.w = v.w > 0.f ? v.w : 0.01f * v.w;
            }
            reinterpret_cast<float4*>(g_s)[e] = v;
        }
        __syncthreads();
        // --- mainloop: 4 k-values per step, both operands LDS.128 ---
#pragma unroll 4
        for (int kk = 0; kk < KT; kk += 4) {
            ulonglong2 wv[TO];
#pragma unroll
            for (int i = 0; i < TO; i++)
                wv[i] = *reinterpret_cast<const ulonglong2*>(w_s + (lane + 32 * i) * WST + kk);
#pragma unroll
            for (int j = 0; j < TMpt; j++) {
                ulonglong2 gv = *reinterpret_cast<const ulonglong2*>(grow0 + j * KT + kk);
#pragma unroll
                for (int i = 0; i < TO; i++) {
                    fma_f32x2(acc[i][j], wv[i].x, gv.x);
                    fma_f32x2(acc[i][j], wv[i].y, gv.y);
                }
            }
        }
    }

    // Epilogue: store + fp32 partial stats
    float ls = 0.f, lss = 0.f;
    float* aout = actout + (size_t)tb * NNODES * O;
#pragma unroll
    for (int j = 0; j < TMpt; j++) {
        int mt = m0 + warp * TMpt + j;
        if (mt < NTRI) {
#pragma unroll
            for (int i = 0; i < TO; i++) {
                int o = och * Oc + lane + 32 * i;
                float2 p = unpack2(acc[i][j]);
                float v = p.x + p.y + bias[o];
                aout[(size_t)(mt + 1) * O + o] = v;
                ls += v;
                lss = fmaf(v, v, lss);
            }
        }
    }
    // warp reduce
#pragma unroll
    for (int off = 16; off > 0; off >>= 1) {
        ls  += __shfl_xor_sync(0xffffffffu, ls,  off);
        lss += __shfl_xor_sync(0xffffffffu, lss, off);
    }
    if (lane == 0) { red[warp] = ls; red[16 + warp] = lss; }
    __syncthreads();
    if (tid == 0) {
        float s = 0.f, ss = 0.f;
#pragma unroll
        for (int wv2 = 0; wv2 < 16; wv2++) { s += red[wv2]; ss += red[16 + wv2]; }
        float* pp = part + ((size_t)tb * 16 + blockIdx.x) * 2;
        pp[0] = s; pp[1] = ss;
    }
}

// ---------------------------------------------------------------------------
// Finalize stats: reduce nparts partials per (tower,b) -> {mean, 1/(std+1e-5)}
// ---------------------------------------------------------------------------
__global__ __launch_bounds__(256) void finalize_stats(
    const float* __restrict__ part, float* __restrict__ stats, int O, int nparts)
{
    int tb = threadIdx.x;
    double s = 0.0, ss = 0.0;
    for (int i = 0; i < nparts; i++) {
        s += (double)part[((size_t)tb * 16 + i) * 2];
        ss += (double)part[((size_t)tb * 16 + i) * 2 + 1];
    }
    double n = 1024.0 * O;
    double mean = s / n;
    double var = (ss - s * s / n) / (n - 1.0);
    if (var < 0.0) var = 0.0;
    stats[tb * 2] = (float)mean;
    stats[tb * 2 + 1] = (float)(1.0 / (sqrt(var) + 1e-5));
}

// ---------------------------------------------------------------------------
// Final: LN(act3) -> channel max over nodes -> FC1(lrelu) -> FC2 ->
//        sigmoid(y_tower0 - y_tower1). One block per batch element.
// ---------------------------------------------------------------------------
__global__ __launch_bounds__(256) void final_kernel(
    const float* __restrict__ act3, const float* __restrict__ stats3,
    const float* __restrict__ wfc1, const float* __restrict__ bfc1,
    const float* __restrict__ wfc2, const float* __restrict__ bfc2,
    float* __restrict__ out)
{
    int b = blockIdx.x;
    int tid = threadIdx.x;
    __shared__ float mx[4][64];
    __shared__ float h[32];
    __shared__ float yy[2];

    for (int tower = 0; tower < 2; tower++) {
        int tb = tower * BATCH + b;
        float mean = stats3[tb * 2], inv = stats3[tb * 2 + 1];
        const float* a = act3 + (size_t)tb * NNODES * 64;
        int c = tid & 63, grp = tid >> 6;
        float m = -1e30f;
        for (int n = grp; n < NNODES; n += 4) {
            float v = (a[(size_t)n * 64 + c] - mean) * inv;
            m = fmaxf(m, v);
        }
        mx[grp][c] = m;
        __syncthreads();
        if (tid < 64) {
            mx[0][tid] = fmaxf(fmaxf(mx[0][tid], mx[1][tid]),
                               fmaxf(mx[2][tid], mx[3][tid]));
        }
        __syncthreads();
        if (tid < 32) {
            float sAcc = bfc1[tid];
            for (int c2 = 0; c2 < 64; c2++) sAcc = fmaf(mx[0][c2], wfc1[tid * 64 + c2], sAcc);
            h[tid] = sAcc > 0.f ? sAcc : 0.01f * sAcc;
        }
        __syncthreads();
        if (tid == 0) {
            float sAcc = bfc2[0];
            for (int i = 0; i < 32; i++) sAcc = fmaf(h[i], wfc2[i], sAcc);
            yy[tower] = sAcc;
        }
        __syncthreads();
    }
    if (tid == 0) {
        float d = yy[0] - yy[1];
        out[b] = 1.f / (1.f + expf(-d));
    }
}

// ---------------------------------------------------------------------------
extern "C" void kernel_launch(void* const* d_in, const int* in_sizes, int n_in,
                              void* d_out, int out_size)
{
    const float* data1 = (const float*)d_in[0];
    const int*   idx1  = (const int*)d_in[1];
    const float* data2 = (const float*)d_in[2];
    const int*   idx2  = (const int*)d_in[3];
    const float* w1 = (const float*)d_in[4];
    const float* b1 = (const float*)d_in[5];
    const float* w2 = (const float*)d_in[6];
    const float* b2 = (const float*)d_in[7];
    const float* w3 = (const float*)d_in[8];
    const float* b3 = (const float*)d_in[9];
    const float* wfc1 = (const float*)d_in[10];
    const float* bfc1 = (const float*)d_in[11];
    const float* wfc2 = (const float*)d_in[12];
    const float* bfc2 = (const float*)d_in[13];
    float* out = (float*)d_out;

    float *act0, *act1, *act2, *act3, *wrt1, *wrt2, *wrt3, *part, *st1, *st2, *st3;
    cudaGetSymbolAddress((void**)&act0, g_act0);
    cudaGetSymbolAddress((void**)&act1, g_act1);
    cudaGetSymbolAddress((void**)&act2, g_act2);
    cudaGetSymbolAddress((void**)&act3, g_act3);
    cudaGetSymbolAddress((void**)&wrt1, g_wrt1);
    cudaGetSymbolAddress((void**)&wrt2, g_wrt2);
    cudaGetSymbolAddress((void**)&wrt3, g_wrt3);
    cudaGetSymbolAddress((void**)&part, g_part);
    cudaGetSymbolAddress((void**)&st1, g_st1);
    cudaGetSymbolAddress((void**)&st2, g_st2);
    cudaGetSymbolAddress((void**)&st3, g_st3);

    // smem bytes: g 128*64*4 = 32768, w Oc*(64+4)*4
    const int smem1 = 32768 + 128 * 68 * 4;  // 67584 (Oc=128)
    const int smem2 = 32768 + 128 * 68 * 4;  // 67584 (Oc=128)
    const int smem3 = 32768 +  64 * 68 * 4;  // 50176 (Oc=64)
    cudaFuncSetAttribute(conv_kernel<64, 256, 2>,
                         cudaFuncAttributeMaxDynamicSharedMemorySize, smem1);
    cudaFuncSetAttribute(conv_kernel<256, 128, 1>,
                         cudaFuncAttributeMaxDynamicSharedMemorySize, smem2);
    cudaFuncSetAttribute(conv_kernel<128, 64, 1>,
                         cudaFuncAttributeMaxDynamicSharedMemorySize, smem3);

    transpose_kernel<<<dim3(32, 2, 256), dim3(32, 8)>>>(data1, data2, act0);
    reorder_w<<<(256 * 192 + 255) / 256, 256>>>(w1, wrt1, 256, 64);
    zero_rows<<<256, 256>>>(act1, act2, act3);

    // m-tiles: ceil(1023/128) = 8
    conv_kernel<64, 256, 2><<<dim3(16, BATCH, 2), 512, smem1>>>(
        act0, idx1, idx2, wrt1, b1, st1 /*unused*/, act1, part);
    finalize_stats<<<1, 256>>>(part, st1, 256, 16);
    reorder_w<<<(128 * 768 + 255) / 256, 256>>>(w2, wrt2, 128, 256);

    conv_kernel<256, 128, 1><<<dim3(8, BATCH, 2), 512, smem2>>>(
        act1, idx1, idx2, wrt2, b2, st1, act2, part);
    finalize_stats<<<1, 256>>>(part, st2, 128, 8);
    reorder_w<<<(64 * 384 + 255) / 256, 256>>>(w3, wrt3, 64, 128);

    conv_kernel<128, 64, 1><<<dim3(8, BATCH, 2), 512, smem3>>>(
        act2, idx1, idx2, wrt3, b3, st2, act3, part);
    finalize_stats<<<1, 256>>>(part, st3, 64, 8);

    final_kernel<<<BATCH, 256>>>(act3, st3, wfc1, bfc1, wfc2, bfc2, out);
}

// round 6
// speedup vs baseline: 1.6958x; 1.0463x over previous
#include <cuda_runtime.h>
#include <math.h>
#include <stdint.h>

#define BATCH 128
#define NNODES 1024
#define NTRI 1023
#define T3 3069

typedef unsigned long long u64;

// Persistent scratch. Node-major activations: [tower*128+b][node][C],
// node 0 is the shared zero node for act1/2/3.
__device__ float g_act0[(size_t)2*BATCH*NNODES*64];    //  64 MB
__device__ float g_act1[(size_t)2*BATCH*NNODES*256];   // 256 MB
__device__ float g_act2[(size_t)2*BATCH*NNODES*128];   // 128 MB
__device__ float g_act3[(size_t)2*BATCH*NNODES*64];    //  64 MB
__device__ float g_wrt1[256*192];   // [O][CK] weights, ck = k*C + c
__device__ float g_wrt2[128*768];
__device__ float g_wrt3[64*384];
__device__ float g_part[2*BATCH*16*2]; // per-block {sum, sumsq} partials
__device__ float g_st1[2*BATCH*2];  // {mean, 1/(std+1e-5)} per (tower,b)
__device__ float g_st2[2*BATCH*2];
__device__ float g_st3[2*BATCH*2];

// ---- packed f32x2 helpers ---------------------------------------------------
__device__ __forceinline__ void fma_f32x2(u64& d, u64 a, u64 b) {
    asm("fma.rn.f32x2 %0, %1, %2, %0;" : "+l"(d) : "l"(a), "l"(b));
}
__device__ __forceinline__ float2 unpack2(u64 v) {
    float2 f;
    asm("mov.b64 {%0, %1}, %2;" : "=f"(f.x), "=f"(f.y) : "l"(v));
    return f;
}
__device__ __forceinline__ uint32_t smem_u32(const void* p) {
    uint32_t a;
    asm("{ .reg .u64 t; cvta.to.shared.u64 t, %1; cvt.u32.u64 %0, t; }"
        : "=r"(a) : "l"(p));
    return a;
}
#define CP16(dst, src) \
    asm volatile("cp.async.cg.shared.global [%0], [%1], 16;" :: "r"(dst), "l"(src))
#define CPCOMMIT() asm volatile("cp.async.commit_group;" ::: "memory")

// ---------------------------------------------------------------------------
// Transpose raw input [b][C=64][N=1024] -> act0 [tower*128+b][N][64]
// ---------------------------------------------------------------------------
__global__ __launch_bounds__(256) void transpose_kernel(
    const float* __restrict__ d1, const float* __restrict__ d2,
    float* __restrict__ act0)
{
    __shared__ float tile[32][33];
    int tb = blockIdx.z;
    int tower = tb / BATCH, b = tb % BATCH;
    const float* src = (tower ? d2 : d1) + (size_t)b * 64 * NNODES; // [64][1024]
    float* dst = act0 + (size_t)tb * NNODES * 64;                   // [1024][64]
    int n0 = blockIdx.x * 32, c0 = blockIdx.y * 32;
    for (int i = threadIdx.y; i < 32; i += 8)
        tile[i][threadIdx.x] = src[(size_t)(c0 + i) * NNODES + n0 + threadIdx.x];
    __syncthreads();
    for (int i = threadIdx.y; i < 32; i += 8)
        dst[(size_t)(n0 + i) * 64 + c0 + threadIdx.x] = tile[threadIdx.x][i];
}

// ---------------------------------------------------------------------------
// Reorder conv weights: w[o][c][k] -> wrt[o][ck] with ck = k*C + c
// ---------------------------------------------------------------------------
__global__ void reorder_w(const float* __restrict__ w, float* __restrict__ wrt,
                          int O, int C)
{
    int i = blockIdx.x * blockDim.x + threadIdx.x;
    int CK = C * 3;
    if (i < O * CK) {
        int o = i / CK, ck = i - o * CK;
        int k = ck / C, c = ck - k * C;
        wrt[i] = w[(o * C + c) * 3 + k];
    }
}

// ---------------------------------------------------------------------------
// Zero the "zero node" row (node 0) of act1/2/3 for every (tower, b)
// ---------------------------------------------------------------------------
__global__ void zero_rows(float* a1, float* a2, float* a3)
{
    int tb = blockIdx.x;
    for (int i = threadIdx.x; i < 256; i += blockDim.x) a1[(size_t)tb * NNODES * 256 + i] = 0.f;
    for (int i = threadIdx.x; i < 128; i += blockDim.x) a2[(size_t)tb * NNODES * 128 + i] = 0.f;
    for (int i = threadIdx.x; i <  64; i += blockDim.x) a3[(size_t)tb * NNODES *  64 + i] = 0.f;
}

// ---------------------------------------------------------------------------
// Elementwise in-place LN + leakyReLU: act[tb][*] = lrelu((x - mean)*inv).
// Applied AFTER finalize_stats; node-0 row transforms from 0 exactly as the
// reference requires. grid = (NNODES*O/4/256, 2*BATCH)
// ---------------------------------------------------------------------------
__global__ __launch_bounds__(256) void transform_act(
    float* __restrict__ act, const float* __restrict__ stats, int O)
{
    int tb = blockIdx.y;
    float mean = stats[tb * 2], inv = stats[tb * 2 + 1];
    float4* a = reinterpret_cast<float4*>(act + (size_t)tb * NNODES * O);
    int i = blockIdx.x * 256 + threadIdx.x;
    float4 v = a[i];
    v.x = (v.x - mean) * inv; v.x = v.x > 0.f ? v.x : 0.01f * v.x;
    v.y = (v.y - mean) * inv; v.y = v.y > 0.f ? v.y : 0.01f * v.y;
    v.z = (v.z - mean) * inv; v.z = v.z > 0.f ? v.z : 0.01f * v.z;
    v.w = (v.w - mean) * inv; v.w = v.w > 0.f ? v.w : 0.01f * v.w;
    a[i] = v;
}

// ---------------------------------------------------------------------------
// Gather-conv GEMM, cp.async double-buffered tiles, K-paired f32x2.
// TM=128 triples/block, 16 warps x TMpt=8 triples, TO=Oc/32 outputs/lane.
// Input activations are PRE-transformed (plain copy gather).
// ---------------------------------------------------------------------------
template<int C, int O, int OCH>
__global__ __launch_bounds__(512, 1) void conv_kernel(
    const float* __restrict__ actin,
    const int* __restrict__ idxA, const int* __restrict__ idxB,
    const float* __restrict__ wrt,      // [O][CK]
    const float* __restrict__ bias,     // [O]
    float* __restrict__ actout,         // [2*BATCH][NNODES][O]
    float* __restrict__ part)           // [2*BATCH][16][2]
{
    constexpr int TM = 128;
    constexpr int CK = 3 * C;
    constexpr int KT = 64;
    constexpr int Oc = O / OCH;
    constexpr int WST = KT + 4;         // 68: LDS.128 conflict-free, 16B-aligned rows
    constexpr int TO = Oc / 32;
    constexpr int TMpt = 8;
    constexpr int NT = CK / KT;

    extern __shared__ float smem[];
    float* g_b[2] = { smem, smem + TM * KT };               // 2 x [TM][KT]
    float* w_b[2] = { smem + 2 * TM * KT,
                      smem + 2 * TM * KT + Oc * WST };      // 2 x [Oc][WST]
    __shared__ int nodes[TM * 3];
    __shared__ float red[32];

    const int tid = threadIdx.x;
    const int och = blockIdx.x % OCH;
    const int m0 = (blockIdx.x / OCH) * TM;
    const int tb = blockIdx.z * BATCH + blockIdx.y;

    const int* idx = (blockIdx.z ? idxB : idxA) + blockIdx.y * T3;
    const float* ain = actin + (size_t)tb * NNODES * C;

    if (tid < TM * 3) {
        int t = m0 * 3 + tid;
        nodes[tid] = (t < T3) ? idx[t] : 0;
    }
    __syncthreads();

    const uint32_t g_s32[2] = { smem_u32(g_b[0]), smem_u32(g_b[1]) };
    const uint32_t w_s32[2] = { smem_u32(w_b[0]), smem_u32(w_b[1]) };

    // issue cp.async for tile t into buffer buf
    auto issue = [&](int t, int buf) {
        const int ck0 = t * KT;
        const int k = ck0 / C;
        const int cbase = ck0 - k * C;
        // w tile: Oc*KT floats = Oc*16 16B chunks
#pragma unroll 4
        for (int e = tid; e < Oc * 16; e += 512) {
            int o = e >> 4, q = e & 15;
            uint32_t dst = w_s32[buf] + (uint32_t)(o * WST + q * 4) * 4u;
            const float* src = wrt + (size_t)(och * Oc + o) * CK + ck0 + q * 4;
            CP16(dst, src);
        }
        // g tile: TM*KT floats = TM*16 chunks
#pragma unroll 4
        for (int e = tid; e < TM * 16; e += 512) {
            int r = e >> 4, q = e & 15;
            int node = nodes[r * 3 + k];
            uint32_t dst = g_s32[buf] + (uint32_t)(r * KT + q * 4) * 4u;
            const float* src = ain + (size_t)node * C + cbase + q * 4;
            CP16(dst, src);
        }
        CPCOMMIT();
    };

    u64 acc[TO][TMpt];
#pragma unroll
    for (int i = 0; i < TO; i++)
#pragma unroll
        for (int j = 0; j < TMpt; j++) acc[i][j] = 0ull;

    const int lane = tid & 31;
    const int warp = tid >> 5;

    issue(0, 0);

    for (int t = 0; t < NT; t++) {
        if (t + 1 < NT) {
            issue(t + 1, (t + 1) & 1);
            asm volatile("cp.async.wait_group 1;" ::: "memory");
        } else {
            asm volatile("cp.async.wait_group 0;" ::: "memory");
        }
        __syncthreads();

        const float* grow0 = g_b[t & 1] + (warp * TMpt) * KT;
        const float* wbuf = w_b[t & 1];
#pragma unroll 4
        for (int kk = 0; kk < KT; kk += 4) {
            ulonglong2 wv[TO];
#pragma unroll
            for (int i = 0; i < TO; i++)
                wv[i] = *reinterpret_cast<const ulonglong2*>(wbuf + (lane + 32 * i) * WST + kk);
#pragma unroll
            for (int j = 0; j < TMpt; j++) {
                ulonglong2 gv = *reinterpret_cast<const ulonglong2*>(grow0 + j * KT + kk);
#pragma unroll
                for (int i = 0; i < TO; i++) {
                    fma_f32x2(acc[i][j], wv[i].x, gv.x);
                    fma_f32x2(acc[i][j], wv[i].y, gv.y);
                }
            }
        }
        __syncthreads();
    }

    // Epilogue: store + fp32 partial stats
    float ls = 0.f, lss = 0.f;
    float* aout = actout + (size_t)tb * NNODES * O;
#pragma unroll
    for (int j = 0; j < TMpt; j++) {
        int mt = m0 + warp * TMpt + j;
        if (mt < NTRI) {
#pragma unroll
            for (int i = 0; i < TO; i++) {
                int o = och * Oc + lane + 32 * i;
                float2 p = unpack2(acc[i][j]);
                float v = p.x + p.y + bias[o];
                aout[(size_t)(mt + 1) * O + o] = v;
                ls += v;
                lss = fmaf(v, v, lss);
            }
        }
    }
#pragma unroll
    for (int off = 16; off > 0; off >>= 1) {
        ls  += __shfl_xor_sync(0xffffffffu, ls,  off);
        lss += __shfl_xor_sync(0xffffffffu, lss, off);
    }
    if (lane == 0) { red[warp] = ls; red[16 + warp] = lss; }
    __syncthreads();
    if (tid == 0) {
        float s = 0.f, ss = 0.f;
#pragma unroll
        for (int wv2 = 0; wv2 < 16; wv2++) { s += red[wv2]; ss += red[16 + wv2]; }
        float* pp = part + ((size_t)tb * 16 + blockIdx.x) * 2;
        pp[0] = s; pp[1] = ss;
    }
}

// ---------------------------------------------------------------------------
// Finalize stats: reduce nparts partials per (tower,b) -> {mean, 1/(std+1e-5)}
// ---------------------------------------------------------------------------
__global__ __launch_bounds__(256) void finalize_stats(
    const float* __restrict__ part, float* __restrict__ stats, int O, int nparts)
{
    int tb = threadIdx.x;
    double s = 0.0, ss = 0.0;
    for (int i = 0; i < nparts; i++) {
        s += (double)part[((size_t)tb * 16 + i) * 2];
        ss += (double)part[((size_t)tb * 16 + i) * 2 + 1];
    }
    double n = 1024.0 * O;
    double mean = s / n;
    double var = (ss - s * s / n) / (n - 1.0);
    if (var < 0.0) var = 0.0;
    stats[tb * 2] = (float)mean;
    stats[tb * 2 + 1] = (float)(1.0 / (sqrt(var) + 1e-5));
}

// ---------------------------------------------------------------------------
// Final: LN(act3) -> channel max over nodes -> FC1(lrelu) -> FC2 ->
//        sigmoid(y_tower0 - y_tower1). One block per batch element.
// ---------------------------------------------------------------------------
__global__ __launch_bounds__(256) void final_kernel(
    const float* __restrict__ act3, const float* __restrict__ stats3,
    const float* __restrict__ wfc1, const float* __restrict__ bfc1,
    const float* __restrict__ wfc2, const float* __restrict__ bfc2,
    float* __restrict__ out)
{
    int b = blockIdx.x;
    int tid = threadIdx.x;
    __shared__ float mx[4][64];
    __shared__ float h[32];
    __shared__ float yy[2];

    for (int tower = 0; tower < 2; tower++) {
        int tb = tower * BATCH + b;
        float mean = stats3[tb * 2], inv = stats3[tb * 2 + 1];
        const float* a = act3 + (size_t)tb * NNODES * 64;
        int c = tid & 63, grp = tid >> 6;
        float m = -1e30f;
        for (int n = grp; n < NNODES; n += 4) {
            float v = (a[(size_t)n * 64 + c] - mean) * inv;
            m = fmaxf(m, v);
        }
        mx[grp][c] = m;
        __syncthreads();
        if (tid < 64) {
            mx[0][tid] = fmaxf(fmaxf(mx[0][tid], mx[1][tid]),
                               fmaxf(mx[2][tid], mx[3][tid]));
        }
        __syncthreads();
        if (tid < 32) {
            float sAcc = bfc1[tid];
            for (int c2 = 0; c2 < 64; c2++) sAcc = fmaf(mx[0][c2], wfc1[tid * 64 + c2], sAcc);
            h[tid] = sAcc > 0.f ? sAcc : 0.01f * sAcc;
        }
        __syncthreads();
        if (tid == 0) {
            float sAcc = bfc2[0];
            for (int i = 0; i < 32; i++) sAcc = fmaf(h[i], wfc2[i], sAcc);
            yy[tower] = sAcc;
        }
        __syncthreads();
    }
    if (tid == 0) {
        float d = yy[0] - yy[1];
        out[b] = 1.f / (1.f + expf(-d));
    }
}

// ---------------------------------------------------------------------------
extern "C" void kernel_launch(void* const* d_in, const int* in_sizes, int n_in,
                              void* d_out, int out_size)
{
    const float* data1 = (const float*)d_in[0];
    const int*   idx1  = (const int*)d_in[1];
    const float* data2 = (const float*)d_in[2];
    const int*   idx2  = (const int*)d_in[3];
    const float* w1 = (const float*)d_in[4];
    const float* b1 = (const float*)d_in[5];
    const float* w2 = (const float*)d_in[6];
    const float* b2 = (const float*)d_in[7];
    const float* w3 = (const float*)d_in[8];
    const float* b3 = (const float*)d_in[9];
    const float* wfc1 = (const float*)d_in[10];
    const float* bfc1 = (const float*)d_in[11];
    const float* wfc2 = (const float*)d_in[12];
    const float* bfc2 = (const float*)d_in[13];
    float* out = (float*)d_out;

    float *act0, *act1, *act2, *act3, *wrt1, *wrt2, *wrt3, *part, *st1, *st2, *st3;
    cudaGetSymbolAddress((void**)&act0, g_act0);
    cudaGetSymbolAddress((void**)&act1, g_act1);
    cudaGetSymbolAddress((void**)&act2, g_act2);
    cudaGetSymbolAddress((void**)&act3, g_act3);
    cudaGetSymbolAddress((void**)&wrt1, g_wrt1);
    cudaGetSymbolAddress((void**)&wrt2, g_wrt2);
    cudaGetSymbolAddress((void**)&wrt3, g_wrt3);
    cudaGetSymbolAddress((void**)&part, g_part);
    cudaGetSymbolAddress((void**)&st1, g_st1);
    cudaGetSymbolAddress((void**)&st2, g_st2);
    cudaGetSymbolAddress((void**)&st3, g_st3);

    // smem: g 2*128*64*4 = 65536, w 2*Oc*68*4
    const int smem12 = 65536 + 2 * 128 * 68 * 4;  // 135168 (Oc=128)
    const int smem3  = 65536 + 2 *  64 * 68 * 4;  // 100352 (Oc=64)
    cudaFuncSetAttribute(conv_kernel<64, 256, 2>,
                         cudaFuncAttributeMaxDynamicSharedMemorySize, smem12);
    cudaFuncSetAttribute(conv_kernel<256, 128, 1>,
                         cudaFuncAttributeMaxDynamicSharedMemorySize, smem12);
    cudaFuncSetAttribute(conv_kernel<128, 64, 1>,
                         cudaFuncAttributeMaxDynamicSharedMemorySize, smem3);

    transpose_kernel<<<dim3(32, 2, 256), dim3(32, 8)>>>(data1, data2, act0);
    reorder_w<<<(256 * 192 + 255) / 256, 256>>>(w1, wrt1, 256, 64);
    zero_rows<<<256, 256>>>(act1, act2, act3);

    conv_kernel<64, 256, 2><<<dim3(16, BATCH, 2), 512, smem12>>>(
        act0, idx1, idx2, wrt1, b1, act1, part);
    finalize_stats<<<1, 256>>>(part, st1, 256, 16);
    transform_act<<<dim3(NNODES * 256 / 4 / 256, 256), 256>>>(act1, st1, 256);
    reorder_w<<<(128 * 768 + 255) / 256, 256>>>(w2, wrt2, 128, 256);

    conv_kernel<256, 128, 1><<<dim3(8, BATCH, 2), 512, smem12>>>(
        act1, idx1, idx2, wrt2, b2, act2, part);
    finalize_stats<<<1, 256>>>(part, st2, 128, 8);
    transform_act<<<dim3(NNODES * 128 / 4 / 256, 256), 256>>>(act2, st2, 128);
    reorder_w<<<(64 * 384 + 255) / 256, 256>>>(w3, wrt3, 64, 128);

    conv_kernel<128, 64, 1><<<dim3(8, BATCH, 2), 512, smem3>>>(
        act2, idx1, idx2, wrt3, b3, act3, part);
    finalize_stats<<<1, 256>>>(part, st3, 64, 8);

    final_kernel<<<BATCH, 256>>>(act3, st3, wfc1, bfc1, wfc2, bfc2, out);
}

// round 7
// speedup vs baseline: 1.7032x; 1.0044x over previous
#include <cuda_runtime.h>
#include <math.h>
#include <stdint.h>

#define BATCH 128
#define NNODES 1024
#define NTRI 1023
#define T3 3069

typedef unsigned long long u64;

// Persistent scratch. Node-major activations: [tower*128+b][node][C],
// node 0 is the shared zero node for act1/2/3.
__device__ float g_act0[(size_t)2*BATCH*NNODES*64];    //  64 MB
__device__ float g_act1[(size_t)2*BATCH*NNODES*256];   // 256 MB
__device__ float g_act2[(size_t)2*BATCH*NNODES*128];   // 128 MB
__device__ float g_act3[(size_t)2*BATCH*NNODES*64];    //  64 MB
__device__ float g_wrt1[256*192];   // [O][CK] weights, ck = k*C + c
__device__ float g_wrt2[128*768];
__device__ float g_wrt3[64*384];
__device__ float g_part[2*BATCH*32*2]; // per-block {sum, sumsq} partials
__device__ float g_st1[2*BATCH*2];  // {mean, 1/(std+1e-5)} per (tower,b)
__device__ float g_st2[2*BATCH*2];
__device__ float g_st3[2*BATCH*2];

// ---- packed f32x2 helpers ---------------------------------------------------
__device__ __forceinline__ void fma_f32x2(u64& d, u64 a, u64 b) {
    asm("fma.rn.f32x2 %0, %1, %2, %0;" : "+l"(d) : "l"(a), "l"(b));
}
__device__ __forceinline__ float2 unpack2(u64 v) {
    float2 f;
    asm("mov.b64 {%0, %1}, %2;" : "=f"(f.x), "=f"(f.y) : "l"(v));
    return f;
}
__device__ __forceinline__ uint32_t smem_u32(const void* p) {
    uint32_t a;
    asm("{ .reg .u64 t; cvta.to.shared.u64 t, %1; cvt.u32.u64 %0, t; }"
        : "=r"(a) : "l"(p));
    return a;
}
#define CP16(dst, src) \
    asm volatile("cp.async.cg.shared.global [%0], [%1], 16;" :: "r"(dst), "l"(src))
#define CPCOMMIT() asm volatile("cp.async.commit_group;" ::: "memory")

// ---------------------------------------------------------------------------
// Transpose raw input [b][C=64][N=1024] -> act0 [tower*128+b][N][64]
// ---------------------------------------------------------------------------
__global__ __launch_bounds__(256) void transpose_kernel(
    const float* __restrict__ d1, const float* __restrict__ d2,
    float* __restrict__ act0)
{
    __shared__ float tile[32][33];
    int tb = blockIdx.z;
    int tower = tb / BATCH, b = tb % BATCH;
    const float* src = (tower ? d2 : d1) + (size_t)b * 64 * NNODES; // [64][1024]
    float* dst = act0 + (size_t)tb * NNODES * 64;                   // [1024][64]
    int n0 = blockIdx.x * 32, c0 = blockIdx.y * 32;
    for (int i = threadIdx.y; i < 32; i += 8)
        tile[i][threadIdx.x] = src[(size_t)(c0 + i) * NNODES + n0 + threadIdx.x];
    __syncthreads();
    for (int i = threadIdx.y; i < 32; i += 8)
        dst[(size_t)(n0 + i) * 64 + c0 + threadIdx.x] = tile[threadIdx.x][i];
}

// ---------------------------------------------------------------------------
// Reorder conv weights: w[o][c][k] -> wrt[o][ck] with ck = k*C + c
// ---------------------------------------------------------------------------
__global__ void reorder_w(const float* __restrict__ w, float* __restrict__ wrt,
                          int O, int C)
{
    int i = blockIdx.x * blockDim.x + threadIdx.x;
    int CK = C * 3;
    if (i < O * CK) {
        int o = i / CK, ck = i - o * CK;
        int k = ck / C, c = ck - k * C;
        wrt[i] = w[(o * C + c) * 3 + k];
    }
}

// ---------------------------------------------------------------------------
// Zero the "zero node" row (node 0) of act1/2/3 for every (tower, b)
// ---------------------------------------------------------------------------
__global__ void zero_rows(float* a1, float* a2, float* a3)
{
    int tb = blockIdx.x;
    for (int i = threadIdx.x; i < 256; i += blockDim.x) a1[(size_t)tb * NNODES * 256 + i] = 0.f;
    for (int i = threadIdx.x; i < 128; i += blockDim.x) a2[(size_t)tb * NNODES * 128 + i] = 0.f;
    for (int i = threadIdx.x; i <  64; i += blockDim.x) a3[(size_t)tb * NNODES *  64 + i] = 0.f;
}

// ---------------------------------------------------------------------------
// Elementwise in-place LN + leakyReLU: act[tb][*] = lrelu((x - mean)*inv).
// ---------------------------------------------------------------------------
__global__ __launch_bounds__(256) void transform_act(
    float* __restrict__ act, const float* __restrict__ stats, int O)
{
    int tb = blockIdx.y;
    float mean = stats[tb * 2], inv = stats[tb * 2 + 1];
    float4* a = reinterpret_cast<float4*>(act + (size_t)tb * NNODES * O);
    int i = blockIdx.x * 256 + threadIdx.x;
    float4 v = a[i];
    v.x = (v.x - mean) * inv; v.x = v.x > 0.f ? v.x : 0.01f * v.x;
    v.y = (v.y - mean) * inv; v.y = v.y > 0.f ? v.y : 0.01f * v.y;
    v.z = (v.z - mean) * inv; v.z = v.z > 0.f ? v.z : 0.01f * v.z;
    v.w = (v.w - mean) * inv; v.w = v.w > 0.f ? v.w : 0.01f * v.w;
    a[i] = v;
}

// ---------------------------------------------------------------------------
// Gather-conv GEMM, cp.async double-buffered tiles, K-paired f32x2.
// 256 threads (8 warps), TM=64 triples, TMpt=8, TO=Oc/32. 2 blocks/SM.
// Input activations are PRE-transformed (plain copy gather).
// ---------------------------------------------------------------------------
template<int C, int O, int OCH>
__global__ __launch_bounds__(256, 2) void conv_kernel(
    const float* __restrict__ actin,
    const int* __restrict__ idxA, const int* __restrict__ idxB,
    const float* __restrict__ wrt,      // [O][CK]
    const float* __restrict__ bias,     // [O]
    float* __restrict__ actout,         // [2*BATCH][NNODES][O]
    float* __restrict__ part)           // [2*BATCH][32][2]
{
    constexpr int TM = 64;
    constexpr int CK = 3 * C;
    constexpr int KT = 64;
    constexpr int Oc = O / OCH;
    constexpr int WST = KT + 4;         // 68: LDS.128 conflict-free, 16B rows
    constexpr int TO = Oc / 32;
    constexpr int TMpt = 8;
    constexpr int NT = CK / KT;

    extern __shared__ float smem[];
    float* g_b[2] = { smem, smem + TM * KT };               // 2 x [TM][KT]
    float* w_b[2] = { smem + 2 * TM * KT,
                      smem + 2 * TM * KT + Oc * WST };      // 2 x [Oc][WST]
    __shared__ int nodes[TM * 3];
    __shared__ float red[16];

    const int tid = threadIdx.x;
    const int och = blockIdx.x % OCH;
    const int m0 = (blockIdx.x / OCH) * TM;
    const int tb = blockIdx.z * BATCH + blockIdx.y;

    const int* idx = (blockIdx.z ? idxB : idxA) + blockIdx.y * T3;
    const float* ain = actin + (size_t)tb * NNODES * C;

    if (tid < TM * 3) {
        int t = m0 * 3 + tid;
        nodes[tid] = (t < T3) ? idx[t] : 0;
    }
    __syncthreads();

    const uint32_t g_s32[2] = { smem_u32(g_b[0]), smem_u32(g_b[1]) };
    const uint32_t w_s32[2] = { smem_u32(w_b[0]), smem_u32(w_b[1]) };

    auto issue = [&](int t, int buf) {
        const int ck0 = t * KT;
        const int k = ck0 / C;
        const int cbase = ck0 - k * C;
#pragma unroll 4
        for (int e = tid; e < Oc * 16; e += 256) {
            int o = e >> 4, q = e & 15;
            uint32_t dst = w_s32[buf] + (uint32_t)(o * WST + q * 4) * 4u;
            const float* src = wrt + (size_t)(och * Oc + o) * CK + ck0 + q * 4;
            CP16(dst, src);
        }
#pragma unroll 4
        for (int e = tid; e < TM * 16; e += 256) {
            int r = e >> 4, q = e & 15;
            int node = nodes[r * 3 + k];
            uint32_t dst = g_s32[buf] + (uint32_t)(r * KT + q * 4) * 4u;
            const float* src = ain + (size_t)node * C + cbase + q * 4;
            CP16(dst, src);
        }
        CPCOMMIT();
    };

    u64 acc[TO][TMpt];
#pragma unroll
    for (int i = 0; i < TO; i++)
#pragma unroll
        for (int j = 0; j < TMpt; j++) acc[i][j] = 0ull;

    const int lane = tid & 31;
    const int warp = tid >> 5;

    issue(0, 0);

    for (int t = 0; t < NT; t++) {
        if (t + 1 < NT) {
            issue(t + 1, (t + 1) & 1);
            asm volatile("cp.async.wait_group 1;" ::: "memory");
        } else {
            asm volatile("cp.async.wait_group 0;" ::: "memory");
        }
        __syncthreads();

        const float* grow0 = g_b[t & 1] + (warp * TMpt) * KT;
        const float* wbuf = w_b[t & 1];
#pragma unroll 4
        for (int kk = 0; kk < KT; kk += 4) {
            ulonglong2 wv[TO];
#pragma unroll
            for (int i = 0; i < TO; i++)
                wv[i] = *reinterpret_cast<const ulonglong2*>(wbuf + (lane + 32 * i) * WST + kk);
            ulonglong2 gv[TMpt];
#pragma unroll
            for (int j = 0; j < TMpt; j++)
                gv[j] = *reinterpret_cast<const ulonglong2*>(grow0 + j * KT + kk);
#pragma unroll
            for (int j = 0; j < TMpt; j++) {
#pragma unroll
                for (int i = 0; i < TO; i++) {
                    fma_f32x2(acc[i][j], wv[i].x, gv[j].x);
                    fma_f32x2(acc[i][j], wv[i].y, gv[j].y);
                }
            }
        }
        __syncthreads();
    }

    // Epilogue: store + fp32 partial stats
    float ls = 0.f, lss = 0.f;
    float* aout = actout + (size_t)tb * NNODES * O;
#pragma unroll
    for (int j = 0; j < TMpt; j++) {
        int mt = m0 + warp * TMpt + j;
        if (mt < NTRI) {
#pragma unroll
            for (int i = 0; i < TO; i++) {
                int o = och * Oc + lane + 32 * i;
                float2 p = unpack2(acc[i][j]);
                float v = p.x + p.y + bias[o];
                aout[(size_t)(mt + 1) * O + o] = v;
                ls += v;
                lss = fmaf(v, v, lss);
            }
        }
    }
#pragma unroll
    for (int off = 16; off > 0; off >>= 1) {
        ls  += __shfl_xor_sync(0xffffffffu, ls,  off);
        lss += __shfl_xor_sync(0xffffffffu, lss, off);
    }
    if (lane == 0) { red[warp] = ls; red[8 + warp] = lss; }
    __syncthreads();
    if (tid == 0) {
        float s = 0.f, ss = 0.f;
#pragma unroll
        for (int wv2 = 0; wv2 < 8; wv2++) { s += red[wv2]; ss += red[8 + wv2]; }
        float* pp = part + ((size_t)tb * 32 + blockIdx.x) * 2;
        pp[0] = s; pp[1] = ss;
    }
}

// ---------------------------------------------------------------------------
// Finalize stats: reduce nparts partials per (tower,b) -> {mean, 1/(std+1e-5)}
// ---------------------------------------------------------------------------
__global__ __launch_bounds__(256) void finalize_stats(
    const float* __restrict__ part, float* __restrict__ stats, int O, int nparts)
{
    int tb = threadIdx.x;
    double s = 0.0, ss = 0.0;
    for (int i = 0; i < nparts; i++) {
        s += (double)part[((size_t)tb * 32 + i) * 2];
        ss += (double)part[((size_t)tb * 32 + i) * 2 + 1];
    }
    double n = 1024.0 * O;
    double mean = s / n;
    double var = (ss - s * s / n) / (n - 1.0);
    if (var < 0.0) var = 0.0;
    stats[tb * 2] = (float)mean;
    stats[tb * 2 + 1] = (float)(1.0 / (sqrt(var) + 1e-5));
}

// ---------------------------------------------------------------------------
// Final: LN(act3) -> channel max over nodes -> FC1(lrelu) -> FC2 ->
//        sigmoid(y_tower0 - y_tower1). One block per batch element.
// ---------------------------------------------------------------------------
__global__ __launch_bounds__(256) void final_kernel(
    const float* __restrict__ act3, const float* __restrict__ stats3,
    const float* __restrict__ wfc1, const float* __restrict__ bfc1,
    const float* __restrict__ wfc2, const float* __restrict__ bfc2,
    float* __restrict__ out)
{
    int b = blockIdx.x;
    int tid = threadIdx.x;
    __shared__ float mx[4][64];
    __shared__ float h[32];
    __shared__ float yy[2];

    for (int tower = 0; tower < 2; tower++) {
        int tb = tower * BATCH + b;
        float mean = stats3[tb * 2], inv = stats3[tb * 2 + 1];
        const float* a = act3 + (size_t)tb * NNODES * 64;
        int c = tid & 63, grp = tid >> 6;
        float m = -1e30f;
        for (int n = grp; n < NNODES; n += 4) {
            float v = (a[(size_t)n * 64 + c] - mean) * inv;
            m = fmaxf(m, v);
        }
        mx[grp][c] = m;
        __syncthreads();
        if (tid < 64) {
            mx[0][tid] = fmaxf(fmaxf(mx[0][tid], mx[1][tid]),
                               fmaxf(mx[2][tid], mx[3][tid]));
        }
        __syncthreads();
        if (tid < 32) {
            float sAcc = bfc1[tid];
            for (int c2 = 0; c2 < 64; c2++) sAcc = fmaf(mx[0][c2], wfc1[tid * 64 + c2], sAcc);
            h[tid] = sAcc > 0.f ? sAcc : 0.01f * sAcc;
        }
        __syncthreads();
        if (tid == 0) {
            float sAcc = bfc2[0];
            for (int i = 0; i < 32; i++) sAcc = fmaf(h[i], wfc2[i], sAcc);
            yy[tower] = sAcc;
        }
        __syncthreads();
    }
    if (tid == 0) {
        float d = yy[0] - yy[1];
        out[b] = 1.f / (1.f + expf(-d));
    }
}

// ---------------------------------------------------------------------------
extern "C" void kernel_launch(void* const* d_in, const int* in_sizes, int n_in,
                              void* d_out, int out_size)
{
    const float* data1 = (const float*)d_in[0];
    const int*   idx1  = (const int*)d_in[1];
    const float* data2 = (const float*)d_in[2];
    const int*   idx2  = (const int*)d_in[3];
    const float* w1 = (const float*)d_in[4];
    const float* b1 = (const float*)d_in[5];
    const float* w2 = (const float*)d_in[6];
    const float* b2 = (const float*)d_in[7];
    const float* w3 = (const float*)d_in[8];
    const float* b3 = (const float*)d_in[9];
    const float* wfc1 = (const float*)d_in[10];
    const float* bfc1 = (const float*)d_in[11];
    const float* wfc2 = (const float*)d_in[12];
    const float* bfc2 = (const float*)d_in[13];
    float* out = (float*)d_out;

    float *act0, *act1, *act2, *act3, *wrt1, *wrt2, *wrt3, *part, *st1, *st2, *st3;
    cudaGetSymbolAddress((void**)&act0, g_act0);
    cudaGetSymbolAddress((void**)&act1, g_act1);
    cudaGetSymbolAddress((void**)&act2, g_act2);
    cudaGetSymbolAddress((void**)&act3, g_act3);
    cudaGetSymbolAddress((void**)&wrt1, g_wrt1);
    cudaGetSymbolAddress((void**)&wrt2, g_wrt2);
    cudaGetSymbolAddress((void**)&wrt3, g_wrt3);
    cudaGetSymbolAddress((void**)&part, g_part);
    cudaGetSymbolAddress((void**)&st1, g_st1);
    cudaGetSymbolAddress((void**)&st2, g_st2);
    cudaGetSymbolAddress((void**)&st3, g_st3);

    // smem: g 2*64*64*4 = 32768, w 2*Oc*68*4
    const int smem12 = 32768 + 2 * 128 * 68 * 4;  // 102400 (Oc=128) -> 2 blocks/SM
    const int smem3  = 32768 + 2 *  64 * 68 * 4;  //  67584 (Oc=64)
    cudaFuncSetAttribute(conv_kernel<64, 256, 2>,
                         cudaFuncAttributeMaxDynamicSharedMemorySize, smem12);
    cudaFuncSetAttribute(conv_kernel<256, 128, 1>,
                         cudaFuncAttributeMaxDynamicSharedMemorySize, smem12);
    cudaFuncSetAttribute(conv_kernel<128, 64, 1>,
                         cudaFuncAttributeMaxDynamicSharedMemorySize, smem3);

    transpose_kernel<<<dim3(32, 2, 256), dim3(32, 8)>>>(data1, data2, act0);
    reorder_w<<<(256 * 192 + 255) / 256, 256>>>(w1, wrt1, 256, 64);
    zero_rows<<<256, 256>>>(act1, act2, act3);

    // m-tiles: 1024/64 = 16
    conv_kernel<64, 256, 2><<<dim3(32, BATCH, 2), 256, smem12>>>(
        act0, idx1, idx2, wrt1, b1, act1, part);
    finalize_stats<<<1, 256>>>(part, st1, 256, 32);
    transform_act<<<dim3(NNODES * 256 / 4 / 256, 256), 256>>>(act1, st1, 256);
    reorder_w<<<(128 * 768 + 255) / 256, 256>>>(w2, wrt2, 128, 256);

    conv_kernel<256, 128, 1><<<dim3(16, BATCH, 2), 256, smem12>>>(
        act1, idx1, idx2, wrt2, b2, act2, part);
    finalize_stats<<<1, 256>>>(part, st2, 128, 16);
    transform_act<<<dim3(NNODES * 128 / 4 / 256, 256), 256>>>(act2, st2, 128);
    reorder_w<<<(64 * 384 + 255) / 256, 256>>>(w3, wrt3, 64, 128);

    conv_kernel<128, 64, 1><<<dim3(16, BATCH, 2), 256, smem3>>>(
        act2, idx1, idx2, wrt3, b3, act3, part);
    finalize_stats<<<1, 256>>>(part, st3, 64, 16);

    final_kernel<<<BATCH, 256>>>(act3, st3, wfc1, bfc1, wfc2, bfc2, out);
}

// round 9
// speedup vs baseline: 3.7696x; 2.2133x over previous
#include <cuda_runtime.h>
#include <cuda_bf16.h>
#include <math.h>
#include <stdint.h>

#define BATCH 128
#define NNODES 1024
#define NTRI 1023
#define T3 3069

typedef unsigned long long u64;

// f32 activations (conv outputs; node-major [tower*128+b][node][C])
__device__ float g_act0[(size_t)2*BATCH*NNODES*64];
__device__ float g_act1[(size_t)2*BATCH*NNODES*256];
__device__ float g_act2[(size_t)2*BATCH*NNODES*128];
__device__ float g_act3[(size_t)2*BATCH*NNODES*64];
// bf16 hi/lo split activations (conv inputs)
__device__ __nv_bfloat16 g_a0h[(size_t)2*BATCH*NNODES*64];
__device__ __nv_bfloat16 g_a0l[(size_t)2*BATCH*NNODES*64];
__device__ __nv_bfloat16 g_a1h[(size_t)2*BATCH*NNODES*256];
__device__ __nv_bfloat16 g_a1l[(size_t)2*BATCH*NNODES*256];
__device__ __nv_bfloat16 g_a2h[(size_t)2*BATCH*NNODES*128];
__device__ __nv_bfloat16 g_a2l[(size_t)2*BATCH*NNODES*128];
// Weight images: bf16 hi/lo, per (och,kt) 64x64 SW128-swizzled tiles (4096 elems)
__device__ __nv_bfloat16 g_whi1[4*3*4096],  g_wlo1[4*3*4096];   // O=256,CK=192
__device__ __nv_bfloat16 g_whi2[2*12*4096], g_wlo2[2*12*4096];  // O=128,CK=768
__device__ __nv_bfloat16 g_whi3[1*6*4096],  g_wlo3[1*6*4096];   // O=64, CK=384
__device__ float g_part[2*BATCH*32*2];
__device__ float g_st1[2*BATCH*2];
__device__ float g_st2[2*BATCH*2];
__device__ float g_st3[2*BATCH*2];

// ---- helpers ----------------------------------------------------------------
__device__ __forceinline__ uint32_t smem_u32(const void* p) {
    uint32_t a;
    asm("{ .reg .u64 t; cvta.to.shared.u64 t, %1; cvt.u32.u64 %0, t; }"
        : "=r"(a) : "l"(p));
    return a;
}
#define CP16(dst, src) \
    asm volatile("cp.async.cg.shared.global [%0], [%1], 16;" :: "r"(dst), "l"(src))
#define CPCOMMIT() asm volatile("cp.async.commit_group;" ::: "memory")

__device__ __forceinline__ void ldsm4(uint32_t* r, uint32_t addr) {
    asm volatile("ldmatrix.sync.aligned.m8n8.x4.shared.b16 {%0,%1,%2,%3}, [%4];"
        : "=r"(r[0]), "=r"(r[1]), "=r"(r[2]), "=r"(r[3]) : "r"(addr));
}
__device__ __forceinline__ void mma_bf16(float* c, const uint32_t* a,
                                         uint32_t b0, uint32_t b1) {
    asm volatile(
        "mma.sync.aligned.m16n8k16.row.col.f32.bf16.bf16.f32 "
        "{%0,%1,%2,%3}, {%4,%5,%6,%7}, {%8,%9}, {%0,%1,%2,%3};"
        : "+f"(c[0]), "+f"(c[1]), "+f"(c[2]), "+f"(c[3])
        : "r"(a[0]), "r"(a[1]), "r"(a[2]), "r"(a[3]), "r"(b0), "r"(b1));
}

// ---------------------------------------------------------------------------
// Transpose raw input [b][C=64][N=1024] -> act0 [tower*128+b][N][64] (f32)
// ---------------------------------------------------------------------------
__global__ __launch_bounds__(256) void transpose_kernel(
    const float* __restrict__ d1, const float* __restrict__ d2,
    float* __restrict__ act0)
{
    __shared__ float tile[32][33];
    int tb = blockIdx.z;
    int tower = tb / BATCH, b = tb % BATCH;
    const float* src = (tower ? d2 : d1) + (size_t)b * 64 * NNODES;
    float* dst = act0 + (size_t)tb * NNODES * 64;
    int n0 = blockIdx.x * 32, c0 = blockIdx.y * 32;
    for (int i = threadIdx.y; i < 32; i += 8)
        tile[i][threadIdx.x] = src[(size_t)(c0 + i) * NNODES + n0 + threadIdx.x];
    __syncthreads();
    for (int i = threadIdx.y; i < 32; i += 8)
        dst[(size_t)(n0 + i) * 64 + c0 + threadIdx.x] = tile[threadIdx.x][i];
}

// ---------------------------------------------------------------------------
// Build bf16 hi/lo weight images, SW128-swizzled 64x64 tiles.
// tile = och*NT + kt; row = o%64, col = ck%64 with ck = k*C + c.
// ---------------------------------------------------------------------------
__global__ void make_wimg(const float* __restrict__ w,
                          __nv_bfloat16* __restrict__ hi,
                          __nv_bfloat16* __restrict__ lo,
                          int O, int C, int NT)
{
    int i = blockIdx.x * 256 + threadIdx.x;
    if (i >= O * 3 * C) return;
    int tile = i >> 12, e = i & 4095;
    int row = e >> 6, col = e & 63;
    int och = tile / NT, kt = tile % NT;
    int o = och * 64 + row;
    int ck = kt * 64 + col;
    int k = ck / C, c = ck - k * C;
    float x = w[(o * C + c) * 3 + k];
    __nv_bfloat16 h = __float2bfloat16(x);
    __nv_bfloat16 l = __float2bfloat16(x - __bfloat162float(h));
    int boff = row * 128 + col * 2;
    int sw = boff ^ ((boff >> 3) & 0x70);
    hi[((size_t)tile << 12) + (sw >> 1)] = h;
    lo[((size_t)tile << 12) + (sw >> 1)] = l;
}

// ---------------------------------------------------------------------------
// Zero node-0 rows of act1/2/3 (f32)
// ---------------------------------------------------------------------------
__global__ void zero_rows(float* a1, float* a2, float* a3)
{
    int tb = blockIdx.x;
    for (int i = threadIdx.x; i < 256; i += blockDim.x) a1[(size_t)tb * NNODES * 256 + i] = 0.f;
    for (int i = threadIdx.x; i < 128; i += blockDim.x) a2[(size_t)tb * NNODES * 128 + i] = 0.f;
    for (int i = threadIdx.x; i <  64; i += blockDim.x) a3[(size_t)tb * NNODES *  64 + i] = 0.f;
}

// ---------------------------------------------------------------------------
// Optionally apply LN+leakyReLU, then split f32 -> bf16 hi/lo arrays.
// grid = (NNODES*O/4/256, 2*BATCH)
// ---------------------------------------------------------------------------
__global__ __launch_bounds__(256) void transform_split(
    const float* __restrict__ act, const float* __restrict__ stats,
    __nv_bfloat16* __restrict__ hi, __nv_bfloat16* __restrict__ lo,
    int O, int ln)
{
    int tb = blockIdx.y;
    float mean = 0.f, inv = 1.f;
    if (ln) { mean = stats[tb * 2]; inv = stats[tb * 2 + 1]; }
    size_t base4 = (size_t)tb * NNODES * O / 4;
    const float4* a = reinterpret_cast<const float4*>(act) + base4;
    int i = blockIdx.x * 256 + threadIdx.x;
    float4 v = a[i];
    if (ln) {
        v.x = (v.x - mean) * inv; v.x = v.x > 0.f ? v.x : 0.01f * v.x;
        v.y = (v.y - mean) * inv; v.y = v.y > 0.f ? v.y : 0.01f * v.y;
        v.z = (v.z - mean) * inv; v.z = v.z > 0.f ? v.z : 0.01f * v.z;
        v.w = (v.w - mean) * inv; v.w = v.w > 0.f ? v.w : 0.01f * v.w;
    }
    uint32_t h01, h23;
    asm("cvt.rn.bf16x2.f32 %0, %1, %2;" : "=r"(h01) : "f"(v.y), "f"(v.x));
    asm("cvt.rn.bf16x2.f32 %0, %1, %2;" : "=r"(h23) : "f"(v.w), "f"(v.z));
    float hx = __uint_as_float(h01 << 16);
    float hy = __uint_as_float(h01 & 0xFFFF0000u);
    float hz = __uint_as_float(h23 << 16);
    float hw = __uint_as_float(h23 & 0xFFFF0000u);
    uint32_t l01, l23;
    asm("cvt.rn.bf16x2.f32 %0, %1, %2;" : "=r"(l01) : "f"(v.y - hy), "f"(v.x - hx));
    asm("cvt.rn.bf16x2.f32 %0, %1, %2;" : "=r"(l23) : "f"(v.w - hw), "f"(v.z - hz));
    u64 hv, lv;
    asm("mov.b64 %0, {%1, %2};" : "=l"(hv) : "r"(h01), "r"(h23));
    asm("mov.b64 %0, {%1, %2};" : "=l"(lv) : "r"(l01), "r"(l23));
    reinterpret_cast<u64*>(hi)[base4 + i] = hv;
    reinterpret_cast<u64*>(lo)[base4 + i] = lv;
}

// ---------------------------------------------------------------------------
// mma.sync gather-conv. 256 threads (8 warps), M=128 triples, N=64 (O chunk),
// K-tiles of 64, cp.async double-buffered, 3-term bf16 split, fused stats.
// ---------------------------------------------------------------------------
template<int C, int O>
__global__ __launch_bounds__(256, 2) void conv_mma(
    const __nv_bfloat16* __restrict__ aHiG, const __nv_bfloat16* __restrict__ aLoG,
    const int* __restrict__ idxA, const int* __restrict__ idxB,
    const __nv_bfloat16* __restrict__ whi, const __nv_bfloat16* __restrict__ wlo,
    const float* __restrict__ bias,
    float* __restrict__ actout, float* __restrict__ part)
{
    constexpr int TM = 128;
    constexpr int CK = 3 * C;
    constexpr int KT = 64;
    constexpr int NT = CK / KT;
    constexpr int OCH = O / 64;

    extern __shared__ char dsm_raw[];
    char* dsm = (char*)(((uintptr_t)dsm_raw + 1023) & ~(uintptr_t)1023);
    __shared__ int nodes[TM * 3];
    __shared__ float red[16];

    const int tid = threadIdx.x, lane = tid & 31, warp = tid >> 5;
    const int och = blockIdx.x % OCH;
    const int m0 = (blockIdx.x / OCH) * TM;
    const int tb = blockIdx.z * BATCH + blockIdx.y;
    const int* idx = (blockIdx.z ? idxB : idxA) + blockIdx.y * T3;

    for (int t = tid; t < TM * 3; t += 256) {
        int tt = m0 * 3 + t;
        nodes[t] = (tt < T3) ? idx[tt] : 0;
    }
    __syncthreads();

    const uint32_t sb = smem_u32(dsm);
    // layout: aHi[2]@0, aLo[2]@32768, bHi/bLo[2]@65536 (16KB per stage pair)
    const __nv_bfloat16* aG[2] = { aHiG + (size_t)tb * NNODES * C,
                                   aLoG + (size_t)tb * NNODES * C };

    auto issue = [&](int kt, int s) {
        const int k = (kt * KT) / C;
        const int cbase = kt * KT - k * C;
        const __nv_bfloat16* bsrc[2] = {
            whi + (((size_t)(och * NT + kt)) << 12),
            wlo + (((size_t)(och * NT + kt)) << 12) };
        const uint32_t bdst[2] = { sb + 65536u + (uint32_t)s * 16384u,
                                   sb + 65536u + (uint32_t)s * 16384u + 8192u };
#pragma unroll 2
        for (int e = tid; e < 1024; e += 256) {
            int ss = e >> 9, q = e & 511;
            CP16(bdst[ss] + (uint32_t)q * 16u, bsrc[ss] + q * 8);
        }
        const uint32_t adst[2] = { sb + (uint32_t)s * 16384u,
                                   sb + 32768u + (uint32_t)s * 16384u };
#pragma unroll 4
        for (int e = tid; e < 2048; e += 256) {
            int ss = e >> 10, e2 = e & 1023, r = e2 >> 3, q = e2 & 7;
            const __nv_bfloat16* src =
                aG[ss] + (size_t)nodes[r * 3 + k] * C + cbase + q * 8;
            uint32_t off = ((uint32_t)(r * 128 + q * 16)) ^ (((uint32_t)(r & 7)) << 4);
            CP16(adst[ss] + off, src);
        }
        CPCOMMIT();
    };

    float acc[8][4];
#pragma unroll
    for (int i = 0; i < 8; i++)
#pragma unroll
        for (int j = 0; j < 4; j++) acc[i][j] = 0.f;

    // ldmatrix lane constants
    const int arow = warp * 16 + (lane & 15);
    const uint32_t aswz = ((uint32_t)(arow & 7)) << 4;
    const uint32_t akh = ((lane >> 4) & 1) * 16;
    const int brow_in = lane & 7;
    const int bpsel = (lane >> 4) & 1;          // which ntile of the pair
    const uint32_t bkh = ((lane >> 3) & 1) * 16;
    const uint32_t bswz = ((uint32_t)brow_in) << 4;

    issue(0, 0);
    for (int kt = 0; kt < NT; kt++) {
        if (kt + 1 < NT) {
            issue(kt + 1, (kt + 1) & 1);
            asm volatile("cp.async.wait_group 1;" ::: "memory");
        } else {
            asm volatile("cp.async.wait_group 0;" ::: "memory");
        }
        __syncthreads();
        const int s = kt & 1;
        const uint32_t ahb = sb + (uint32_t)s * 16384u + (uint32_t)arow * 128u;
        const uint32_t alb = ahb + 32768u;
        const uint32_t bhb = sb + 65536u + (uint32_t)s * 16384u;
        const uint32_t blb = bhb + 8192u;
#pragma unroll
        for (int ks = 0; ks < 4; ks++) {
            const uint32_t akb = (uint32_t)(ks * 32) + akh;
            uint32_t Ah[4], Al[4];
            ldsm4(Ah, ahb + (akb ^ aswz));
            ldsm4(Al, alb + (akb ^ aswz));
            const uint32_t bkb = (uint32_t)(ks * 32) + bkh;
#pragma unroll
            for (int p = 0; p < 4; p++) {
                const uint32_t broff =
                    (uint32_t)((2 * p + bpsel) * 8 + brow_in) * 128u + (bkb ^ bswz);
                uint32_t Bh[4], Bl[4];
                ldsm4(Bh, bhb + broff);
                ldsm4(Bl, blb + broff);
                mma_bf16(acc[2 * p],     Ah, Bh[0], Bh[1]);
                mma_bf16(acc[2 * p],     Ah, Bl[0], Bl[1]);
                mma_bf16(acc[2 * p],     Al, Bh[0], Bh[1]);
                mma_bf16(acc[2 * p + 1], Ah, Bh[2], Bh[3]);
                mma_bf16(acc[2 * p + 1], Ah, Bl[2], Bl[3]);
                mma_bf16(acc[2 * p + 1], Al, Bh[2], Bh[3]);
            }
        }
        __syncthreads();
    }

    // Epilogue: D fragments -> gmem (float2) + fused stats
    float ls = 0.f, lss = 0.f;
    float* aout = actout + (size_t)tb * NNODES * O;
    const int r0 = m0 + warp * 16 + (lane >> 2);
    const int colb = och * 64 + 2 * (lane & 3);
#pragma unroll
    for (int nt = 0; nt < 8; nt++) {
        int col = colb + nt * 8;
        float2 bv = *reinterpret_cast<const float2*>(bias + col);
        if (r0 < NTRI) {
            float2 v;
            v.x = acc[nt][0] + bv.x; v.y = acc[nt][1] + bv.y;
            *reinterpret_cast<float2*>(aout + (size_t)(r0 + 1) * O + col) = v;
            ls += v.x + v.y;
            lss = fmaf(v.x, v.x, lss); lss = fmaf(v.y, v.y, lss);
        }
        if (r0 + 8 < NTRI) {
            float2 v;
            v.x = acc[nt][2] + bv.x; v.y = acc[nt][3] + bv.y;
            *reinterpret_cast<float2*>(aout + (size_t)(r0 + 9) * O + col) = v;
            ls += v.x + v.y;
            lss = fmaf(v.x, v.x, lss); lss = fmaf(v.y, v.y, lss);
        }
    }
#pragma unroll
    for (int off = 16; off > 0; off >>= 1) {
        ls  += __shfl_xor_sync(0xffffffffu, ls,  off);
        lss += __shfl_xor_sync(0xffffffffu, lss, off);
    }
    if (lane == 0) { red[warp] = ls; red[8 + warp] = lss; }
    __syncthreads();
    if (tid == 0) {
        float s = 0.f, ss = 0.f;
#pragma unroll
        for (int wv = 0; wv < 8; wv++) { s += red[wv]; ss += red[8 + wv]; }
        float* pp = part + ((size_t)tb * 32 + blockIdx.x) * 2;
        pp[0] = s; pp[1] = ss;
    }
}

// ---------------------------------------------------------------------------
// Finalize stats: reduce nparts partials per (tower,b)
// ---------------------------------------------------------------------------
__global__ __launch_bounds__(256) void finalize_stats(
    const float* __restrict__ part, float* __restrict__ stats, int O, int nparts)
{
    int tb = threadIdx.x;
    double s = 0.0, ss = 0.0;
    for (int i = 0; i < nparts; i++) {
        s += (double)part[((size_t)tb * 32 + i) * 2];
        ss += (double)part[((size_t)tb * 32 + i) * 2 + 1];
    }
    double n = 1024.0 * O;
    double mean = s / n;
    double var = (ss - s * s / n) / (n - 1.0);
    if (var < 0.0) var = 0.0;
    stats[tb * 2] = (float)mean;
    stats[tb * 2 + 1] = (float)(1.0 / (sqrt(var) + 1e-5));
}

// ---------------------------------------------------------------------------
// Final head: LN(act3) -> max-pool -> FC1(lrelu) -> FC2 -> sigmoid(diff)
// ---------------------------------------------------------------------------
__global__ __launch_bounds__(256) void final_kernel(
    const float* __restrict__ act3, const float* __restrict__ stats3,
    const float* __restrict__ wfc1, const float* __restrict__ bfc1,
    const float* __restrict__ wfc2, const float* __restrict__ bfc2,
    float* __restrict__ out)
{
    int b = blockIdx.x;
    int tid = threadIdx.x;
    __shared__ float mx[4][64];
    __shared__ float h[32];
    __shared__ float yy[2];

    for (int tower = 0; tower < 2; tower++) {
        int tb = tower * BATCH + b;
        float mean = stats3[tb * 2], inv = stats3[tb * 2 + 1];
        const float* a = act3 + (size_t)tb * NNODES * 64;
        int c = tid & 63, grp = tid >> 6;
        float m = -1e30f;
        for (int n = grp; n < NNODES; n += 4) {
            float v = (a[(size_t)n * 64 + c] - mean) * inv;
            m = fmaxf(m, v);
        }
        mx[grp][c] = m;
        __syncthreads();
        if (tid < 64) {
            mx[0][tid] = fmaxf(fmaxf(mx[0][tid], mx[1][tid]),
                               fmaxf(mx[2][tid], mx[3][tid]));
        }
        __syncthreads();
        if (tid < 32) {
            float sAcc = bfc1[tid];
            for (int c2 = 0; c2 < 64; c2++) sAcc = fmaf(mx[0][c2], wfc1[tid * 64 + c2], sAcc);
            h[tid] = sAcc > 0.f ? sAcc : 0.01f * sAcc;
        }
        __syncthreads();
        if (tid == 0) {
            float sAcc = bfc2[0];
            for (int i = 0; i < 32; i++) sAcc = fmaf(h[i], wfc2[i], sAcc);
            yy[tower] = sAcc;
        }
        __syncthreads();
    }
    if (tid == 0) {
        float d = yy[0] - yy[1];
        out[b] = 1.f / (1.f + expf(-d));
    }
}

// ---------------------------------------------------------------------------
extern "C" void kernel_launch(void* const* d_in, const int* in_sizes, int n_in,
                              void* d_out, int out_size)
{
    const float* data1 = (const float*)d_in[0];
    const int*   idx1  = (const int*)d_in[1];
    const float* data2 = (const float*)d_in[2];
    const int*   idx2  = (const int*)d_in[3];
    const float* w1 = (const float*)d_in[4];
    const float* b1 = (const float*)d_in[5];
    const float* w2 = (const float*)d_in[6];
    const float* b2 = (const float*)d_in[7];
    const float* w3 = (const float*)d_in[8];
    const float* b3 = (const float*)d_in[9];
    const float* wfc1 = (const float*)d_in[10];
    const float* bfc1 = (const float*)d_in[11];
    const float* wfc2 = (const float*)d_in[12];
    const float* bfc2 = (const float*)d_in[13];
    float* out = (float*)d_out;

    float *act0, *act1, *act2, *act3, *part, *st1, *st2, *st3;
    __nv_bfloat16 *a0h, *a0l, *a1h, *a1l, *a2h, *a2l;
    __nv_bfloat16 *whi1, *wlo1, *whi2, *wlo2, *whi3, *wlo3;
    cudaGetSymbolAddress((void**)&act0, g_act0);
    cudaGetSymbolAddress((void**)&act1, g_act1);
    cudaGetSymbolAddress((void**)&act2, g_act2);
    cudaGetSymbolAddress((void**)&act3, g_act3);
    cudaGetSymbolAddress((void**)&a0h, g_a0h);
    cudaGetSymbolAddress((void**)&a0l, g_a0l);
    cudaGetSymbolAddress((void**)&a1h, g_a1h);
    cudaGetSymbolAddress((void**)&a1l, g_a1l);
    cudaGetSymbolAddress((void**)&a2h, g_a2h);
    cudaGetSymbolAddress((void**)&a2l, g_a2l);
    cudaGetSymbolAddress((void**)&whi1, g_whi1);
    cudaGetSymbolAddress((void**)&wlo1, g_wlo1);
    cudaGetSymbolAddress((void**)&whi2, g_whi2);
    cudaGetSymbolAddress((void**)&wlo2, g_wlo2);
    cudaGetSymbolAddress((void**)&whi3, g_whi3);
    cudaGetSymbolAddress((void**)&wlo3, g_wlo3);
    cudaGetSymbolAddress((void**)&part, g_part);
    cudaGetSymbolAddress((void**)&st1, g_st1);
    cudaGetSymbolAddress((void**)&st2, g_st2);
    cudaGetSymbolAddress((void**)&st3, g_st3);

    // dynamic smem: 1024 align slack + A hi/lo 2x16KB each + B hi/lo 2x8KB each
    const int smem = 1024 + 98304;  // 99328
    cudaFuncSetAttribute(conv_mma<64, 256>,
                         cudaFuncAttributeMaxDynamicSharedMemorySize, smem);
    cudaFuncSetAttribute(conv_mma<256, 128>,
                         cudaFuncAttributeMaxDynamicSharedMemorySize, smem);
    cudaFuncSetAttribute(conv_mma<128, 64>,
                         cudaFuncAttributeMaxDynamicSharedMemorySize, smem);

    transpose_kernel<<<dim3(32, 2, 256), dim3(32, 8)>>>(data1, data2, act0);
    make_wimg<<<(256 * 192 + 255) / 256, 256>>>(w1, whi1, wlo1, 256, 64, 3);
    zero_rows<<<256, 256>>>(act1, act2, act3);
    // act0 -> bf16 hi/lo (no LN)
    transform_split<<<dim3(NNODES * 64 / 4 / 256, 256), 256>>>(
        act0, st1, a0h, a0l, 64, 0);

    conv_mma<64, 256><<<dim3(32, BATCH, 2), 256, smem>>>(
        a0h, a0l, idx1, idx2, whi1, wlo1, b1, act1, part);
    finalize_stats<<<1, 256>>>(part, st1, 256, 32);
    transform_split<<<dim3(NNODES * 256 / 4 / 256, 256), 256>>>(
        act1, st1, a1h, a1l, 256, 1);
    make_wimg<<<(128 * 768 + 255) / 256, 256>>>(w2, whi2, wlo2, 128, 256, 12);

    conv_mma<256, 128><<<dim3(16, BATCH, 2), 256, smem>>>(
        a1h, a1l, idx1, idx2, whi2, wlo2, b2, act2, part);
    finalize_stats<<<1, 256>>>(part, st2, 128, 16);
    transform_split<<<dim3(NNODES * 128 / 4 / 256, 256), 256>>>(
        act2, st2, a2h, a2l, 128, 1);
    make_wimg<<<(64 * 384 + 255) / 256, 256>>>(w3, whi3, wlo3, 64, 128, 6);

    conv_mma<128, 64><<<dim3(8, BATCH, 2), 256, smem>>>(
        a2h, a2l, idx1, idx2, whi3, wlo3, b3, act3, part);
    finalize_stats<<<1, 256>>>(part, st3, 64, 8);

    final_kernel<<<BATCH, 256>>>(act3, st3, wfc1, bfc1, wfc2, bfc2, out);
}

// round 10
// speedup vs baseline: 3.8200x; 1.0134x over previous
#include <cuda_runtime.h>
#include <cuda_bf16.h>
#include <math.h>
#include <stdint.h>

#define BATCH 128
#define NNODES 1024
#define NTRI 1023
#define T3 3069

typedef unsigned long long u64;

// f32 activations (conv outputs; node-major [tower*128+b][node][C])
__device__ float g_act0[(size_t)2*BATCH*NNODES*64];
__device__ float g_act1[(size_t)2*BATCH*NNODES*256];
__device__ float g_act2[(size_t)2*BATCH*NNODES*128];
__device__ float g_act3[(size_t)2*BATCH*NNODES*64];
// bf16 hi/lo split activations (conv inputs)
__device__ __nv_bfloat16 g_a0h[(size_t)2*BATCH*NNODES*64];
__device__ __nv_bfloat16 g_a0l[(size_t)2*BATCH*NNODES*64];
__device__ __nv_bfloat16 g_a1h[(size_t)2*BATCH*NNODES*256];
__device__ __nv_bfloat16 g_a1l[(size_t)2*BATCH*NNODES*256];
__device__ __nv_bfloat16 g_a2h[(size_t)2*BATCH*NNODES*128];
__device__ __nv_bfloat16 g_a2l[(size_t)2*BATCH*NNODES*128];
// Weight images: bf16 hi/lo, per (och,kt) 64x64 SW128-swizzled tiles (4096 elems)
__device__ __nv_bfloat16 g_whi1[4*3*4096],  g_wlo1[4*3*4096];   // O=256,CK=192
__device__ __nv_bfloat16 g_whi2[2*12*4096], g_wlo2[2*12*4096];  // O=128,CK=768
__device__ __nv_bfloat16 g_whi3[1*6*4096],  g_wlo3[1*6*4096];   // O=64, CK=384
__device__ float g_part[2*BATCH*32*2];
__device__ float g_st1[2*BATCH*2];
__device__ float g_st2[2*BATCH*2];
__device__ float g_st3[2*BATCH*2];

// ---- helpers ----------------------------------------------------------------
__device__ __forceinline__ uint32_t smem_u32(const void* p) {
    uint32_t a;
    asm("{ .reg .u64 t; cvta.to.shared.u64 t, %1; cvt.u32.u64 %0, t; }"
        : "=r"(a) : "l"(p));
    return a;
}
#define CP16(dst, src) \
    asm volatile("cp.async.cg.shared.global [%0], [%1], 16;" :: "r"(dst), "l"(src))
#define CPCOMMIT() asm volatile("cp.async.commit_group;" ::: "memory")

__device__ __forceinline__ void ldsm4(uint32_t* r, uint32_t addr) {
    asm volatile("ldmatrix.sync.aligned.m8n8.x4.shared.b16 {%0,%1,%2,%3}, [%4];"
        : "=r"(r[0]), "=r"(r[1]), "=r"(r[2]), "=r"(r[3]) : "r"(addr));
}
__device__ __forceinline__ void mma_bf16(float* c, const uint32_t* a,
                                         uint32_t b0, uint32_t b1) {
    asm volatile(
        "mma.sync.aligned.m16n8k16.row.col.f32.bf16.bf16.f32 "
        "{%0,%1,%2,%3}, {%4,%5,%6,%7}, {%8,%9}, {%0,%1,%2,%3};"
        : "+f"(c[0]), "+f"(c[1]), "+f"(c[2]), "+f"(c[3])
        : "r"(a[0]), "r"(a[1]), "r"(a[2]), "r"(a[3]), "r"(b0), "r"(b1));
}

// ---------------------------------------------------------------------------
// Transpose raw input [b][C=64][N=1024] -> act0 [tower*128+b][N][64] (f32)
// ---------------------------------------------------------------------------
__global__ __launch_bounds__(256) void transpose_kernel(
    const float* __restrict__ d1, const float* __restrict__ d2,
    float* __restrict__ act0)
{
    __shared__ float tile[32][33];
    int tb = blockIdx.z;
    int tower = tb / BATCH, b = tb % BATCH;
    const float* src = (tower ? d2 : d1) + (size_t)b * 64 * NNODES;
    float* dst = act0 + (size_t)tb * NNODES * 64;
    int n0 = blockIdx.x * 32, c0 = blockIdx.y * 32;
    for (int i = threadIdx.y; i < 32; i += 8)
        tile[i][threadIdx.x] = src[(size_t)(c0 + i) * NNODES + n0 + threadIdx.x];
    __syncthreads();
    for (int i = threadIdx.y; i < 32; i += 8)
        dst[(size_t)(n0 + i) * 64 + c0 + threadIdx.x] = tile[threadIdx.x][i];
}

// ---------------------------------------------------------------------------
// Build bf16 hi/lo weight images, SW128-swizzled 64x64 tiles.
// ---------------------------------------------------------------------------
__global__ void make_wimg(const float* __restrict__ w,
                          __nv_bfloat16* __restrict__ hi,
                          __nv_bfloat16* __restrict__ lo,
                          int O, int C, int NT)
{
    int i = blockIdx.x * 256 + threadIdx.x;
    if (i >= O * 3 * C) return;
    int tile = i >> 12, e = i & 4095;
    int row = e >> 6, col = e & 63;
    int och = tile / NT, kt = tile % NT;
    int o = och * 64 + row;
    int ck = kt * 64 + col;
    int k = ck / C, c = ck - k * C;
    float x = w[(o * C + c) * 3 + k];
    __nv_bfloat16 h = __float2bfloat16(x);
    __nv_bfloat16 l = __float2bfloat16(x - __bfloat162float(h));
    int boff = row * 128 + col * 2;
    int sw = boff ^ ((boff >> 3) & 0x70);
    hi[((size_t)tile << 12) + (sw >> 1)] = h;
    lo[((size_t)tile << 12) + (sw >> 1)] = l;
}

// ---------------------------------------------------------------------------
// Zero node-0 rows of act1/2/3 (f32)
// ---------------------------------------------------------------------------
__global__ void zero_rows(float* a1, float* a2, float* a3)
{
    int tb = blockIdx.x;
    for (int i = threadIdx.x; i < 256; i += blockDim.x) a1[(size_t)tb * NNODES * 256 + i] = 0.f;
    for (int i = threadIdx.x; i < 128; i += blockDim.x) a2[(size_t)tb * NNODES * 128 + i] = 0.f;
    for (int i = threadIdx.x; i <  64; i += blockDim.x) a3[(size_t)tb * NNODES *  64 + i] = 0.f;
}

// ---------------------------------------------------------------------------
// Optionally apply LN+leakyReLU, then split f32 -> bf16 hi/lo arrays.
// ---------------------------------------------------------------------------
__global__ __launch_bounds__(256) void transform_split(
    const float* __restrict__ act, const float* __restrict__ stats,
    __nv_bfloat16* __restrict__ hi, __nv_bfloat16* __restrict__ lo,
    int O, int ln)
{
    int tb = blockIdx.y;
    float mean = 0.f, inv = 1.f;
    if (ln) { mean = stats[tb * 2]; inv = stats[tb * 2 + 1]; }
    size_t base4 = (size_t)tb * NNODES * O / 4;
    const float4* a = reinterpret_cast<const float4*>(act) + base4;
    int i = blockIdx.x * 256 + threadIdx.x;
    float4 v = a[i];
    if (ln) {
        v.x = (v.x - mean) * inv; v.x = v.x > 0.f ? v.x : 0.01f * v.x;
        v.y = (v.y - mean) * inv; v.y = v.y > 0.f ? v.y : 0.01f * v.y;
        v.z = (v.z - mean) * inv; v.z = v.z > 0.f ? v.z : 0.01f * v.z;
        v.w = (v.w - mean) * inv; v.w = v.w > 0.f ? v.w : 0.01f * v.w;
    }
    uint32_t h01, h23;
    asm("cvt.rn.bf16x2.f32 %0, %1, %2;" : "=r"(h01) : "f"(v.y), "f"(v.x));
    asm("cvt.rn.bf16x2.f32 %0, %1, %2;" : "=r"(h23) : "f"(v.w), "f"(v.z));
    float hx = __uint_as_float(h01 << 16);
    float hy = __uint_as_float(h01 & 0xFFFF0000u);
    float hz = __uint_as_float(h23 << 16);
    float hw = __uint_as_float(h23 & 0xFFFF0000u);
    uint32_t l01, l23;
    asm("cvt.rn.bf16x2.f32 %0, %1, %2;" : "=r"(l01) : "f"(v.y - hy), "f"(v.x - hx));
    asm("cvt.rn.bf16x2.f32 %0, %1, %2;" : "=r"(l23) : "f"(v.w - hw), "f"(v.z - hz));
    u64 hv, lv;
    asm("mov.b64 %0, {%1, %2};" : "=l"(hv) : "r"(h01), "r"(h23));
    asm("mov.b64 %0, {%1, %2};" : "=l"(lv) : "r"(l01), "r"(l23));
    reinterpret_cast<u64*>(hi)[base4 + i] = hv;
    reinterpret_cast<u64*>(lo)[base4 + i] = lv;
}

// ---------------------------------------------------------------------------
// mma.sync gather-conv. 256 threads (8 warps, 4 m-groups x 2 n-groups of
// 32x32 warp tiles). M=128 triples, N=64 (O chunk), K-tiles of 64,
// cp.async double-buffered, 3-term bf16 split, fused stats.
// ---------------------------------------------------------------------------
template<int C, int O>
__global__ __launch_bounds__(256, 2) void conv_mma(
    const __nv_bfloat16* __restrict__ aHiG, const __nv_bfloat16* __restrict__ aLoG,
    const int* __restrict__ idxA, const int* __restrict__ idxB,
    const __nv_bfloat16* __restrict__ whi, const __nv_bfloat16* __restrict__ wlo,
    const float* __restrict__ bias,
    float* __restrict__ actout, float* __restrict__ part)
{
    constexpr int TM = 128;
    constexpr int CK = 3 * C;
    constexpr int KT = 64;
    constexpr int NT = CK / KT;
    constexpr int OCH = O / 64;

    extern __shared__ char dsm_raw[];
    char* dsm = (char*)(((uintptr_t)dsm_raw + 1023) & ~(uintptr_t)1023);
    __shared__ int nodes[TM * 3];
    __shared__ float red[16];

    const int tid = threadIdx.x, lane = tid & 31, warp = tid >> 5;
    const int mg = warp >> 1, ng = warp & 1;
    const int och = blockIdx.x % OCH;
    const int m0 = (blockIdx.x / OCH) * TM;
    const int tb = blockIdx.z * BATCH + blockIdx.y;
    const int* idx = (blockIdx.z ? idxB : idxA) + blockIdx.y * T3;

    for (int t = tid; t < TM * 3; t += 256) {
        int tt = m0 * 3 + t;
        nodes[t] = (tt < T3) ? idx[tt] : 0;
    }
    __syncthreads();

    const uint32_t sb = smem_u32(dsm);
    // layout: aHi[2]@0, aLo[2]@32768, bHi/bLo[2]@65536 (16KB per stage pair)
    const __nv_bfloat16* aG[2] = { aHiG + (size_t)tb * NNODES * C,
                                   aLoG + (size_t)tb * NNODES * C };

    auto issue = [&](int kt, int s) {
        const int k = (kt * KT) / C;
        const int cbase = kt * KT - k * C;
        const __nv_bfloat16* bsrc[2] = {
            whi + (((size_t)(och * NT + kt)) << 12),
            wlo + (((size_t)(och * NT + kt)) << 12) };
        const uint32_t bdst[2] = { sb + 65536u + (uint32_t)s * 16384u,
                                   sb + 65536u + (uint32_t)s * 16384u + 8192u };
#pragma unroll 2
        for (int e = tid; e < 1024; e += 256) {
            int ss = e >> 9, q = e & 511;
            CP16(bdst[ss] + (uint32_t)q * 16u, bsrc[ss] + q * 8);
        }
        const uint32_t adst[2] = { sb + (uint32_t)s * 16384u,
                                   sb + 32768u + (uint32_t)s * 16384u };
#pragma unroll 4
        for (int e = tid; e < 2048; e += 256) {
            int ss = e >> 10, e2 = e & 1023, r = e2 >> 3, q = e2 & 7;
            const __nv_bfloat16* src =
                aG[ss] + (size_t)nodes[r * 3 + k] * C + cbase + q * 8;
            uint32_t off = ((uint32_t)(r * 128 + q * 16)) ^ (((uint32_t)(r & 7)) << 4);
            CP16(adst[ss] + off, src);
        }
        CPCOMMIT();
    };

    float acc[2][4][4];
#pragma unroll
    for (int mi = 0; mi < 2; mi++)
#pragma unroll
        for (int i = 0; i < 4; i++)
#pragma unroll
            for (int j = 0; j < 4; j++) acc[mi][i][j] = 0.f;

    // ldmatrix lane constants
    const int arow0 = mg * 32 + (lane & 15);       // + mi*16
    const uint32_t aswz = ((uint32_t)(arow0 & 7)) << 4;   // invariant under +16
    const uint32_t akh = ((lane >> 4) & 1) * 16;
    const int brow_in = lane & 7;
    const int bps = (lane >> 4) & 1;
    const uint32_t bkh = ((lane >> 3) & 1) * 16;
    const uint32_t bswz = ((uint32_t)brow_in) << 4;

    issue(0, 0);
    for (int kt = 0; kt < NT; kt++) {
        if (kt + 1 < NT) {
            issue(kt + 1, (kt + 1) & 1);
            asm volatile("cp.async.wait_group 1;" ::: "memory");
        } else {
            asm volatile("cp.async.wait_group 0;" ::: "memory");
        }
        __syncthreads();
        const int s = kt & 1;
        const uint32_t ahb = sb + (uint32_t)s * 16384u;
        const uint32_t bhb = sb + 65536u + (uint32_t)s * 16384u;
#pragma unroll
        for (int ks = 0; ks < 4; ks++) {
            const uint32_t akb = (uint32_t)(ks * 32) + akh;
            uint32_t Ah[2][4], Al[2][4];
#pragma unroll
            for (int mi = 0; mi < 2; mi++) {
                uint32_t aoff = (uint32_t)(arow0 + mi * 16) * 128u + (akb ^ aswz);
                ldsm4(Ah[mi], ahb + aoff);
                ldsm4(Al[mi], ahb + 32768u + aoff);
            }
            const uint32_t bkb = (uint32_t)(ks * 32) + bkh;
            uint32_t Bh[2][4], Bl[2][4];
#pragma unroll
            for (int p2 = 0; p2 < 2; p2++) {
                uint32_t brow = (uint32_t)(ng * 32 + p2 * 16 + bps * 8 + brow_in);
                uint32_t boff = brow * 128u + (bkb ^ bswz);
                ldsm4(Bh[p2], bhb + boff);
                ldsm4(Bl[p2], bhb + 8192u + boff);
            }
#pragma unroll
            for (int mi = 0; mi < 2; mi++) {
#pragma unroll
                for (int p2 = 0; p2 < 2; p2++) {
                    mma_bf16(acc[mi][p2 * 2],     Ah[mi], Bh[p2][0], Bh[p2][1]);
                    mma_bf16(acc[mi][p2 * 2],     Ah[mi], Bl[p2][0], Bl[p2][1]);
                    mma_bf16(acc[mi][p2 * 2],     Al[mi], Bh[p2][0], Bh[p2][1]);
                    mma_bf16(acc[mi][p2 * 2 + 1], Ah[mi], Bh[p2][2], Bh[p2][3]);
                    mma_bf16(acc[mi][p2 * 2 + 1], Ah[mi], Bl[p2][2], Bl[p2][3]);
                    mma_bf16(acc[mi][p2 * 2 + 1], Al[mi], Bh[p2][2], Bh[p2][3]);
                }
            }
        }
        __syncthreads();
    }

    // Epilogue: D fragments -> gmem (float2) + fused stats
    float ls = 0.f, lss = 0.f;
    float* aout = actout + (size_t)tb * NNODES * O;
#pragma unroll
    for (int mi = 0; mi < 2; mi++) {
        const int r0 = m0 + mg * 32 + mi * 16 + (lane >> 2);
#pragma unroll
        for (int nt = 0; nt < 4; nt++) {
            int col = och * 64 + ng * 32 + nt * 8 + 2 * (lane & 3);
            float2 bv = *reinterpret_cast<const float2*>(bias + col);
            if (r0 < NTRI) {
                float2 v;
                v.x = acc[mi][nt][0] + bv.x; v.y = acc[mi][nt][1] + bv.y;
                *reinterpret_cast<float2*>(aout + (size_t)(r0 + 1) * O + col) = v;
                ls += v.x + v.y;
                lss = fmaf(v.x, v.x, lss); lss = fmaf(v.y, v.y, lss);
            }
            if (r0 + 8 < NTRI) {
                float2 v;
                v.x = acc[mi][nt][2] + bv.x; v.y = acc[mi][nt][3] + bv.y;
                *reinterpret_cast<float2*>(aout + (size_t)(r0 + 9) * O + col) = v;
                ls += v.x + v.y;
                lss = fmaf(v.x, v.x, lss); lss = fmaf(v.y, v.y, lss);
            }
        }
    }
#pragma unroll
    for (int off = 16; off > 0; off >>= 1) {
        ls  += __shfl_xor_sync(0xffffffffu, ls,  off);
        lss += __shfl_xor_sync(0xffffffffu, lss, off);
    }
    if (lane == 0) { red[warp] = ls; red[8 + warp] = lss; }
    __syncthreads();
    if (tid == 0) {
        float s = 0.f, ss = 0.f;
#pragma unroll
        for (int wv = 0; wv < 8; wv++) { s += red[wv]; ss += red[8 + wv]; }
        float* pp = part + ((size_t)tb * 32 + blockIdx.x) * 2;
        pp[0] = s; pp[1] = ss;
    }
}

// ---------------------------------------------------------------------------
// Finalize stats: reduce nparts partials per (tower,b)
// ---------------------------------------------------------------------------
__global__ __launch_bounds__(256) void finalize_stats(
    const float* __restrict__ part, float* __restrict__ stats, int O, int nparts)
{
    int tb = threadIdx.x;
    double s = 0.0, ss = 0.0;
    for (int i = 0; i < nparts; i++) {
        s += (double)part[((size_t)tb * 32 + i) * 2];
        ss += (double)part[((size_t)tb * 32 + i) * 2 + 1];
    }
    double n = 1024.0 * O;
    double mean = s / n;
    double var = (ss - s * s / n) / (n - 1.0);
    if (var < 0.0) var = 0.0;
    stats[tb * 2] = (float)mean;
    stats[tb * 2 + 1] = (float)(1.0 / (sqrt(var) + 1e-5));
}

// ---------------------------------------------------------------------------
// Final head: LN(act3) -> max-pool -> FC1(lrelu) -> FC2 -> sigmoid(diff)
// ---------------------------------------------------------------------------
__global__ __launch_bounds__(256) void final_kernel(
    const float* __restrict__ act3, const float* __restrict__ stats3,
    const float* __restrict__ wfc1, const float* __restrict__ bfc1,
    const float* __restrict__ wfc2, const float* __restrict__ bfc2,
    float* __restrict__ out)
{
    int b = blockIdx.x;
    int tid = threadIdx.x;
    __shared__ float mx[4][64];
    __shared__ float h[32];
    __shared__ float yy[2];

    for (int tower = 0; tower < 2; tower++) {
        int tb = tower * BATCH + b;
        float mean = stats3[tb * 2], inv = stats3[tb * 2 + 1];
        const float* a = act3 + (size_t)tb * NNODES * 64;
        int c = tid & 63, grp = tid >> 6;
        float m = -1e30f;
        for (int n = grp; n < NNODES; n += 4) {
            float v = (a[(size_t)n * 64 + c] - mean) * inv;
            m = fmaxf(m, v);
        }
        mx[grp][c] = m;
        __syncthreads();
        if (tid < 64) {
            mx[0][tid] = fmaxf(fmaxf(mx[0][tid], mx[1][tid]),
                               fmaxf(mx[2][tid], mx[3][tid]));
        }
        __syncthreads();
        if (tid < 32) {
            float sAcc = bfc1[tid];
            for (int c2 = 0; c2 < 64; c2++) sAcc = fmaf(mx[0][c2], wfc1[tid * 64 + c2], sAcc);
            h[tid] = sAcc > 0.f ? sAcc : 0.01f * sAcc;
        }
        __syncthreads();
        if (tid == 0) {
            float sAcc = bfc2[0];
            for (int i = 0; i < 32; i++) sAcc = fmaf(h[i], wfc2[i], sAcc);
            yy[tower] = sAcc;
        }
        __syncthreads();
    }
    if (tid == 0) {
        float d = yy[0] - yy[1];
        out[b] = 1.f / (1.f + expf(-d));
    }
}

// ---------------------------------------------------------------------------
extern "C" void kernel_launch(void* const* d_in, const int* in_sizes, int n_in,
                              void* d_out, int out_size)
{
    const float* data1 = (const float*)d_in[0];
    const int*   idx1  = (const int*)d_in[1];
    const float* data2 = (const float*)d_in[2];
    const int*   idx2  = (const int*)d_in[3];
    const float* w1 = (const float*)d_in[4];
    const float* b1 = (const float*)d_in[5];
    const float* w2 = (const float*)d_in[6];
    const float* b2 = (const float*)d_in[7];
    const float* w3 = (const float*)d_in[8];
    const float* b3 = (const float*)d_in[9];
    const float* wfc1 = (const float*)d_in[10];
    const float* bfc1 = (const float*)d_in[11];
    const float* wfc2 = (const float*)d_in[12];
    const float* bfc2 = (const float*)d_in[13];
    float* out = (float*)d_out;

    float *act0, *act1, *act2, *act3, *part, *st1, *st2, *st3;
    __nv_bfloat16 *a0h, *a0l, *a1h, *a1l, *a2h, *a2l;
    __nv_bfloat16 *whi1, *wlo1, *whi2, *wlo2, *whi3, *wlo3;
    cudaGetSymbolAddress((void**)&act0, g_act0);
    cudaGetSymbolAddress((void**)&act1, g_act1);
    cudaGetSymbolAddress((void**)&act2, g_act2);
    cudaGetSymbolAddress((void**)&act3, g_act3);
    cudaGetSymbolAddress((void**)&a0h, g_a0h);
    cudaGetSymbolAddress((void**)&a0l, g_a0l);
    cudaGetSymbolAddress((void**)&a1h, g_a1h);
    cudaGetSymbolAddress((void**)&a1l, g_a1l);
    cudaGetSymbolAddress((void**)&a2h, g_a2h);
    cudaGetSymbolAddress((void**)&a2l, g_a2l);
    cudaGetSymbolAddress((void**)&whi1, g_whi1);
    cudaGetSymbolAddress((void**)&wlo1, g_wlo1);
    cudaGetSymbolAddress((void**)&whi2, g_whi2);
    cudaGetSymbolAddress((void**)&wlo2, g_wlo2);
    cudaGetSymbolAddress((void**)&whi3, g_whi3);
    cudaGetSymbolAddress((void**)&wlo3, g_wlo3);
    cudaGetSymbolAddress((void**)&part, g_part);
    cudaGetSymbolAddress((void**)&st1, g_st1);
    cudaGetSymbolAddress((void**)&st2, g_st2);
    cudaGetSymbolAddress((void**)&st3, g_st3);

    const int smem = 1024 + 98304;  // 99328
    cudaFuncSetAttribute(conv_mma<64, 256>,
                         cudaFuncAttributeMaxDynamicSharedMemorySize, smem);
    cudaFuncSetAttribute(conv_mma<256, 128>,
                         cudaFuncAttributeMaxDynamicSharedMemorySize, smem);
    cudaFuncSetAttribute(conv_mma<128, 64>,
                         cudaFuncAttributeMaxDynamicSharedMemorySize, smem);

    // Launch order: conv1 is the 4th launch (ncu capture slot).
    transpose_kernel<<<dim3(32, 2, 256), dim3(32, 8)>>>(data1, data2, act0);
    make_wimg<<<(256 * 192 + 255) / 256, 256>>>(w1, whi1, wlo1, 256, 64, 3);
    transform_split<<<dim3(NNODES * 64 / 4 / 256, 256), 256>>>(
        act0, st1, a0h, a0l, 64, 0);

    conv_mma<64, 256><<<dim3(32, BATCH, 2), 256, smem>>>(
        a0h, a0l, idx1, idx2, whi1, wlo1, b1, act1, part);
    zero_rows<<<256, 256>>>(act1, act2, act3);
    finalize_stats<<<1, 256>>>(part, st1, 256, 32);
    transform_split<<<dim3(NNODES * 256 / 4 / 256, 256), 256>>>(
        act1, st1, a1h, a1l, 256, 1);
    make_wimg<<<(128 * 768 + 255) / 256, 256>>>(w2, whi2, wlo2, 128, 256, 12);

    conv_mma<256, 128><<<dim3(16, BATCH, 2), 256, smem>>>(
        a1h, a1l, idx1, idx2, whi2, wlo2, b2, act2, part);
    finalize_stats<<<1, 256>>>(part, st2, 128, 16);
    transform_split<<<dim3(NNODES * 128 / 4 / 256, 256), 256>>>(
        act2, st2, a2h, a2l, 128, 1);
    make_wimg<<<(64 * 384 + 255) / 256, 256>>>(w3, whi3, wlo3, 64, 128, 6);

    conv_mma<128, 64><<<dim3(8, BATCH, 2), 256, smem>>>(
        a2h, a2l, idx1, idx2, whi3, wlo3, b3, act3, part);
    finalize_stats<<<1, 256>>>(part, st3, 64, 8);

    final_kernel<<<BATCH, 256>>>(act3, st3, wfc1, bfc1, wfc2, bfc2, out);
}

// round 11
// speedup vs baseline: 4.1435x; 1.0847x over previous
#include <cuda_runtime.h>
#include <cuda_bf16.h>
#include <math.h>
#include <stdint.h>

#define BATCH 128
#define NNODES 1024
#define NTRI 1023
#define T3 3069

typedef unsigned long long u64;

// f32 activations (conv outputs; node-major [tower*128+b][node][C])
__device__ float g_act0[(size_t)2*BATCH*NNODES*64];
__device__ float g_act1[(size_t)2*BATCH*NNODES*256];
__device__ float g_act2[(size_t)2*BATCH*NNODES*128];
__device__ float g_act3[(size_t)2*BATCH*NNODES*64];
// bf16 hi/lo split activations (conv inputs)
__device__ __nv_bfloat16 g_a0h[(size_t)2*BATCH*NNODES*64];
__device__ __nv_bfloat16 g_a0l[(size_t)2*BATCH*NNODES*64];
__device__ __nv_bfloat16 g_a1h[(size_t)2*BATCH*NNODES*256];
__device__ __nv_bfloat16 g_a1l[(size_t)2*BATCH*NNODES*256];
__device__ __nv_bfloat16 g_a2h[(size_t)2*BATCH*NNODES*128];
__device__ __nv_bfloat16 g_a2l[(size_t)2*BATCH*NNODES*128];
// Weight images: bf16 hi/lo, per (och64,kt) 64x64 SW128-swizzled tiles
__device__ __nv_bfloat16 g_whi1[4*3*4096],  g_wlo1[4*3*4096];   // O=256,CK=192
__device__ __nv_bfloat16 g_whi2[2*12*4096], g_wlo2[2*12*4096];  // O=128,CK=768
__device__ __nv_bfloat16 g_whi3[1*6*4096],  g_wlo3[1*6*4096];   // O=64, CK=384
__device__ float g_part[2*BATCH*32*2];
__device__ float g_st1[2*BATCH*2];
__device__ float g_st2[2*BATCH*2];
__device__ float g_st3[2*BATCH*2];

// ---- helpers ----------------------------------------------------------------
__device__ __forceinline__ uint32_t smem_u32(const void* p) {
    uint32_t a;
    asm("{ .reg .u64 t; cvta.to.shared.u64 t, %1; cvt.u32.u64 %0, t; }"
        : "=r"(a) : "l"(p));
    return a;
}
#define CP16(dst, src) \
    asm volatile("cp.async.cg.shared.global [%0], [%1], 16;" :: "r"(dst), "l"(src))
#define CPCOMMIT() asm volatile("cp.async.commit_group;" ::: "memory")

__device__ __forceinline__ void ldsm4(uint32_t* r, uint32_t addr) {
    asm volatile("ldmatrix.sync.aligned.m8n8.x4.shared.b16 {%0,%1,%2,%3}, [%4];"
        : "=r"(r[0]), "=r"(r[1]), "=r"(r[2]), "=r"(r[3]) : "r"(addr));
}
__device__ __forceinline__ void mma_bf16(float* c, const uint32_t* a,
                                         uint32_t b0, uint32_t b1) {
    asm volatile(
        "mma.sync.aligned.m16n8k16.row.col.f32.bf16.bf16.f32 "
        "{%0,%1,%2,%3}, {%4,%5,%6,%7}, {%8,%9}, {%0,%1,%2,%3};"
        : "+f"(c[0]), "+f"(c[1]), "+f"(c[2]), "+f"(c[3])
        : "r"(a[0]), "r"(a[1]), "r"(a[2]), "r"(a[3]), "r"(b0), "r"(b1));
}

// ---------------------------------------------------------------------------
// Transpose raw input [b][C=64][N=1024] -> act0 [tower*128+b][N][64] (f32)
// ---------------------------------------------------------------------------
__global__ __launch_bounds__(256) void transpose_kernel(
    const float* __restrict__ d1, const float* __restrict__ d2,
    float* __restrict__ act0)
{
    __shared__ float tile[32][33];
    int tb = blockIdx.z;
    int tower = tb / BATCH, b = tb % BATCH;
    const float* src = (tower ? d2 : d1) + (size_t)b * 64 * NNODES;
    float* dst = act0 + (size_t)tb * NNODES * 64;
    int n0 = blockIdx.x * 32, c0 = blockIdx.y * 32;
    for (int i = threadIdx.y; i < 32; i += 8)
        tile[i][threadIdx.x] = src[(size_t)(c0 + i) * NNODES + n0 + threadIdx.x];
    __syncthreads();
    for (int i = threadIdx.y; i < 32; i += 8)
        dst[(size_t)(n0 + i) * 64 + c0 + threadIdx.x] = tile[threadIdx.x][i];
}

// ---------------------------------------------------------------------------
// Build bf16 hi/lo weight images, SW128-swizzled 64x64 tiles.
// ---------------------------------------------------------------------------
__global__ void make_wimg(const float* __restrict__ w,
                          __nv_bfloat16* __restrict__ hi,
                          __nv_bfloat16* __restrict__ lo,
                          int O, int C, int NT)
{
    int i = blockIdx.x * 256 + threadIdx.x;
    if (i >= O * 3 * C) return;
    int tile = i >> 12, e = i & 4095;
    int row = e >> 6, col = e & 63;
    int och = tile / NT, kt = tile % NT;
    int o = och * 64 + row;
    int ck = kt * 64 + col;
    int k = ck / C, c = ck - k * C;
    float x = w[(o * C + c) * 3 + k];
    __nv_bfloat16 h = __float2bfloat16(x);
    __nv_bfloat16 l = __float2bfloat16(x - __bfloat162float(h));
    int boff = row * 128 + col * 2;
    int sw = boff ^ ((boff >> 3) & 0x70);
    hi[((size_t)tile << 12) + (sw >> 1)] = h;
    lo[((size_t)tile << 12) + (sw >> 1)] = l;
}

// ---------------------------------------------------------------------------
// Zero node-0 rows of act1/2/3 (f32)
// ---------------------------------------------------------------------------
__global__ void zero_rows(float* a1, float* a2, float* a3)
{
    int tb = blockIdx.x;
    for (int i = threadIdx.x; i < 256; i += blockDim.x) a1[(size_t)tb * NNODES * 256 + i] = 0.f;
    for (int i = threadIdx.x; i < 128; i += blockDim.x) a2[(size_t)tb * NNODES * 128 + i] = 0.f;
    for (int i = threadIdx.x; i <  64; i += blockDim.x) a3[(size_t)tb * NNODES *  64 + i] = 0.f;
}

// ---------------------------------------------------------------------------
// Optionally apply LN+leakyReLU, then split f32 -> bf16 hi/lo arrays.
// ---------------------------------------------------------------------------
__global__ __launch_bounds__(256) void transform_split(
    const float* __restrict__ act, const float* __restrict__ stats,
    __nv_bfloat16* __restrict__ hi, __nv_bfloat16* __restrict__ lo,
    int O, int ln)
{
    int tb = blockIdx.y;
    float mean = 0.f, inv = 1.f;
    if (ln) { mean = stats[tb * 2]; inv = stats[tb * 2 + 1]; }
    size_t base4 = (size_t)tb * NNODES * O / 4;
    const float4* a = reinterpret_cast<const float4*>(act) + base4;
    int i = blockIdx.x * 256 + threadIdx.x;
    float4 v = a[i];
    if (ln) {
        v.x = (v.x - mean) * inv; v.x = v.x > 0.f ? v.x : 0.01f * v.x;
        v.y = (v.y - mean) * inv; v.y = v.y > 0.f ? v.y : 0.01f * v.y;
        v.z = (v.z - mean) * inv; v.z = v.z > 0.f ? v.z : 0.01f * v.z;
        v.w = (v.w - mean) * inv; v.w = v.w > 0.f ? v.w : 0.01f * v.w;
    }
    uint32_t h01, h23;
    asm("cvt.rn.bf16x2.f32 %0, %1, %2;" : "=r"(h01) : "f"(v.y), "f"(v.x));
    asm("cvt.rn.bf16x2.f32 %0, %1, %2;" : "=r"(h23) : "f"(v.w), "f"(v.z));
    float hx = __uint_as_float(h01 << 16);
    float hy = __uint_as_float(h01 & 0xFFFF0000u);
    float hz = __uint_as_float(h23 << 16);
    float hw = __uint_as_float(h23 & 0xFFFF0000u);
    uint32_t l01, l23;
    asm("cvt.rn.bf16x2.f32 %0, %1, %2;" : "=r"(l01) : "f"(v.y - hy), "f"(v.x - hx));
    asm("cvt.rn.bf16x2.f32 %0, %1, %2;" : "=r"(l23) : "f"(v.w - hw), "f"(v.z - hz));
    u64 hv, lv;
    asm("mov.b64 %0, {%1, %2};" : "=l"(hv) : "r"(h01), "r"(h23));
    asm("mov.b64 %0, {%1, %2};" : "=l"(lv) : "r"(l01), "r"(l23));
    reinterpret_cast<u64*>(hi)[base4 + i] = hv;
    reinterpret_cast<u64*>(lo)[base4 + i] = lv;
}

// ---------------------------------------------------------------------------
// mma.sync gather-conv. Warp tile 64x32 (4 mi x 4 n8 x 3 terms = 48 MMA per
// k16 from 12 ldsm). Block tile 128 x BN, warps = 2mg x (BN/32)ng, threads =
// 2*BN. K-tiles of 64, cp.async double-buffered, 3-term bf16 split.
// ---------------------------------------------------------------------------
template<int C, int O, int BN>
__global__ __launch_bounds__(2 * BN, (BN == 64) ? 2 : 1) void conv_mma(
    const __nv_bfloat16* __restrict__ aHiG, const __nv_bfloat16* __restrict__ aLoG,
    const int* __restrict__ idxA, const int* __restrict__ idxB,
    const __nv_bfloat16* __restrict__ whi, const __nv_bfloat16* __restrict__ wlo,
    const float* __restrict__ bias,
    float* __restrict__ actout, float* __restrict__ part)
{
    constexpr int TM = 128;
    constexpr int CK = 3 * C;
    constexpr int KT = 64;
    constexpr int NT = CK / KT;
    constexpr int OCHB = O / BN;       // BN-sized o-chunks
    constexpr int NSUB = BN / 64;      // 64-row B subtiles per stage
    constexpr int NTH = 2 * BN;        // threads
    constexpr int NGC = BN / 32;       // n-groups
    constexpr uint32_t BSTG = (uint32_t)BN * 256u;  // bytes per B stage (hi+lo)

    extern __shared__ char dsm_raw[];
    char* dsm = (char*)(((uintptr_t)dsm_raw + 1023) & ~(uintptr_t)1023);
    __shared__ int nodes[TM * 3];
    __shared__ float red[16];

    const int tid = threadIdx.x, lane = tid & 31, warp = tid >> 5;
    const int mg = warp / NGC, ng = warp % NGC;
    const int ochb = blockIdx.x % OCHB;
    const int m0 = (blockIdx.x / OCHB) * TM;
    const int tb = blockIdx.z * BATCH + blockIdx.y;
    const int* idx = (blockIdx.z ? idxB : idxA) + blockIdx.y * T3;

    for (int t = tid; t < TM * 3; t += NTH) {
        int tt = m0 * 3 + t;
        nodes[t] = (tt < T3) ? idx[tt] : 0;
    }
    __syncthreads();

    const uint32_t sb = smem_u32(dsm);
    // layout: aHi[2]@0 (16KB/stage), aLo[2]@32768, B stages @65536 (BSTG each)
    const __nv_bfloat16* aG[2] = { aHiG + (size_t)tb * NNODES * C,
                                   aLoG + (size_t)tb * NNODES * C };

    auto issue = [&](int kt, int s) {
        const int k = (kt * KT) / C;
        const int cbase = kt * KT - k * C;
        // B: linear copy of pre-swizzled 64x64 subtiles (hi then lo)
        const uint32_t bb = sb + 65536u + (uint32_t)s * BSTG;
#pragma unroll 2
        for (int e = tid; e < NSUB * 1024; e += NTH) {
            int ss = e / (NSUB * 512);             // 0=hi, 1=lo
            int e2 = e - ss * NSUB * 512;
            int st = e2 >> 9, q = e2 & 511;
            const __nv_bfloat16* src =
                (ss ? wlo : whi) + (((size_t)((ochb * NSUB + st) * NT + kt)) << 12) + q * 8;
            CP16(bb + (uint32_t)ss * (BN * 128u) + (uint32_t)st * 8192u
                    + (uint32_t)q * 16u, src);
        }
        // A: gathered rows, hi/lo, SW128 swizzle on 16B chunks
        const uint32_t adst[2] = { sb + (uint32_t)s * 16384u,
                                   sb + 32768u + (uint32_t)s * 16384u };
#pragma unroll 4
        for (int e = tid; e < 2048; e += NTH) {
            int ss = e >> 10, e2 = e & 1023, r = e2 >> 3, q = e2 & 7;
            const __nv_bfloat16* src =
                aG[ss] + (size_t)nodes[r * 3 + k] * C + cbase + q * 8;
            uint32_t off = ((uint32_t)(r * 128 + q * 16)) ^ (((uint32_t)(r & 7)) << 4);
            CP16(adst[ss] + off, src);
        }
        CPCOMMIT();
    };

    float acc[4][4][4];
#pragma unroll
    for (int mi = 0; mi < 4; mi++)
#pragma unroll
        for (int i = 0; i < 4; i++)
#pragma unroll
            for (int j = 0; j < 4; j++) acc[mi][i][j] = 0.f;

    // ldmatrix lane constants
    const int arow0 = mg * 64 + (lane & 15);              // + mi*16
    const uint32_t aswz = ((uint32_t)(arow0 & 7)) << 4;   // invariant under +16
    const uint32_t akh = ((lane >> 4) & 1) * 16;
    const int brow_in = lane & 7;
    const int bps = (lane >> 4) & 1;
    const uint32_t bkh = ((lane >> 3) & 1) * 16;
    const uint32_t bswz = ((uint32_t)brow_in) << 4;

    issue(0, 0);
    for (int kt = 0; kt < NT; kt++) {
        if (kt + 1 < NT) {
            issue(kt + 1, (kt + 1) & 1);
            asm volatile("cp.async.wait_group 1;" ::: "memory");
        } else {
            asm volatile("cp.async.wait_group 0;" ::: "memory");
        }
        __syncthreads();
        const int s = kt & 1;
        const uint32_t ahb = sb + (uint32_t)s * 16384u;
        const uint32_t bhb = sb + 65536u + (uint32_t)s * BSTG;
#pragma unroll
        for (int ks = 0; ks < 4; ks++) {
            const uint32_t akb = (uint32_t)(ks * 32) + akh;
            uint32_t Ah[4][4], Al[4][4];
#pragma unroll
            for (int mi = 0; mi < 4; mi++) {
                uint32_t aoff = (uint32_t)(arow0 + mi * 16) * 128u + (akb ^ aswz);
                ldsm4(Ah[mi], ahb + aoff);
                ldsm4(Al[mi], ahb + 32768u + aoff);
            }
            const uint32_t bkb = (uint32_t)(ks * 32) + bkh;
            uint32_t Bh[2][4], Bl[2][4];
#pragma unroll
            for (int p2 = 0; p2 < 2; p2++) {
                int r = ng * 32 + p2 * 16 + bps * 8 + brow_in;
                uint32_t boff = (uint32_t)(r >> 6) * 8192u
                              + (uint32_t)(r & 63) * 128u + (bkb ^ bswz);
                ldsm4(Bh[p2], bhb + boff);
                ldsm4(Bl[p2], bhb + (uint32_t)(BN * 128u) + boff);
            }
#pragma unroll
            for (int mi = 0; mi < 4; mi++) {
#pragma unroll
                for (int p2 = 0; p2 < 2; p2++) {
                    mma_bf16(acc[mi][p2 * 2],     Ah[mi], Bh[p2][0], Bh[p2][1]);
                    mma_bf16(acc[mi][p2 * 2],     Ah[mi], Bl[p2][0], Bl[p2][1]);
                    mma_bf16(acc[mi][p2 * 2],     Al[mi], Bh[p2][0], Bh[p2][1]);
                    mma_bf16(acc[mi][p2 * 2 + 1], Ah[mi], Bh[p2][2], Bh[p2][3]);
                    mma_bf16(acc[mi][p2 * 2 + 1], Ah[mi], Bl[p2][2], Bl[p2][3]);
                    mma_bf16(acc[mi][p2 * 2 + 1], Al[mi], Bh[p2][2], Bh[p2][3]);
                }
            }
        }
        __syncthreads();
    }

    // Epilogue: D fragments -> gmem (float2) + fused stats
    float ls = 0.f, lss = 0.f;
    float* aout = actout + (size_t)tb * NNODES * O;
#pragma unroll
    for (int mi = 0; mi < 4; mi++) {
        const int r0 = m0 + mg * 64 + mi * 16 + (lane >> 2);
#pragma unroll
        for (int nt = 0; nt < 4; nt++) {
            int col = ochb * BN + ng * 32 + nt * 8 + 2 * (lane & 3);
            float2 bv = *reinterpret_cast<const float2*>(bias + col);
            if (r0 < NTRI) {
                float2 v;
                v.x = acc[mi][nt][0] + bv.x; v.y = acc[mi][nt][1] + bv.y;
                *reinterpret_cast<float2*>(aout + (size_t)(r0 + 1) * O + col) = v;
                ls += v.x + v.y;
                lss = fmaf(v.x, v.x, lss); lss = fmaf(v.y, v.y, lss);
            }
            if (r0 + 8 < NTRI) {
                float2 v;
                v.x = acc[mi][nt][2] + bv.x; v.y = acc[mi][nt][3] + bv.y;
                *reinterpret_cast<float2*>(aout + (size_t)(r0 + 9) * O + col) = v;
                ls += v.x + v.y;
                lss = fmaf(v.x, v.x, lss); lss = fmaf(v.y, v.y, lss);
            }
        }
    }
#pragma unroll
    for (int off = 16; off > 0; off >>= 1) {
        ls  += __shfl_xor_sync(0xffffffffu, ls,  off);
        lss += __shfl_xor_sync(0xffffffffu, lss, off);
    }
    if (lane == 0) { red[warp] = ls; red[8 + warp] = lss; }
    __syncthreads();
    if (tid == 0) {
        float s = 0.f, ss = 0.f;
#pragma unroll
        for (int wv = 0; wv < NTH / 32; wv++) { s += red[wv]; ss += red[8 + wv]; }
        float* pp = part + ((size_t)tb * 32 + blockIdx.x) * 2;
        pp[0] = s; pp[1] = ss;
    }
}

// ---------------------------------------------------------------------------
// Finalize stats: reduce nparts partials per (tower,b)
// ---------------------------------------------------------------------------
__global__ __launch_bounds__(256) void finalize_stats(
    const float* __restrict__ part, float* __restrict__ stats, int O, int nparts)
{
    int tb = threadIdx.x;
    double s = 0.0, ss = 0.0;
    for (int i = 0; i < nparts; i++) {
        s += (double)part[((size_t)tb * 32 + i) * 2];
        ss += (double)part[((size_t)tb * 32 + i) * 2 + 1];
    }
    double n = 1024.0 * O;
    double mean = s / n;
    double var = (ss - s * s / n) / (n - 1.0);
    if (var < 0.0) var = 0.0;
    stats[tb * 2] = (float)mean;
    stats[tb * 2 + 1] = (float)(1.0 / (sqrt(var) + 1e-5));
}

// ---------------------------------------------------------------------------
// Final head: LN(act3) -> max-pool -> FC1(lrelu) -> FC2 -> sigmoid(diff)
// ---------------------------------------------------------------------------
__global__ __launch_bounds__(256) void final_kernel(
    const float* __restrict__ act3, const float* __restrict__ stats3,
    const float* __restrict__ wfc1, const float* __restrict__ bfc1,
    const float* __restrict__ wfc2, const float* __restrict__ bfc2,
    float* __restrict__ out)
{
    int b = blockIdx.x;
    int tid = threadIdx.x;
    __shared__ float mx[4][64];
    __shared__ float h[32];
    __shared__ float yy[2];

    for (int tower = 0; tower < 2; tower++) {
        int tb = tower * BATCH + b;
        float mean = stats3[tb * 2], inv = stats3[tb * 2 + 1];
        const float* a = act3 + (size_t)tb * NNODES * 64;
        int c = tid & 63, grp = tid >> 6;
        float m = -1e30f;
        for (int n = grp; n < NNODES; n += 4) {
            float v = (a[(size_t)n * 64 + c] - mean) * inv;
            m = fmaxf(m, v);
        }
        mx[grp][c] = m;
        __syncthreads();
        if (tid < 64) {
            mx[0][tid] = fmaxf(fmaxf(mx[0][tid], mx[1][tid]),
                               fmaxf(mx[2][tid], mx[3][tid]));
        }
        __syncthreads();
        if (tid < 32) {
            float sAcc = bfc1[tid];
            for (int c2 = 0; c2 < 64; c2++) sAcc = fmaf(mx[0][c2], wfc1[tid * 64 + c2], sAcc);
            h[tid] = sAcc > 0.f ? sAcc : 0.01f * sAcc;
        }
        __syncthreads();
        if (tid == 0) {
            float sAcc = bfc2[0];
            for (int i = 0; i < 32; i++) sAcc = fmaf(h[i], wfc2[i], sAcc);
            yy[tower] = sAcc;
        }
        __syncthreads();
    }
    if (tid == 0) {
        float d = yy[0] - yy[1];
        out[b] = 1.f / (1.f + expf(-d));
    }
}

// ---------------------------------------------------------------------------
extern "C" void kernel_launch(void* const* d_in, const int* in_sizes, int n_in,
                              void* d_out, int out_size)
{
    const float* data1 = (const float*)d_in[0];
    const int*   idx1  = (const int*)d_in[1];
    const float* data2 = (const float*)d_in[2];
    const int*   idx2  = (const int*)d_in[3];
    const float* w1 = (const float*)d_in[4];
    const float* b1 = (const float*)d_in[5];
    const float* w2 = (const float*)d_in[6];
    const float* b2 = (const float*)d_in[7];
    const float* w3 = (const float*)d_in[8];
    const float* b3 = (const float*)d_in[9];
    const float* wfc1 = (const float*)d_in[10];
    const float* bfc1 = (const float*)d_in[11];
    const float* wfc2 = (const float*)d_in[12];
    const float* bfc2 = (const float*)d_in[13];
    float* out = (float*)d_out;

    float *act0, *act1, *act2, *act3, *part, *st1, *st2, *st3;
    __nv_bfloat16 *a0h, *a0l, *a1h, *a1l, *a2h, *a2l;
    __nv_bfloat16 *whi1, *wlo1, *whi2, *wlo2, *whi3, *wlo3;
    cudaGetSymbolAddress((void**)&act0, g_act0);
    cudaGetSymbolAddress((void**)&act1, g_act1);
    cudaGetSymbolAddress((void**)&act2, g_act2);
    cudaGetSymbolAddress((void**)&act3, g_act3);
    cudaGetSymbolAddress((void**)&a0h, g_a0h);
    cudaGetSymbolAddress((void**)&a0l, g_a0l);
    cudaGetSymbolAddress((void**)&a1h, g_a1h);
    cudaGetSymbolAddress((void**)&a1l, g_a1l);
    cudaGetSymbolAddress((void**)&a2h, g_a2h);
    cudaGetSymbolAddress((void**)&a2l, g_a2l);
    cudaGetSymbolAddress((void**)&whi1, g_whi1);
    cudaGetSymbolAddress((void**)&wlo1, g_wlo1);
    cudaGetSymbolAddress((void**)&whi2, g_whi2);
    cudaGetSymbolAddress((void**)&wlo2, g_wlo2);
    cudaGetSymbolAddress((void**)&whi3, g_whi3);
    cudaGetSymbolAddress((void**)&wlo3, g_wlo3);
    cudaGetSymbolAddress((void**)&part, g_part);
    cudaGetSymbolAddress((void**)&st1, g_st1);
    cudaGetSymbolAddress((void**)&st2, g_st2);
    cudaGetSymbolAddress((void**)&st3, g_st3);

    // dyn smem: align 1024 + A 64KB + B 2 stages * (BN*256)
    const int smem128 = 1024 + 65536 + 2 * 128 * 256;  // 132096
    const int smem64  = 1024 + 65536 + 2 * 64 * 256;   //  99328
    cudaFuncSetAttribute(conv_mma<64, 256, 128>,
                         cudaFuncAttributeMaxDynamicSharedMemorySize, smem128);
    cudaFuncSetAttribute(conv_mma<256, 128, 128>,
                         cudaFuncAttributeMaxDynamicSharedMemorySize, smem128);
    cudaFuncSetAttribute(conv_mma<128, 64, 64>,
                         cudaFuncAttributeMaxDynamicSharedMemorySize, smem64);

    // Launch order: conv1 is the 4th launch (ncu capture slot).
    transpose_kernel<<<dim3(32, 2, 256), dim3(32, 8)>>>(data1, data2, act0);
    make_wimg<<<(256 * 192 + 255) / 256, 256>>>(w1, whi1, wlo1, 256, 64, 3);
    transform_split<<<dim3(NNODES * 64 / 4 / 256, 256), 256>>>(
        act0, st1, a0h, a0l, 64, 0);

    conv_mma<64, 256, 128><<<dim3(16, BATCH, 2), 256, smem128>>>(
        a0h, a0l, idx1, idx2, whi1, wlo1, b1, act1, part);
    zero_rows<<<256, 256>>>(act1, act2, act3);
    finalize_stats<<<1, 256>>>(part, st1, 256, 16);
    transform_split<<<dim3(NNODES * 256 / 4 / 256, 256), 256>>>(
        act1, st1, a1h, a1l, 256, 1);
    make_wimg<<<(128 * 768 + 255) / 256, 256>>>(w2, whi2, wlo2, 128, 256, 12);

    conv_mma<256, 128, 128><<<dim3(8, BATCH, 2), 256, smem128>>>(
        a1h, a1l, idx1, idx2, whi2, wlo2, b2, act2, part);
    finalize_stats<<<1, 256>>>(part, st2, 128, 8);
    transform_split<<<dim3(NNODES * 128 / 4 / 256, 256), 256>>>(
        act2, st2, a2h, a2l, 128, 1);
    make_wimg<<<(64 * 384 + 255) / 256, 256>>>(w3, whi3, wlo3, 64, 128, 6);

    conv_mma<128, 64, 64><<<dim3(8, BATCH, 2), 128, smem64>>>(
        a2h, a2l, idx1, idx2, whi3, wlo3, b3, act3, part);
    finalize_stats<<<1, 256>>>(part, st3, 64, 8);

    final_kernel<<<BATCH, 256>>>(act3, st3, wfc1, bfc1, wfc2, bfc2, out);
}

// round 12
// speedup vs baseline: 4.1436x; 1.0000x over previous
#include <cuda_runtime.h>
#include <cuda_bf16.h>
#include <math.h>
#include <stdint.h>

#define BATCH 128
#define NNODES 1024
#define NTRI 1023
#define T3 3069

typedef unsigned long long u64;

// f32 activations (conv outputs; node-major [tower*128+b][node][C])
__device__ float g_act0[(size_t)2*BATCH*NNODES*64];
__device__ float g_act1[(size_t)2*BATCH*NNODES*256];
__device__ float g_act2[(size_t)2*BATCH*NNODES*128];
__device__ float g_act3[(size_t)2*BATCH*NNODES*64];
// bf16 hi/lo split activations (conv inputs)
__device__ __nv_bfloat16 g_a0h[(size_t)2*BATCH*NNODES*64];
__device__ __nv_bfloat16 g_a0l[(size_t)2*BATCH*NNODES*64];
__device__ __nv_bfloat16 g_a1h[(size_t)2*BATCH*NNODES*256];
__device__ __nv_bfloat16 g_a1l[(size_t)2*BATCH*NNODES*256];
__device__ __nv_bfloat16 g_a2h[(size_t)2*BATCH*NNODES*128];
__device__ __nv_bfloat16 g_a2l[(size_t)2*BATCH*NNODES*128];
// Weight images: bf16 hi/lo, per (och64,kt) 64x64 SW128-swizzled tiles
__device__ __nv_bfloat16 g_whi1[4*3*4096],  g_wlo1[4*3*4096];   // O=256,CK=192
__device__ __nv_bfloat16 g_whi2[2*12*4096], g_wlo2[2*12*4096];  // O=128,CK=768
__device__ __nv_bfloat16 g_whi3[1*6*4096],  g_wlo3[1*6*4096];   // O=64, CK=384
__device__ float g_part[2*BATCH*32*2];
__device__ float g_st1[2*BATCH*2];
__device__ float g_st2[2*BATCH*2];
__device__ float g_st3[2*BATCH*2];

// ---- helpers ----------------------------------------------------------------
__device__ __forceinline__ uint32_t smem_u32(const void* p) {
    uint32_t a;
    asm("{ .reg .u64 t; cvta.to.shared.u64 t, %1; cvt.u32.u64 %0, t; }"
        : "=r"(a) : "l"(p));
    return a;
}
#define CP16(dst, src) \
    asm volatile("cp.async.cg.shared.global [%0], [%1], 16;" :: "r"(dst), "l"(src))
#define CPCOMMIT() asm volatile("cp.async.commit_group;" ::: "memory")

__device__ __forceinline__ void ldsm4(uint32_t* r, uint32_t addr) {
    asm volatile("ldmatrix.sync.aligned.m8n8.x4.shared.b16 {%0,%1,%2,%3}, [%4];"
        : "=r"(r[0]), "=r"(r[1]), "=r"(r[2]), "=r"(r[3]) : "r"(addr));
}
__device__ __forceinline__ void mma_bf16(float* c, const uint32_t* a,
                                         uint32_t b0, uint32_t b1) {
    asm volatile(
        "mma.sync.aligned.m16n8k16.row.col.f32.bf16.bf16.f32 "
        "{%0,%1,%2,%3}, {%4,%5,%6,%7}, {%8,%9}, {%0,%1,%2,%3};"
        : "+f"(c[0]), "+f"(c[1]), "+f"(c[2]), "+f"(c[3])
        : "r"(a[0]), "r"(a[1]), "r"(a[2]), "r"(a[3]), "r"(b0), "r"(b1));
}

// ---------------------------------------------------------------------------
// Transpose raw input [b][C=64][N=1024] -> act0 [tower*128+b][N][64] (f32)
// ---------------------------------------------------------------------------
__global__ __launch_bounds__(256) void transpose_kernel(
    const float* __restrict__ d1, const float* __restrict__ d2,
    float* __restrict__ act0)
{
    __shared__ float tile[32][33];
    int tb = blockIdx.z;
    int tower = tb / BATCH, b = tb % BATCH;
    const float* src = (tower ? d2 : d1) + (size_t)b * 64 * NNODES;
    float* dst = act0 + (size_t)tb * NNODES * 64;
    int n0 = blockIdx.x * 32, c0 = blockIdx.y * 32;
    for (int i = threadIdx.y; i < 32; i += 8)
        tile[i][threadIdx.x] = src[(size_t)(c0 + i) * NNODES + n0 + threadIdx.x];
    __syncthreads();
    for (int i = threadIdx.y; i < 32; i += 8)
        dst[(size_t)(n0 + i) * 64 + c0 + threadIdx.x] = tile[threadIdx.x][i];
}

// ---------------------------------------------------------------------------
// Build bf16 hi/lo weight images, SW128-swizzled 64x64 tiles.
// ---------------------------------------------------------------------------
__global__ void make_wimg(const float* __restrict__ w,
                          __nv_bfloat16* __restrict__ hi,
                          __nv_bfloat16* __restrict__ lo,
                          int O, int C, int NT)
{
    int i = blockIdx.x * 256 + threadIdx.x;
    if (i >= O * 3 * C) return;
    int tile = i >> 12, e = i & 4095;
    int row = e >> 6, col = e & 63;
    int och = tile / NT, kt = tile % NT;
    int o = och * 64 + row;
    int ck = kt * 64 + col;
    int k = ck / C, c = ck - k * C;
    float x = w[(o * C + c) * 3 + k];
    __nv_bfloat16 h = __float2bfloat16(x);
    __nv_bfloat16 l = __float2bfloat16(x - __bfloat162float(h));
    int boff = row * 128 + col * 2;
    int sw = boff ^ ((boff >> 3) & 0x70);
    hi[((size_t)tile << 12) + (sw >> 1)] = h;
    lo[((size_t)tile << 12) + (sw >> 1)] = l;
}

// ---------------------------------------------------------------------------
// Zero node-0 rows of act1/2/3 (f32)
// ---------------------------------------------------------------------------
__global__ void zero_rows(float* a1, float* a2, float* a3)
{
    int tb = blockIdx.x;
    for (int i = threadIdx.x; i < 256; i += blockDim.x) a1[(size_t)tb * NNODES * 256 + i] = 0.f;
    for (int i = threadIdx.x; i < 128; i += blockDim.x) a2[(size_t)tb * NNODES * 128 + i] = 0.f;
    for (int i = threadIdx.x; i <  64; i += blockDim.x) a3[(size_t)tb * NNODES *  64 + i] = 0.f;
}

// ---------------------------------------------------------------------------
// Optionally apply LN+leakyReLU, then split f32 -> bf16 hi/lo arrays.
// ---------------------------------------------------------------------------
__global__ __launch_bounds__(256) void transform_split(
    const float* __restrict__ act, const float* __restrict__ stats,
    __nv_bfloat16* __restrict__ hi, __nv_bfloat16* __restrict__ lo,
    int O, int ln)
{
    int tb = blockIdx.y;
    float mean = 0.f, inv = 1.f;
    if (ln) { mean = stats[tb * 2]; inv = stats[tb * 2 + 1]; }
    size_t base4 = (size_t)tb * NNODES * O / 4;
    const float4* a = reinterpret_cast<const float4*>(act) + base4;
    int i = blockIdx.x * 256 + threadIdx.x;
    float4 v = a[i];
    if (ln) {
        v.x = (v.x - mean) * inv; v.x = v.x > 0.f ? v.x : 0.01f * v.x;
        v.y = (v.y - mean) * inv; v.y = v.y > 0.f ? v.y : 0.01f * v.y;
        v.z = (v.z - mean) * inv; v.z = v.z > 0.f ? v.z : 0.01f * v.z;
        v.w = (v.w - mean) * inv; v.w = v.w > 0.f ? v.w : 0.01f * v.w;
    }
    uint32_t h01, h23;
    asm("cvt.rn.bf16x2.f32 %0, %1, %2;" : "=r"(h01) : "f"(v.y), "f"(v.x));
    asm("cvt.rn.bf16x2.f32 %0, %1, %2;" : "=r"(h23) : "f"(v.w), "f"(v.z));
    float hx = __uint_as_float(h01 << 16);
    float hy = __uint_as_float(h01 & 0xFFFF0000u);
    float hz = __uint_as_float(h23 << 16);
    float hw = __uint_as_float(h23 & 0xFFFF0000u);
    uint32_t l01, l23;
    asm("cvt.rn.bf16x2.f32 %0, %1, %2;" : "=r"(l01) : "f"(v.y - hy), "f"(v.x - hx));
    asm("cvt.rn.bf16x2.f32 %0, %1, %2;" : "=r"(l23) : "f"(v.w - hw), "f"(v.z - hz));
    u64 hv, lv;
    asm("mov.b64 %0, {%1, %2};" : "=l"(hv) : "r"(h01), "r"(h23));
    asm("mov.b64 %0, {%1, %2};" : "=l"(lv) : "r"(l01), "r"(l23));
    reinterpret_cast<u64*>(hi)[base4 + i] = hv;
    reinterpret_cast<u64*>(lo)[base4 + i] = lv;
}

// ---------------------------------------------------------------------------
// mma.sync gather-conv. Warp tile 64x32, block tile 128 x BN.
// TERM-MAJOR MMA order: all 16 Ah*Bh, then 16 Ah*Bl, then 16 Al*Bh — every
// accumulator reused only once per 16-MMA span (hides HMMA latency).
// ---------------------------------------------------------------------------
template<int C, int O, int BN>
__global__ __launch_bounds__(2 * BN, (BN == 64) ? 2 : 1) void conv_mma(
    const __nv_bfloat16* __restrict__ aHiG, const __nv_bfloat16* __restrict__ aLoG,
    const int* __restrict__ idxA, const int* __restrict__ idxB,
    const __nv_bfloat16* __restrict__ whi, const __nv_bfloat16* __restrict__ wlo,
    const float* __restrict__ bias,
    float* __restrict__ actout, float* __restrict__ part)
{
    constexpr int TM = 128;
    constexpr int CK = 3 * C;
    constexpr int KT = 64;
    constexpr int NT = CK / KT;
    constexpr int OCHB = O / BN;
    constexpr int NSUB = BN / 64;
    constexpr int NTH = 2 * BN;
    constexpr int NGC = BN / 32;
    constexpr uint32_t BSTG = (uint32_t)BN * 256u;

    extern __shared__ char dsm_raw[];
    char* dsm = (char*)(((uintptr_t)dsm_raw + 1023) & ~(uintptr_t)1023);
    __shared__ int nodes[TM * 3];
    __shared__ float red[16];

    const int tid = threadIdx.x, lane = tid & 31, warp = tid >> 5;
    const int mg = warp / NGC, ng = warp % NGC;
    const int ochb = blockIdx.x % OCHB;
    const int m0 = (blockIdx.x / OCHB) * TM;
    const int tb = blockIdx.z * BATCH + blockIdx.y;
    const int* idx = (blockIdx.z ? idxB : idxA) + blockIdx.y * T3;

    for (int t = tid; t < TM * 3; t += NTH) {
        int tt = m0 * 3 + t;
        nodes[t] = (tt < T3) ? idx[tt] : 0;
    }
    __syncthreads();

    const uint32_t sb = smem_u32(dsm);
    const __nv_bfloat16* aG[2] = { aHiG + (size_t)tb * NNODES * C,
                                   aLoG + (size_t)tb * NNODES * C };

    auto issue = [&](int kt, int s) {
        const int k = (kt * KT) / C;
        const int cbase = kt * KT - k * C;
        const uint32_t bb = sb + 65536u + (uint32_t)s * BSTG;
#pragma unroll 2
        for (int e = tid; e < NSUB * 1024; e += NTH) {
            int ss = e / (NSUB * 512);
            int e2 = e - ss * NSUB * 512;
            int st = e2 >> 9, q = e2 & 511;
            const __nv_bfloat16* src =
                (ss ? wlo : whi) + (((size_t)((ochb * NSUB + st) * NT + kt)) << 12) + q * 8;
            CP16(bb + (uint32_t)ss * (BN * 128u) + (uint32_t)st * 8192u
                    + (uint32_t)q * 16u, src);
        }
        const uint32_t adst[2] = { sb + (uint32_t)s * 16384u,
                                   sb + 32768u + (uint32_t)s * 16384u };
#pragma unroll 4
        for (int e = tid; e < 2048; e += NTH) {
            int ss = e >> 10, e2 = e & 1023, r = e2 >> 3, q = e2 & 7;
            const __nv_bfloat16* src =
                aG[ss] + (size_t)nodes[r * 3 + k] * C + cbase + q * 8;
            uint32_t off = ((uint32_t)(r * 128 + q * 16)) ^ (((uint32_t)(r & 7)) << 4);
            CP16(adst[ss] + off, src);
        }
        CPCOMMIT();
    };

    float acc[4][4][4];
#pragma unroll
    for (int mi = 0; mi < 4; mi++)
#pragma unroll
        for (int i = 0; i < 4; i++)
#pragma unroll
            for (int j = 0; j < 4; j++) acc[mi][i][j] = 0.f;

    const int arow0 = mg * 64 + (lane & 15);
    const uint32_t aswz = ((uint32_t)(arow0 & 7)) << 4;
    const uint32_t akh = ((lane >> 4) & 1) * 16;
    const int brow_in = lane & 7;
    const int bps = (lane >> 4) & 1;
    const uint32_t bkh = ((lane >> 3) & 1) * 16;
    const uint32_t bswz = ((uint32_t)brow_in) << 4;

    issue(0, 0);
    for (int kt = 0; kt < NT; kt++) {
        if (kt + 1 < NT) {
            issue(kt + 1, (kt + 1) & 1);
            asm volatile("cp.async.wait_group 1;" ::: "memory");
        } else {
            asm volatile("cp.async.wait_group 0;" ::: "memory");
        }
        __syncthreads();
        const int s = kt & 1;
        const uint32_t ahb = sb + (uint32_t)s * 16384u;
        const uint32_t bhb = sb + 65536u + (uint32_t)s * BSTG;
#pragma unroll
        for (int ks = 0; ks < 4; ks++) {
            const uint32_t akb = (uint32_t)(ks * 32) + akh;
            uint32_t Ah[4][4], Al[4][4];
#pragma unroll
            for (int mi = 0; mi < 4; mi++) {
                uint32_t aoff = (uint32_t)(arow0 + mi * 16) * 128u + (akb ^ aswz);
                ldsm4(Ah[mi], ahb + aoff);
                ldsm4(Al[mi], ahb + 32768u + aoff);
            }
            const uint32_t bkb = (uint32_t)(ks * 32) + bkh;
            uint32_t Bh[2][4], Bl[2][4];
#pragma unroll
            for (int p2 = 0; p2 < 2; p2++) {
                int r = ng * 32 + p2 * 16 + bps * 8 + brow_in;
                uint32_t boff = (uint32_t)(r >> 6) * 8192u
                              + (uint32_t)(r & 63) * 128u + (bkb ^ bswz);
                ldsm4(Bh[p2], bhb + boff);
                ldsm4(Bl[p2], bhb + (uint32_t)(BN * 128u) + boff);
            }
            // term-major: acc RAW distance = 16 MMAs
#pragma unroll
            for (int mi = 0; mi < 4; mi++)
#pragma unroll
                for (int p2 = 0; p2 < 2; p2++) {
                    mma_bf16(acc[mi][p2 * 2],     Ah[mi], Bh[p2][0], Bh[p2][1]);
                    mma_bf16(acc[mi][p2 * 2 + 1], Ah[mi], Bh[p2][2], Bh[p2][3]);
                }
#pragma unroll
            for (int mi = 0; mi < 4; mi++)
#pragma unroll
                for (int p2 = 0; p2 < 2; p2++) {
                    mma_bf16(acc[mi][p2 * 2],     Ah[mi], Bl[p2][0], Bl[p2][1]);
                    mma_bf16(acc[mi][p2 * 2 + 1], Ah[mi], Bl[p2][2], Bl[p2][3]);
                }
#pragma unroll
            for (int mi = 0; mi < 4; mi++)
#pragma unroll
                for (int p2 = 0; p2 < 2; p2++) {
                    mma_bf16(acc[mi][p2 * 2],     Al[mi], Bh[p2][0], Bh[p2][1]);
                    mma_bf16(acc[mi][p2 * 2 + 1], Al[mi], Bh[p2][2], Bh[p2][3]);
                }
        }
        __syncthreads();
    }

    // Epilogue: D fragments -> gmem (float2) + fused stats
    float ls = 0.f, lss = 0.f;
    float* aout = actout + (size_t)tb * NNODES * O;
#pragma unroll
    for (int mi = 0; mi < 4; mi++) {
        const int r0 = m0 + mg * 64 + mi * 16 + (lane >> 2);
#pragma unroll
        for (int nt = 0; nt < 4; nt++) {
            int col = ochb * BN + ng * 32 + nt * 8 + 2 * (lane & 3);
            float2 bv = *reinterpret_cast<const float2*>(bias + col);
            if (r0 < NTRI) {
                float2 v;
                v.x = acc[mi][nt][0] + bv.x; v.y = acc[mi][nt][1] + bv.y;
                *reinterpret_cast<float2*>(aout + (size_t)(r0 + 1) * O + col) = v;
                ls += v.x + v.y;
                lss = fmaf(v.x, v.x, lss); lss = fmaf(v.y, v.y, lss);
            }
            if (r0 + 8 < NTRI) {
                float2 v;
                v.x = acc[mi][nt][2] + bv.x; v.y = acc[mi][nt][3] + bv.y;
                *reinterpret_cast<float2*>(aout + (size_t)(r0 + 9) * O + col) = v;
                ls += v.x + v.y;
                lss = fmaf(v.x, v.x, lss); lss = fmaf(v.y, v.y, lss);
            }
        }
    }
#pragma unroll
    for (int off = 16; off > 0; off >>= 1) {
        ls  += __shfl_xor_sync(0xffffffffu, ls,  off);
        lss += __shfl_xor_sync(0xffffffffu, lss, off);
    }
    if (lane == 0) { red[warp] = ls; red[8 + warp] = lss; }
    __syncthreads();
    if (tid == 0) {
        float s = 0.f, ss = 0.f;
#pragma unroll
        for (int wv = 0; wv < NTH / 32; wv++) { s += red[wv]; ss += red[8 + wv]; }
        float* pp = part + ((size_t)tb * 32 + blockIdx.x) * 2;
        pp[0] = s; pp[1] = ss;
    }
}

// ---------------------------------------------------------------------------
// Finalize stats: reduce nparts partials per (tower,b)
// ---------------------------------------------------------------------------
__global__ __launch_bounds__(256) void finalize_stats(
    const float* __restrict__ part, float* __restrict__ stats, int O, int nparts)
{
    int tb = threadIdx.x;
    double s = 0.0, ss = 0.0;
    for (int i = 0; i < nparts; i++) {
        s += (double)part[((size_t)tb * 32 + i) * 2];
        ss += (double)part[((size_t)tb * 32 + i) * 2 + 1];
    }
    double n = 1024.0 * O;
    double mean = s / n;
    double var = (ss - s * s / n) / (n - 1.0);
    if (var < 0.0) var = 0.0;
    stats[tb * 2] = (float)mean;
    stats[tb * 2 + 1] = (float)(1.0 / (sqrt(var) + 1e-5));
}

// ---------------------------------------------------------------------------
// Final head: LN(act3) -> max-pool -> FC1(lrelu) -> FC2 -> sigmoid(diff)
// ---------------------------------------------------------------------------
__global__ __launch_bounds__(256) void final_kernel(
    const float* __restrict__ act3, const float* __restrict__ stats3,
    const float* __restrict__ wfc1, const float* __restrict__ bfc1,
    const float* __restrict__ wfc2, const float* __restrict__ bfc2,
    float* __restrict__ out)
{
    int b = blockIdx.x;
    int tid = threadIdx.x;
    __shared__ float mx[4][64];
    __shared__ float h[32];
    __shared__ float yy[2];

    for (int tower = 0; tower < 2; tower++) {
        int tb = tower * BATCH + b;
        float mean = stats3[tb * 2], inv = stats3[tb * 2 + 1];
        const float* a = act3 + (size_t)tb * NNODES * 64;
        int c = tid & 63, grp = tid >> 6;
        float m = -1e30f;
        for (int n = grp; n < NNODES; n += 4) {
            float v = (a[(size_t)n * 64 + c] - mean) * inv;
            m = fmaxf(m, v);
        }
        mx[grp][c] = m;
        __syncthreads();
        if (tid < 64) {
            mx[0][tid] = fmaxf(fmaxf(mx[0][tid], mx[1][tid]),
                               fmaxf(mx[2][tid], mx[3][tid]));
        }
        __syncthreads();
        if (tid < 32) {
            float sAcc = bfc1[tid];
            for (int c2 = 0; c2 < 64; c2++) sAcc = fmaf(mx[0][c2], wfc1[tid * 64 + c2], sAcc);
            h[tid] = sAcc > 0.f ? sAcc : 0.01f * sAcc;
        }
        __syncthreads();
        if (tid == 0) {
            float sAcc = bfc2[0];
            for (int i = 0; i < 32; i++) sAcc = fmaf(h[i], wfc2[i], sAcc);
            yy[tower] = sAcc;
        }
        __syncthreads();
    }
    if (tid == 0) {
        float d = yy[0] - yy[1];
        out[b] = 1.f / (1.f + expf(-d));
    }
}

// ---------------------------------------------------------------------------
extern "C" void kernel_launch(void* const* d_in, const int* in_sizes, int n_in,
                              void* d_out, int out_size)
{
    const float* data1 = (const float*)d_in[0];
    const int*   idx1  = (const int*)d_in[1];
    const float* data2 = (const float*)d_in[2];
    const int*   idx2  = (const int*)d_in[3];
    const float* w1 = (const float*)d_in[4];
    const float* b1 = (const float*)d_in[5];
    const float* w2 = (const float*)d_in[6];
    const float* b2 = (const float*)d_in[7];
    const float* w3 = (const float*)d_in[8];
    const float* b3 = (const float*)d_in[9];
    const float* wfc1 = (const float*)d_in[10];
    const float* bfc1 = (const float*)d_in[11];
    const float* wfc2 = (const float*)d_in[12];
    const float* bfc2 = (const float*)d_in[13];
    float* out = (float*)d_out;

    float *act0, *act1, *act2, *act3, *part, *st1, *st2, *st3;
    __nv_bfloat16 *a0h, *a0l, *a1h, *a1l, *a2h, *a2l;
    __nv_bfloat16 *whi1, *wlo1, *whi2, *wlo2, *whi3, *wlo3;
    cudaGetSymbolAddress((void**)&act0, g_act0);
    cudaGetSymbolAddress((void**)&act1, g_act1);
    cudaGetSymbolAddress((void**)&act2, g_act2);
    cudaGetSymbolAddress((void**)&act3, g_act3);
    cudaGetSymbolAddress((void**)&a0h, g_a0h);
    cudaGetSymbolAddress((void**)&a0l, g_a0l);
    cudaGetSymbolAddress((void**)&a1h, g_a1h);
    cudaGetSymbolAddress((void**)&a1l, g_a1l);
    cudaGetSymbolAddress((void**)&a2h, g_a2h);
    cudaGetSymbolAddress((void**)&a2l, g_a2l);
    cudaGetSymbolAddress((void**)&whi1, g_whi1);
    cudaGetSymbolAddress((void**)&wlo1, g_wlo1);
    cudaGetSymbolAddress((void**)&whi2, g_whi2);
    cudaGetSymbolAddress((void**)&wlo2, g_wlo2);
    cudaGetSymbolAddress((void**)&whi3, g_whi3);
    cudaGetSymbolAddress((void**)&wlo3, g_wlo3);
    cudaGetSymbolAddress((void**)&part, g_part);
    cudaGetSymbolAddress((void**)&st1, g_st1);
    cudaGetSymbolAddress((void**)&st2, g_st2);
    cudaGetSymbolAddress((void**)&st3, g_st3);

    const int smem128 = 1024 + 65536 + 2 * 128 * 256;  // 132096
    const int smem64  = 1024 + 65536 + 2 * 64 * 256;   //  99328
    cudaFuncSetAttribute(conv_mma<64, 256, 128>,
                         cudaFuncAttributeMaxDynamicSharedMemorySize, smem128);
    cudaFuncSetAttribute(conv_mma<256, 128, 128>,
                         cudaFuncAttributeMaxDynamicSharedMemorySize, smem128);
    cudaFuncSetAttribute(conv_mma<128, 64, 64>,
                         cudaFuncAttributeMaxDynamicSharedMemorySize, smem64);

    // Launch order: conv1 is the 4th launch (ncu capture slot).
    transpose_kernel<<<dim3(32, 2, 256), dim3(32, 8)>>>(data1, data2, act0);
    make_wimg<<<(256 * 192 + 255) / 256, 256>>>(w1, whi1, wlo1, 256, 64, 3);
    transform_split<<<dim3(NNODES * 64 / 4 / 256, 256), 256>>>(
        act0, st1, a0h, a0l, 64, 0);

    conv_mma<64, 256, 128><<<dim3(16, BATCH, 2), 256, smem128>>>(
        a0h, a0l, idx1, idx2, whi1, wlo1, b1, act1, part);
    zero_rows<<<256, 256>>>(act1, act2, act3);
    finalize_stats<<<1, 256>>>(part, st1, 256, 16);
    transform_split<<<dim3(NNODES * 256 / 4 / 256, 256), 256>>>(
        act1, st1, a1h, a1l, 256, 1);
    make_wimg<<<(128 * 768 + 255) / 256, 256>>>(w2, whi2, wlo2, 128, 256, 12);

    conv_mma<256, 128, 128><<<dim3(8, BATCH, 2), 256, smem128>>>(
        a1h, a1l, idx1, idx2, whi2, wlo2, b2, act2, part);
    finalize_stats<<<1, 256>>>(part, st2, 128, 8);
    transform_split<<<dim3(NNODES * 128 / 4 / 256, 256), 256>>>(
        act2, st2, a2h, a2l, 128, 1);
    make_wimg<<<(64 * 384 + 255) / 256, 256>>>(w3, whi3, wlo3, 64, 128, 6);

    conv_mma<128, 64, 64><<<dim3(8, BATCH, 2), 128, smem64>>>(
        a2h, a2l, idx1, idx2, whi3, wlo3, b3, act3, part);
    finalize_stats<<<1, 256>>>(part, st3, 64, 8);

    final_kernel<<<BATCH, 256>>>(act3, st3, wfc1, bfc1, wfc2, bfc2, out);
}

// round 13
// speedup vs baseline: 4.1463x; 1.0006x over previous
#include <cuda_runtime.h>
#include <cuda_bf16.h>
#include <math.h>
#include <stdint.h>

#define BATCH 128
#define NNODES 1024
#define NTRI 1023
#define T3 3069

typedef unsigned long long u64;

// f32 activations (conv outputs; node-major [tower*128+b][node][C])
__device__ float g_act0[(size_t)2*BATCH*NNODES*64];
__device__ float g_act1[(size_t)2*BATCH*NNODES*256];
__device__ float g_act2[(size_t)2*BATCH*NNODES*128];
__device__ float g_act3[(size_t)2*BATCH*NNODES*64];
// bf16 hi/lo split activations (conv inputs)
__device__ __nv_bfloat16 g_a0h[(size_t)2*BATCH*NNODES*64];
__device__ __nv_bfloat16 g_a0l[(size_t)2*BATCH*NNODES*64];
__device__ __nv_bfloat16 g_a1h[(size_t)2*BATCH*NNODES*256];
__device__ __nv_bfloat16 g_a1l[(size_t)2*BATCH*NNODES*256];
__device__ __nv_bfloat16 g_a2h[(size_t)2*BATCH*NNODES*128];
__device__ __nv_bfloat16 g_a2l[(size_t)2*BATCH*NNODES*128];
// Weight images: bf16 hi/lo, per (och64,kt) 64x64 SW128-swizzled tiles
__device__ __nv_bfloat16 g_whi1[4*3*4096],  g_wlo1[4*3*4096];   // O=256,CK=192
__device__ __nv_bfloat16 g_whi2[2*12*4096], g_wlo2[2*12*4096];  // O=128,CK=768
__device__ __nv_bfloat16 g_whi3[1*6*4096],  g_wlo3[1*6*4096];   // O=64, CK=384
__device__ float g_part[2*BATCH*32*2];
__device__ float g_st1[2*BATCH*2];
__device__ float g_st2[2*BATCH*2];
__device__ float g_st3[2*BATCH*2];

// ---- helpers ----------------------------------------------------------------
__device__ __forceinline__ uint32_t smem_u32(const void* p) {
    uint32_t a;
    asm("{ .reg .u64 t; cvta.to.shared.u64 t, %1; cvt.u32.u64 %0, t; }"
        : "=r"(a) : "l"(p));
    return a;
}
#define CP16(dst, src) \
    asm volatile("cp.async.cg.shared.global [%0], [%1], 16;" :: "r"(dst), "l"(src))
#define CPCOMMIT() asm volatile("cp.async.commit_group;" ::: "memory")

__device__ __forceinline__ void ldsm4(uint32_t* r, uint32_t addr) {
    asm volatile("ldmatrix.sync.aligned.m8n8.x4.shared.b16 {%0,%1,%2,%3}, [%4];"
        : "=r"(r[0]), "=r"(r[1]), "=r"(r[2]), "=r"(r[3]) : "r"(addr));
}
__device__ __forceinline__ void mma_bf16(float* c, const uint32_t* a,
                                         uint32_t b0, uint32_t b1) {
    asm volatile(
        "mma.sync.aligned.m16n8k16.row.col.f32.bf16.bf16.f32 "
        "{%0,%1,%2,%3}, {%4,%5,%6,%7}, {%8,%9}, {%0,%1,%2,%3};"
        : "+f"(c[0]), "+f"(c[1]), "+f"(c[2]), "+f"(c[3])
        : "r"(a[0]), "r"(a[1]), "r"(a[2]), "r"(a[3]), "r"(b0), "r"(b1));
}

// ---------------------------------------------------------------------------
// Transpose raw input [b][C=64][N=1024] -> act0 [tower*128+b][N][64] (f32)
// ---------------------------------------------------------------------------
__global__ __launch_bounds__(256) void transpose_kernel(
    const float* __restrict__ d1, const float* __restrict__ d2,
    float* __restrict__ act0)
{
    __shared__ float tile[32][33];
    int tb = blockIdx.z;
    int tower = tb / BATCH, b = tb % BATCH;
    const float* src = (tower ? d2 : d1) + (size_t)b * 64 * NNODES;
    float* dst = act0 + (size_t)tb * NNODES * 64;
    int n0 = blockIdx.x * 32, c0 = blockIdx.y * 32;
    for (int i = threadIdx.y; i < 32; i += 8)
        tile[i][threadIdx.x] = src[(size_t)(c0 + i) * NNODES + n0 + threadIdx.x];
    __syncthreads();
    for (int i = threadIdx.y; i < 32; i += 8)
        dst[(size_t)(n0 + i) * 64 + c0 + threadIdx.x] = tile[threadIdx.x][i];
}

// ---------------------------------------------------------------------------
// Build bf16 hi/lo weight images, SW128-swizzled 64x64 tiles.
// ---------------------------------------------------------------------------
__global__ void make_wimg(const float* __restrict__ w,
                          __nv_bfloat16* __restrict__ hi,
                          __nv_bfloat16* __restrict__ lo,
                          int O, int C, int NT)
{
    int i = blockIdx.x * 256 + threadIdx.x;
    if (i >= O * 3 * C) return;
    int tile = i >> 12, e = i & 4095;
    int row = e >> 6, col = e & 63;
    int och = tile / NT, kt = tile % NT;
    int o = och * 64 + row;
    int ck = kt * 64 + col;
    int k = ck / C, c = ck - k * C;
    float x = w[(o * C + c) * 3 + k];
    __nv_bfloat16 h = __float2bfloat16(x);
    __nv_bfloat16 l = __float2bfloat16(x - __bfloat162float(h));
    int boff = row * 128 + col * 2;
    int sw = boff ^ ((boff >> 3) & 0x70);
    hi[((size_t)tile << 12) + (sw >> 1)] = h;
    lo[((size_t)tile << 12) + (sw >> 1)] = l;
}

// ---------------------------------------------------------------------------
// Zero node-0 rows of act1/2/3 (f32)
// ---------------------------------------------------------------------------
__global__ void zero_rows(float* a1, float* a2, float* a3)
{
    int tb = blockIdx.x;
    for (int i = threadIdx.x; i < 256; i += blockDim.x) a1[(size_t)tb * NNODES * 256 + i] = 0.f;
    for (int i = threadIdx.x; i < 128; i += blockDim.x) a2[(size_t)tb * NNODES * 128 + i] = 0.f;
    for (int i = threadIdx.x; i <  64; i += blockDim.x) a3[(size_t)tb * NNODES *  64 + i] = 0.f;
}

// ---------------------------------------------------------------------------
// Optionally apply LN+leakyReLU, then split f32 -> bf16 hi/lo arrays.
// ---------------------------------------------------------------------------
__global__ __launch_bounds__(256) void transform_split(
    const float* __restrict__ act, const float* __restrict__ stats,
    __nv_bfloat16* __restrict__ hi, __nv_bfloat16* __restrict__ lo,
    int O, int ln)
{
    int tb = blockIdx.y;
    float mean = 0.f, inv = 1.f;
    if (ln) { mean = stats[tb * 2]; inv = stats[tb * 2 + 1]; }
    size_t base4 = (size_t)tb * NNODES * O / 4;
    const float4* a = reinterpret_cast<const float4*>(act) + base4;
    int i = blockIdx.x * 256 + threadIdx.x;
    float4 v = a[i];
    if (ln) {
        v.x = (v.x - mean) * inv; v.x = v.x > 0.f ? v.x : 0.01f * v.x;
        v.y = (v.y - mean) * inv; v.y = v.y > 0.f ? v.y : 0.01f * v.y;
        v.z = (v.z - mean) * inv; v.z = v.z > 0.f ? v.z : 0.01f * v.z;
        v.w = (v.w - mean) * inv; v.w = v.w > 0.f ? v.w : 0.01f * v.w;
    }
    uint32_t h01, h23;
    asm("cvt.rn.bf16x2.f32 %0, %1, %2;" : "=r"(h01) : "f"(v.y), "f"(v.x));
    asm("cvt.rn.bf16x2.f32 %0, %1, %2;" : "=r"(h23) : "f"(v.w), "f"(v.z));
    float hx = __uint_as_float(h01 << 16);
    float hy = __uint_as_float(h01 & 0xFFFF0000u);
    float hz = __uint_as_float(h23 << 16);
    float hw = __uint_as_float(h23 & 0xFFFF0000u);
    uint32_t l01, l23;
    asm("cvt.rn.bf16x2.f32 %0, %1, %2;" : "=r"(l01) : "f"(v.y - hy), "f"(v.x - hx));
    asm("cvt.rn.bf16x2.f32 %0, %1, %2;" : "=r"(l23) : "f"(v.w - hw), "f"(v.z - hz));
    u64 hv, lv;
    asm("mov.b64 %0, {%1, %2};" : "=l"(hv) : "r"(h01), "r"(h23));
    asm("mov.b64 %0, {%1, %2};" : "=l"(lv) : "r"(l01), "r"(l23));
    reinterpret_cast<u64*>(hi)[base4 + i] = hv;
    reinterpret_cast<u64*>(lo)[base4 + i] = lv;
}

// ---------------------------------------------------------------------------
// mma.sync gather-conv. Warp tile 64x32, block tile 128 x BN.
// Register fragment DOUBLE BUFFER: ldsm for ks+1 issued before MMAs of ks,
// hiding ldmatrix latency under the 48-MMA stream.
// ---------------------------------------------------------------------------
template<int C, int O, int BN>
__global__ __launch_bounds__(2 * BN, (BN == 64) ? 2 : 1) void conv_mma(
    const __nv_bfloat16* __restrict__ aHiG, const __nv_bfloat16* __restrict__ aLoG,
    const int* __restrict__ idxA, const int* __restrict__ idxB,
    const __nv_bfloat16* __restrict__ whi, const __nv_bfloat16* __restrict__ wlo,
    const float* __restrict__ bias,
    float* __restrict__ actout, float* __restrict__ part)
{
    constexpr int TM = 128;
    constexpr int CK = 3 * C;
    constexpr int KT = 64;
    constexpr int NT = CK / KT;
    constexpr int OCHB = O / BN;
    constexpr int NSUB = BN / 64;
    constexpr int NTH = 2 * BN;
    constexpr int NGC = BN / 32;
    constexpr uint32_t BSTG = (uint32_t)BN * 256u;

    extern __shared__ char dsm_raw[];
    char* dsm = (char*)(((uintptr_t)dsm_raw + 1023) & ~(uintptr_t)1023);
    __shared__ int nodes[TM * 3];
    __shared__ float red[16];

    const int tid = threadIdx.x, lane = tid & 31, warp = tid >> 5;
    const int mg = warp / NGC, ng = warp % NGC;
    const int ochb = blockIdx.x % OCHB;
    const int m0 = (blockIdx.x / OCHB) * TM;
    const int tb = blockIdx.z * BATCH + blockIdx.y;
    const int* idx = (blockIdx.z ? idxB : idxA) + blockIdx.y * T3;

    for (int t = tid; t < TM * 3; t += NTH) {
        int tt = m0 * 3 + t;
        nodes[t] = (tt < T3) ? idx[tt] : 0;
    }
    __syncthreads();

    const uint32_t sb = smem_u32(dsm);
    const __nv_bfloat16* aG[2] = { aHiG + (size_t)tb * NNODES * C,
                                   aLoG + (size_t)tb * NNODES * C };

    auto issue = [&](int kt, int s) {
        const int k = (kt * KT) / C;
        const int cbase = kt * KT - k * C;
        const uint32_t bb = sb + 65536u + (uint32_t)s * BSTG;
#pragma unroll 2
        for (int e = tid; e < NSUB * 1024; e += NTH) {
            int ss = e / (NSUB * 512);
            int e2 = e - ss * NSUB * 512;
            int st = e2 >> 9, q = e2 & 511;
            const __nv_bfloat16* src =
                (ss ? wlo : whi) + (((size_t)((ochb * NSUB + st) * NT + kt)) << 12) + q * 8;
            CP16(bb + (uint32_t)ss * (BN * 128u) + (uint32_t)st * 8192u
                    + (uint32_t)q * 16u, src);
        }
        const uint32_t adst[2] = { sb + (uint32_t)s * 16384u,
                                   sb + 32768u + (uint32_t)s * 16384u };
#pragma unroll 4
        for (int e = tid; e < 2048; e += NTH) {
            int ss = e >> 10, e2 = e & 1023, r = e2 >> 3, q = e2 & 7;
            const __nv_bfloat16* src =
                aG[ss] + (size_t)nodes[r * 3 + k] * C + cbase + q * 8;
            uint32_t off = ((uint32_t)(r * 128 + q * 16)) ^ (((uint32_t)(r & 7)) << 4);
            CP16(adst[ss] + off, src);
        }
        CPCOMMIT();
    };

    float acc[4][4][4];
#pragma unroll
    for (int mi = 0; mi < 4; mi++)
#pragma unroll
        for (int i = 0; i < 4; i++)
#pragma unroll
            for (int j = 0; j < 4; j++) acc[mi][i][j] = 0.f;

    const int arow0 = mg * 64 + (lane & 15);
    const uint32_t aswz = ((uint32_t)(arow0 & 7)) << 4;
    const uint32_t akh = ((lane >> 4) & 1) * 16;
    const int brow_in = lane & 7;
    const int bps = (lane >> 4) & 1;
    const uint32_t bkh = ((lane >> 3) & 1) * 16;
    const uint32_t bswz = ((uint32_t)brow_in) << 4;

    // fragment double buffers
    uint32_t Ah[2][4][4], Al[2][4][4], Bh[2][2][4], Bl[2][2][4];

    issue(0, 0);
    for (int kt = 0; kt < NT; kt++) {
        if (kt + 1 < NT) {
            issue(kt + 1, (kt + 1) & 1);
            asm volatile("cp.async.wait_group 1;" ::: "memory");
        } else {
            asm volatile("cp.async.wait_group 0;" ::: "memory");
        }
        __syncthreads();
        const int s = kt & 1;
        const uint32_t ahb = sb + (uint32_t)s * 16384u;
        const uint32_t bhb = sb + 65536u + (uint32_t)s * BSTG;

        // prologue: fragments for ks=0
        {
            const uint32_t akb = akh;
#pragma unroll
            for (int mi = 0; mi < 4; mi++) {
                uint32_t aoff = (uint32_t)(arow0 + mi * 16) * 128u + (akb ^ aswz);
                ldsm4(Ah[0][mi], ahb + aoff);
                ldsm4(Al[0][mi], ahb + 32768u + aoff);
            }
            const uint32_t bkb = bkh;
#pragma unroll
            for (int p2 = 0; p2 < 2; p2++) {
                int r = ng * 32 + p2 * 16 + bps * 8 + brow_in;
                uint32_t boff = (uint32_t)(r >> 6) * 8192u
                              + (uint32_t)(r & 63) * 128u + (bkb ^ bswz);
                ldsm4(Bh[0][p2], bhb + boff);
                ldsm4(Bl[0][p2], bhb + (uint32_t)(BN * 128u) + boff);
            }
        }
#pragma unroll
        for (int ks = 0; ks < 4; ks++) {
            const int cur = ks & 1, nxt = cur ^ 1;
            if (ks < 3) {
                // prefetch fragments for ks+1 BEFORE the MMA burst
                const uint32_t akb = (uint32_t)((ks + 1) * 32) + akh;
#pragma unroll
                for (int mi = 0; mi < 4; mi++) {
                    uint32_t aoff = (uint32_t)(arow0 + mi * 16) * 128u + (akb ^ aswz);
                    ldsm4(Ah[nxt][mi], ahb + aoff);
                    ldsm4(Al[nxt][mi], ahb + 32768u + aoff);
                }
                const uint32_t bkb = (uint32_t)((ks + 1) * 32) + bkh;
#pragma unroll
                for (int p2 = 0; p2 < 2; p2++) {
                    int r = ng * 32 + p2 * 16 + bps * 8 + brow_in;
                    uint32_t boff = (uint32_t)(r >> 6) * 8192u
                                  + (uint32_t)(r & 63) * 128u + (bkb ^ bswz);
                    ldsm4(Bh[nxt][p2], bhb + boff);
                    ldsm4(Bl[nxt][p2], bhb + (uint32_t)(BN * 128u) + boff);
                }
            }
            // 48 MMAs on current fragments (term-major)
#pragma unroll
            for (int mi = 0; mi < 4; mi++)
#pragma unroll
                for (int p2 = 0; p2 < 2; p2++) {
                    mma_bf16(acc[mi][p2 * 2],     Ah[cur][mi], Bh[cur][p2][0], Bh[cur][p2][1]);
                    mma_bf16(acc[mi][p2 * 2 + 1], Ah[cur][mi], Bh[cur][p2][2], Bh[cur][p2][3]);
                }
#pragma unroll
            for (int mi = 0; mi < 4; mi++)
#pragma unroll
                for (int p2 = 0; p2 < 2; p2++) {
                    mma_bf16(acc[mi][p2 * 2],     Ah[cur][mi], Bl[cur][p2][0], Bl[cur][p2][1]);
                    mma_bf16(acc[mi][p2 * 2 + 1], Ah[cur][mi], Bl[cur][p2][2], Bl[cur][p2][3]);
                }
#pragma unroll
            for (int mi = 0; mi < 4; mi++)
#pragma unroll
                for (int p2 = 0; p2 < 2; p2++) {
                    mma_bf16(acc[mi][p2 * 2],     Al[cur][mi], Bh[cur][p2][0], Bh[cur][p2][1]);
                    mma_bf16(acc[mi][p2 * 2 + 1], Al[cur][mi], Bh[cur][p2][2], Bh[cur][p2][3]);
                }
        }
        __syncthreads();
    }

    // Epilogue: D fragments -> gmem (float2) + fused stats
    float ls = 0.f, lss = 0.f;
    float* aout = actout + (size_t)tb * NNODES * O;
#pragma unroll
    for (int mi = 0; mi < 4; mi++) {
        const int r0 = m0 + mg * 64 + mi * 16 + (lane >> 2);
#pragma unroll
        for (int nt = 0; nt < 4; nt++) {
            int col = ochb * BN + ng * 32 + nt * 8 + 2 * (lane & 3);
            float2 bv = *reinterpret_cast<const float2*>(bias + col);
            if (r0 < NTRI) {
                float2 v;
                v.x = acc[mi][nt][0] + bv.x; v.y = acc[mi][nt][1] + bv.y;
                *reinterpret_cast<float2*>(aout + (size_t)(r0 + 1) * O + col) = v;
                ls += v.x + v.y;
                lss = fmaf(v.x, v.x, lss); lss = fmaf(v.y, v.y, lss);
            }
            if (r0 + 8 < NTRI) {
                float2 v;
                v.x = acc[mi][nt][2] + bv.x; v.y = acc[mi][nt][3] + bv.y;
                *reinterpret_cast<float2*>(aout + (size_t)(r0 + 9) * O + col) = v;
                ls += v.x + v.y;
                lss = fmaf(v.x, v.x, lss); lss = fmaf(v.y, v.y, lss);
            }
        }
    }
#pragma unroll
    for (int off = 16; off > 0; off >>= 1) {
        ls  += __shfl_xor_sync(0xffffffffu, ls,  off);
        lss += __shfl_xor_sync(0xffffffffu, lss, off);
    }
    if (lane == 0) { red[warp] = ls; red[8 + warp] = lss; }
    __syncthreads();
    if (tid == 0) {
        float s = 0.f, ss = 0.f;
#pragma unroll
        for (int wv = 0; wv < NTH / 32; wv++) { s += red[wv]; ss += red[8 + wv]; }
        float* pp = part + ((size_t)tb * 32 + blockIdx.x) * 2;
        pp[0] = s; pp[1] = ss;
    }
}

// ---------------------------------------------------------------------------
// Finalize stats: reduce nparts partials per (tower,b)
// ---------------------------------------------------------------------------
__global__ __launch_bounds__(256) void finalize_stats(
    const float* __restrict__ part, float* __restrict__ stats, int O, int nparts)
{
    int tb = threadIdx.x;
    double s = 0.0, ss = 0.0;
    for (int i = 0; i < nparts; i++) {
        s += (double)part[((size_t)tb * 32 + i) * 2];
        ss += (double)part[((size_t)tb * 32 + i) * 2 + 1];
    }
    double n = 1024.0 * O;
    double mean = s / n;
    double var = (ss - s * s / n) / (n - 1.0);
    if (var < 0.0) var = 0.0;
    stats[tb * 2] = (float)mean;
    stats[tb * 2 + 1] = (float)(1.0 / (sqrt(var) + 1e-5));
}

// ---------------------------------------------------------------------------
// Final head: LN(act3) -> max-pool -> FC1(lrelu) -> FC2 -> sigmoid(diff)
// ---------------------------------------------------------------------------
__global__ __launch_bounds__(256) void final_kernel(
    const float* __restrict__ act3, const float* __restrict__ stats3,
    const float* __restrict__ wfc1, const float* __restrict__ bfc1,
    const float* __restrict__ wfc2, const float* __restrict__ bfc2,
    float* __restrict__ out)
{
    int b = blockIdx.x;
    int tid = threadIdx.x;
    __shared__ float mx[4][64];
    __shared__ float h[32];
    __shared__ float yy[2];

    for (int tower = 0; tower < 2; tower++) {
        int tb = tower * BATCH + b;
        float mean = stats3[tb * 2], inv = stats3[tb * 2 + 1];
        const float* a = act3 + (size_t)tb * NNODES * 64;
        int c = tid & 63, grp = tid >> 6;
        float m = -1e30f;
        for (int n = grp; n < NNODES; n += 4) {
            float v = (a[(size_t)n * 64 + c] - mean) * inv;
            m = fmaxf(m, v);
        }
        mx[grp][c] = m;
        __syncthreads();
        if (tid < 64) {
            mx[0][tid] = fmaxf(fmaxf(mx[0][tid], mx[1][tid]),
                               fmaxf(mx[2][tid], mx[3][tid]));
        }
        __syncthreads();
        if (tid < 32) {
            float sAcc = bfc1[tid];
            for (int c2 = 0; c2 < 64; c2++) sAcc = fmaf(mx[0][c2], wfc1[tid * 64 + c2], sAcc);
            h[tid] = sAcc > 0.f ? sAcc : 0.01f * sAcc;
        }
        __syncthreads();
        if (tid == 0) {
            float sAcc = bfc2[0];
            for (int i = 0; i < 32; i++) sAcc = fmaf(h[i], wfc2[i], sAcc);
            yy[tower] = sAcc;
        }
        __syncthreads();
    }
    if (tid == 0) {
        float d = yy[0] - yy[1];
        out[b] = 1.f / (1.f + expf(-d));
    }
}

// ---------------------------------------------------------------------------
extern "C" void kernel_launch(void* const* d_in, const int* in_sizes, int n_in,
                              void* d_out, int out_size)
{
    const float* data1 = (const float*)d_in[0];
    const int*   idx1  = (const int*)d_in[1];
    const float* data2 = (const float*)d_in[2];
    const int*   idx2  = (const int*)d_in[3];
    const float* w1 = (const float*)d_in[4];
    const float* b1 = (const float*)d_in[5];
    const float* w2 = (const float*)d_in[6];
    const float* b2 = (const float*)d_in[7];
    const float* w3 = (const float*)d_in[8];
    const float* b3 = (const float*)d_in[9];
    const float* wfc1 = (const float*)d_in[10];
    const float* bfc1 = (const float*)d_in[11];
    const float* wfc2 = (const float*)d_in[12];
    const float* bfc2 = (const float*)d_in[13];
    float* out = (float*)d_out;

    float *act0, *act1, *act2, *act3, *part, *st1, *st2, *st3;
    __nv_bfloat16 *a0h, *a0l, *a1h, *a1l, *a2h, *a2l;
    __nv_bfloat16 *whi1, *wlo1, *whi2, *wlo2, *whi3, *wlo3;
    cudaGetSymbolAddress((void**)&act0, g_act0);
    cudaGetSymbolAddress((void**)&act1, g_act1);
    cudaGetSymbolAddress((void**)&act2, g_act2);
    cudaGetSymbolAddress((void**)&act3, g_act3);
    cudaGetSymbolAddress((void**)&a0h, g_a0h);
    cudaGetSymbolAddress((void**)&a0l, g_a0l);
    cudaGetSymbolAddress((void**)&a1h, g_a1h);
    cudaGetSymbolAddress((void**)&a1l, g_a1l);
    cudaGetSymbolAddress((void**)&a2h, g_a2h);
    cudaGetSymbolAddress((void**)&a2l, g_a2l);
    cudaGetSymbolAddress((void**)&whi1, g_whi1);
    cudaGetSymbolAddress((void**)&wlo1, g_wlo1);
    cudaGetSymbolAddress((void**)&whi2, g_whi2);
    cudaGetSymbolAddress((void**)&wlo2, g_wlo2);
    cudaGetSymbolAddress((void**)&whi3, g_whi3);
    cudaGetSymbolAddress((void**)&wlo3, g_wlo3);
    cudaGetSymbolAddress((void**)&part, g_part);
    cudaGetSymbolAddress((void**)&st1, g_st1);
    cudaGetSymbolAddress((void**)&st2, g_st2);
    cudaGetSymbolAddress((void**)&st3, g_st3);

    const int smem128 = 1024 + 65536 + 2 * 128 * 256;  // 132096
    const int smem64  = 1024 + 65536 + 2 * 64 * 256;   //  99328
    cudaFuncSetAttribute(conv_mma<64, 256, 128>,
                         cudaFuncAttributeMaxDynamicSharedMemorySize, smem128);
    cudaFuncSetAttribute(conv_mma<256, 128, 128>,
                         cudaFuncAttributeMaxDynamicSharedMemorySize, smem128);
    cudaFuncSetAttribute(conv_mma<128, 64, 64>,
                         cudaFuncAttributeMaxDynamicSharedMemorySize, smem64);

    // Launch order: conv1 is the 4th launch (ncu capture slot).
    transpose_kernel<<<dim3(32, 2, 256), dim3(32, 8)>>>(data1, data2, act0);
    make_wimg<<<(256 * 192 + 255) / 256, 256>>>(w1, whi1, wlo1, 256, 64, 3);
    transform_split<<<dim3(NNODES * 64 / 4 / 256, 256), 256>>>(
        act0, st1, a0h, a0l, 64, 0);

    conv_mma<64, 256, 128><<<dim3(16, BATCH, 2), 256, smem128>>>(
        a0h, a0l, idx1, idx2, whi1, wlo1, b1, act1, part);
    zero_rows<<<256, 256>>>(act1, act2, act3);
    finalize_stats<<<1, 256>>>(part, st1, 256, 16);
    transform_split<<<dim3(NNODES * 256 / 4 / 256, 256), 256>>>(
        act1, st1, a1h, a1l, 256, 1);
    make_wimg<<<(128 * 768 + 255) / 256, 256>>>(w2, whi2, wlo2, 128, 256, 12);

    conv_mma<256, 128, 128><<<dim3(8, BATCH, 2), 256, smem128>>>(
        a1h, a1l, idx1, idx2, whi2, wlo2, b2, act2, part);
    finalize_stats<<<1, 256>>>(part, st2, 128, 8);
    transform_split<<<dim3(NNODES * 128 / 4 / 256, 256), 256>>>(
        act2, st2, a2h, a2l, 128, 1);
    make_wimg<<<(64 * 384 + 255) / 256, 256>>>(w3, whi3, wlo3, 64, 128, 6);

    conv_mma<128, 64, 64><<<dim3(8, BATCH, 2), 128, smem64>>>(
        a2h, a2l, idx1, idx2, whi3, wlo3, b3, act3, part);
    finalize_stats<<<1, 256>>>(part, st3, 64, 8);

    final_kernel<<<BATCH, 256>>>(act3, st3, wfc1, bfc1, wfc2, bfc2, out);
}

// round 14
// speedup vs baseline: 6.3194x; 1.5241x over previous
#include <cuda_runtime.h>
#include <cuda_bf16.h>
#include <math.h>
#include <stdint.h>

#define BATCH 128
#define NNODES 1024
#define NTRI 1023
#define T3 3069

typedef unsigned long long u64;

// f32 activations (conv outputs; node-major [tower*128+b][node][C])
__device__ float g_act0[(size_t)2*BATCH*NNODES*64];
__device__ float g_act1[(size_t)2*BATCH*NNODES*256];
__device__ float g_act2[(size_t)2*BATCH*NNODES*128];
__device__ float g_act3[(size_t)2*BATCH*NNODES*64];
// bf16 activations (conv inputs; hi only — 2-term split)
__device__ __nv_bfloat16 g_a0h[(size_t)2*BATCH*NNODES*64];
__device__ __nv_bfloat16 g_a1h[(size_t)2*BATCH*NNODES*256];
__device__ __nv_bfloat16 g_a2h[(size_t)2*BATCH*NNODES*128];
// Weight images: bf16 hi/lo, per (och64,kt) 64x64 SW128-swizzled tiles
__device__ __nv_bfloat16 g_whi1[4*3*4096],  g_wlo1[4*3*4096];   // O=256,CK=192
__device__ __nv_bfloat16 g_whi2[2*12*4096], g_wlo2[2*12*4096];  // O=128,CK=768
__device__ __nv_bfloat16 g_whi3[1*6*4096],  g_wlo3[1*6*4096];   // O=64, CK=384
__device__ float g_part[2*BATCH*32*2];
__device__ float g_st1[2*BATCH*2];
__device__ float g_st2[2*BATCH*2];
__device__ float g_st3[2*BATCH*2];

// ---- helpers ----------------------------------------------------------------
__device__ __forceinline__ uint32_t smem_u32(const void* p) {
    uint32_t a;
    asm("{ .reg .u64 t; cvta.to.shared.u64 t, %1; cvt.u32.u64 %0, t; }"
        : "=r"(a) : "l"(p));
    return a;
}
#define CP16(dst, src) \
    asm volatile("cp.async.cg.shared.global [%0], [%1], 16;" :: "r"(dst), "l"(src))
#define CPCOMMIT() asm volatile("cp.async.commit_group;" ::: "memory")

__device__ __forceinline__ void ldsm4(uint32_t* r, uint32_t addr) {
    asm volatile("ldmatrix.sync.aligned.m8n8.x4.shared.b16 {%0,%1,%2,%3}, [%4];"
        : "=r"(r[0]), "=r"(r[1]), "=r"(r[2]), "=r"(r[3]) : "r"(addr));
}
__device__ __forceinline__ void mma_bf16(float* c, const uint32_t* a,
                                         uint32_t b0, uint32_t b1) {
    asm volatile(
        "mma.sync.aligned.m16n8k16.row.col.f32.bf16.bf16.f32 "
        "{%0,%1,%2,%3}, {%4,%5,%6,%7}, {%8,%9}, {%0,%1,%2,%3};"
        : "+f"(c[0]), "+f"(c[1]), "+f"(c[2]), "+f"(c[3])
        : "r"(a[0]), "r"(a[1]), "r"(a[2]), "r"(a[3]), "r"(b0), "r"(b1));
}

// ---------------------------------------------------------------------------
// Transpose raw input [b][C=64][N=1024] -> act0 [tower*128+b][N][64] (f32)
// ---------------------------------------------------------------------------
__global__ __launch_bounds__(256) void transpose_kernel(
    const float* __restrict__ d1, const float* __restrict__ d2,
    float* __restrict__ act0)
{
    __shared__ float tile[32][33];
    int tb = blockIdx.z;
    int tower = tb / BATCH, b = tb % BATCH;
    const float* src = (tower ? d2 : d1) + (size_t)b * 64 * NNODES;
    float* dst = act0 + (size_t)tb * NNODES * 64;
    int n0 = blockIdx.x * 32, c0 = blockIdx.y * 32;
    for (int i = threadIdx.y; i < 32; i += 8)
        tile[i][threadIdx.x] = src[(size_t)(c0 + i) * NNODES + n0 + threadIdx.x];
    __syncthreads();
    for (int i = threadIdx.y; i < 32; i += 8)
        dst[(size_t)(n0 + i) * 64 + c0 + threadIdx.x] = tile[threadIdx.x][i];
}

// ---------------------------------------------------------------------------
// Build bf16 hi/lo weight images, SW128-swizzled 64x64 tiles.
// ---------------------------------------------------------------------------
__global__ void make_wimg(const float* __restrict__ w,
                          __nv_bfloat16* __restrict__ hi,
                          __nv_bfloat16* __restrict__ lo,
                          int O, int C, int NT)
{
    int i = blockIdx.x * 256 + threadIdx.x;
    if (i >= O * 3 * C) return;
    int tile = i >> 12, e = i & 4095;
    int row = e >> 6, col = e & 63;
    int och = tile / NT, kt = tile % NT;
    int o = och * 64 + row;
    int ck = kt * 64 + col;
    int k = ck / C, c = ck - k * C;
    float x = w[(o * C + c) * 3 + k];
    __nv_bfloat16 h = __float2bfloat16(x);
    __nv_bfloat16 l = __float2bfloat16(x - __bfloat162float(h));
    int boff = row * 128 + col * 2;
    int sw = boff ^ ((boff >> 3) & 0x70);
    hi[((size_t)tile << 12) + (sw >> 1)] = h;
    lo[((size_t)tile << 12) + (sw >> 1)] = l;
}

// ---------------------------------------------------------------------------
// Zero node-0 rows of act1/2/3 (f32)
// ---------------------------------------------------------------------------
__global__ void zero_rows(float* a1, float* a2, float* a3)
{
    int tb = blockIdx.x;
    for (int i = threadIdx.x; i < 256; i += blockDim.x) a1[(size_t)tb * NNODES * 256 + i] = 0.f;
    for (int i = threadIdx.x; i < 128; i += blockDim.x) a2[(size_t)tb * NNODES * 128 + i] = 0.f;
    for (int i = threadIdx.x; i <  64; i += blockDim.x) a3[(size_t)tb * NNODES *  64 + i] = 0.f;
}

// ---------------------------------------------------------------------------
// Optionally apply LN+leakyReLU, then convert f32 -> bf16 (hi only).
// ---------------------------------------------------------------------------
__global__ __launch_bounds__(256) void transform_split(
    const float* __restrict__ act, const float* __restrict__ stats,
    __nv_bfloat16* __restrict__ hi, int O, int ln)
{
    int tb = blockIdx.y;
    float mean = 0.f, inv = 1.f;
    if (ln) { mean = stats[tb * 2]; inv = stats[tb * 2 + 1]; }
    size_t base4 = (size_t)tb * NNODES * O / 4;
    const float4* a = reinterpret_cast<const float4*>(act) + base4;
    int i = blockIdx.x * 256 + threadIdx.x;
    float4 v = a[i];
    if (ln) {
        v.x = (v.x - mean) * inv; v.x = v.x > 0.f ? v.x : 0.01f * v.x;
        v.y = (v.y - mean) * inv; v.y = v.y > 0.f ? v.y : 0.01f * v.y;
        v.z = (v.z - mean) * inv; v.z = v.z > 0.f ? v.z : 0.01f * v.z;
        v.w = (v.w - mean) * inv; v.w = v.w > 0.f ? v.w : 0.01f * v.w;
    }
    uint32_t h01, h23;
    asm("cvt.rn.bf16x2.f32 %0, %1, %2;" : "=r"(h01) : "f"(v.y), "f"(v.x));
    asm("cvt.rn.bf16x2.f32 %0, %1, %2;" : "=r"(h23) : "f"(v.w), "f"(v.z));
    u64 hv;
    asm("mov.b64 %0, {%1, %2};" : "=l"(hv) : "r"(h01), "r"(h23));
    reinterpret_cast<u64*>(hi)[base4 + i] = hv;
}

// ---------------------------------------------------------------------------
// mma.sync gather-conv, 2-term split: D = Ah*Bh + Ah*Bl (weights hi+lo,
// activations bf16). Warp tile 64x32, block tile 128 x BN, 2 blocks/SM.
// ---------------------------------------------------------------------------
template<int C, int O, int BN>
__global__ __launch_bounds__(2 * BN, 2) void conv_mma(
    const __nv_bfloat16* __restrict__ aHiG,
    const int* __restrict__ idxA, const int* __restrict__ idxB,
    const __nv_bfloat16* __restrict__ whi, const __nv_bfloat16* __restrict__ wlo,
    const float* __restrict__ bias,
    float* __restrict__ actout, float* __restrict__ part)
{
    constexpr int TM = 128;
    constexpr int CK = 3 * C;
    constexpr int KT = 64;
    constexpr int NT = CK / KT;
    constexpr int OCHB = O / BN;
    constexpr int NSUB = BN / 64;
    constexpr int NTH = 2 * BN;
    constexpr int NGC = BN / 32;
    constexpr uint32_t BSTG = (uint32_t)BN * 256u;  // hi + lo

    extern __shared__ char dsm_raw[];
    char* dsm = (char*)(((uintptr_t)dsm_raw + 1023) & ~(uintptr_t)1023);
    __shared__ int nodes[TM * 3];
    __shared__ float red[16];

    const int tid = threadIdx.x, lane = tid & 31, warp = tid >> 5;
    const int mg = warp / NGC, ng = warp % NGC;
    const int ochb = blockIdx.x % OCHB;
    const int m0 = (blockIdx.x / OCHB) * TM;
    const int tb = blockIdx.z * BATCH + blockIdx.y;
    const int* idx = (blockIdx.z ? idxB : idxA) + blockIdx.y * T3;

    for (int t = tid; t < TM * 3; t += NTH) {
        int tt = m0 * 3 + t;
        nodes[t] = (tt < T3) ? idx[tt] : 0;
    }
    __syncthreads();

    const uint32_t sb = smem_u32(dsm);
    // layout: A hi 2 stages @ [0, 32768); B stages @ 32768 (BSTG each)
    const __nv_bfloat16* aG = aHiG + (size_t)tb * NNODES * C;

    auto issue = [&](int kt, int s) {
        const int k = (kt * KT) / C;
        const int cbase = kt * KT - k * C;
        const uint32_t bb = sb + 32768u + (uint32_t)s * BSTG;
#pragma unroll 2
        for (int e = tid; e < NSUB * 1024; e += NTH) {
            int ss = e / (NSUB * 512);             // 0=hi, 1=lo
            int e2 = e - ss * NSUB * 512;
            int st = e2 >> 9, q = e2 & 511;
            const __nv_bfloat16* src =
                (ss ? wlo : whi) + (((size_t)((ochb * NSUB + st) * NT + kt)) << 12) + q * 8;
            CP16(bb + (uint32_t)ss * (BN * 128u) + (uint32_t)st * 8192u
                    + (uint32_t)q * 16u, src);
        }
        const uint32_t adst = sb + (uint32_t)s * 16384u;
#pragma unroll 4
        for (int e = tid; e < 1024; e += NTH) {
            int r = e >> 3, q = e & 7;
            const __nv_bfloat16* src =
                aG + (size_t)nodes[r * 3 + k] * C + cbase + q * 8;
            uint32_t off = ((uint32_t)(r * 128 + q * 16)) ^ (((uint32_t)(r & 7)) << 4);
            CP16(adst + off, src);
        }
        CPCOMMIT();
    };

    float acc[4][4][4];
#pragma unroll
    for (int mi = 0; mi < 4; mi++)
#pragma unroll
        for (int i = 0; i < 4; i++)
#pragma unroll
            for (int j = 0; j < 4; j++) acc[mi][i][j] = 0.f;

    const int arow0 = mg * 64 + (lane & 15);
    const uint32_t aswz = ((uint32_t)(arow0 & 7)) << 4;
    const uint32_t akh = ((lane >> 4) & 1) * 16;
    const int brow_in = lane & 7;
    const int bps = (lane >> 4) & 1;
    const uint32_t bkh = ((lane >> 3) & 1) * 16;
    const uint32_t bswz = ((uint32_t)brow_in) << 4;

    issue(0, 0);
    for (int kt = 0; kt < NT; kt++) {
        if (kt + 1 < NT) {
            issue(kt + 1, (kt + 1) & 1);
            asm volatile("cp.async.wait_group 1;" ::: "memory");
        } else {
            asm volatile("cp.async.wait_group 0;" ::: "memory");
        }
        __syncthreads();
        const int s = kt & 1;
        const uint32_t ahb = sb + (uint32_t)s * 16384u;
        const uint32_t bhb = sb + 32768u + (uint32_t)s * BSTG;
#pragma unroll
        for (int ks = 0; ks < 4; ks++) {
            const uint32_t akb = (uint32_t)(ks * 32) + akh;
            uint32_t Ah[4][4];
#pragma unroll
            for (int mi = 0; mi < 4; mi++) {
                uint32_t aoff = (uint32_t)(arow0 + mi * 16) * 128u + (akb ^ aswz);
                ldsm4(Ah[mi], ahb + aoff);
            }
            const uint32_t bkb = (uint32_t)(ks * 32) + bkh;
            uint32_t Bh[2][4], Bl[2][4];
#pragma unroll
            for (int p2 = 0; p2 < 2; p2++) {
                int r = ng * 32 + p2 * 16 + bps * 8 + brow_in;
                uint32_t boff = (uint32_t)(r >> 6) * 8192u
                              + (uint32_t)(r & 63) * 128u + (bkb ^ bswz);
                ldsm4(Bh[p2], bhb + boff);
                ldsm4(Bl[p2], bhb + (uint32_t)(BN * 128u) + boff);
            }
            // 32 MMAs: term-major (Bh pass, then Bl pass)
#pragma unroll
            for (int mi = 0; mi < 4; mi++)
#pragma unroll
                for (int p2 = 0; p2 < 2; p2++) {
                    mma_bf16(acc[mi][p2 * 2],     Ah[mi], Bh[p2][0], Bh[p2][1]);
                    mma_bf16(acc[mi][p2 * 2 + 1], Ah[mi], Bh[p2][2], Bh[p2][3]);
                }
#pragma unroll
            for (int mi = 0; mi < 4; mi++)
#pragma unroll
                for (int p2 = 0; p2 < 2; p2++) {
                    mma_bf16(acc[mi][p2 * 2],     Ah[mi], Bl[p2][0], Bl[p2][1]);
                    mma_bf16(acc[mi][p2 * 2 + 1], Ah[mi], Bl[p2][2], Bl[p2][3]);
                }
        }
        __syncthreads();
    }

    // Epilogue: D fragments -> gmem (float2) + fused stats
    float ls = 0.f, lss = 0.f;
    float* aout = actout + (size_t)tb * NNODES * O;
#pragma unroll
    for (int mi = 0; mi < 4; mi++) {
        const int r0 = m0 + mg * 64 + mi * 16 + (lane >> 2);
#pragma unroll
        for (int nt = 0; nt < 4; nt++) {
            int col = ochb * BN + ng * 32 + nt * 8 + 2 * (lane & 3);
            float2 bv = *reinterpret_cast<const float2*>(bias + col);
            if (r0 < NTRI) {
                float2 v;
                v.x = acc[mi][nt][0] + bv.x; v.y = acc[mi][nt][1] + bv.y;
                *reinterpret_cast<float2*>(aout + (size_t)(r0 + 1) * O + col) = v;
                ls += v.x + v.y;
                lss = fmaf(v.x, v.x, lss); lss = fmaf(v.y, v.y, lss);
            }
            if (r0 + 8 < NTRI) {
                float2 v;
                v.x = acc[mi][nt][2] + bv.x; v.y = acc[mi][nt][3] + bv.y;
                *reinterpret_cast<float2*>(aout + (size_t)(r0 + 9) * O + col) = v;
                ls += v.x + v.y;
                lss = fmaf(v.x, v.x, lss); lss = fmaf(v.y, v.y, lss);
            }
        }
    }
#pragma unroll
    for (int off = 16; off > 0; off >>= 1) {
        ls  += __shfl_xor_sync(0xffffffffu, ls,  off);
        lss += __shfl_xor_sync(0xffffffffu, lss, off);
    }
    if (lane == 0) { red[warp] = ls; red[8 + warp] = lss; }
    __syncthreads();
    if (tid == 0) {
        float s = 0.f, ss = 0.f;
#pragma unroll
        for (int wv = 0; wv < NTH / 32; wv++) { s += red[wv]; ss += red[8 + wv]; }
        float* pp = part + ((size_t)tb * 32 + blockIdx.x) * 2;
        pp[0] = s; pp[1] = ss;
    }
}

// ---------------------------------------------------------------------------
// Finalize stats: reduce nparts partials per (tower,b)
// ---------------------------------------------------------------------------
__global__ __launch_bounds__(256) void finalize_stats(
    const float* __restrict__ part, float* __restrict__ stats, int O, int nparts)
{
    int tb = threadIdx.x;
    double s = 0.0, ss = 0.0;
    for (int i = 0; i < nparts; i++) {
        s += (double)part[((size_t)tb * 32 + i) * 2];
        ss += (double)part[((size_t)tb * 32 + i) * 2 + 1];
    }
    double n = 1024.0 * O;
    double mean = s / n;
    double var = (ss - s * s / n) / (n - 1.0);
    if (var < 0.0) var = 0.0;
    stats[tb * 2] = (float)mean;
    stats[tb * 2 + 1] = (float)(1.0 / (sqrt(var) + 1e-5));
}

// ---------------------------------------------------------------------------
// Final head: LN(act3) -> max-pool -> FC1(lrelu) -> FC2 -> sigmoid(diff)
// ---------------------------------------------------------------------------
__global__ __launch_bounds__(256) void final_kernel(
    const float* __restrict__ act3, const float* __restrict__ stats3,
    const float* __restrict__ wfc1, const float* __restrict__ bfc1,
    const float* __restrict__ wfc2, const float* __restrict__ bfc2,
    float* __restrict__ out)
{
    int b = blockIdx.x;
    int tid = threadIdx.x;
    __shared__ float mx[4][64];
    __shared__ float h[32];
    __shared__ float yy[2];

    for (int tower = 0; tower < 2; tower++) {
        int tb = tower * BATCH + b;
        float mean = stats3[tb * 2], inv = stats3[tb * 2 + 1];
        const float* a = act3 + (size_t)tb * NNODES * 64;
        int c = tid & 63, grp = tid >> 6;
        float m = -1e30f;
        for (int n = grp; n < NNODES; n += 4) {
            float v = (a[(size_t)n * 64 + c] - mean) * inv;
            m = fmaxf(m, v);
        }
        mx[grp][c] = m;
        __syncthreads();
        if (tid < 64) {
            mx[0][tid] = fmaxf(fmaxf(mx[0][tid], mx[1][tid]),
                               fmaxf(mx[2][tid], mx[3][tid]));
        }
        __syncthreads();
        if (tid < 32) {
            float sAcc = bfc1[tid];
            for (int c2 = 0; c2 < 64; c2++) sAcc = fmaf(mx[0][c2], wfc1[tid * 64 + c2], sAcc);
            h[tid] = sAcc > 0.f ? sAcc : 0.01f * sAcc;
        }
        __syncthreads();
        if (tid == 0) {
            float sAcc = bfc2[0];
            for (int i = 0; i < 32; i++) sAcc = fmaf(h[i], wfc2[i], sAcc);
            yy[tower] = sAcc;
        }
        __syncthreads();
    }
    if (tid == 0) {
        float d = yy[0] - yy[1];
        out[b] = 1.f / (1.f + expf(-d));
    }
}

// ---------------------------------------------------------------------------
extern "C" void kernel_launch(void* const* d_in, const int* in_sizes, int n_in,
                              void* d_out, int out_size)
{
    const float* data1 = (const float*)d_in[0];
    const int*   idx1  = (const int*)d_in[1];
    const float* data2 = (const float*)d_in[2];
    const int*   idx2  = (const int*)d_in[3];
    const float* w1 = (const float*)d_in[4];
    const float* b1 = (const float*)d_in[5];
    const float* w2 = (const float*)d_in[6];
    const float* b2 = (const float*)d_in[7];
    const float* w3 = (const float*)d_in[8];
    const float* b3 = (const float*)d_in[9];
    const float* wfc1 = (const float*)d_in[10];
    const float* bfc1 = (const float*)d_in[11];
    const float* wfc2 = (const float*)d_in[12];
    const float* bfc2 = (const float*)d_in[13];
    float* out = (float*)d_out;

    float *act0, *act1, *act2, *act3, *part, *st1, *st2, *st3;
    __nv_bfloat16 *a0h, *a1h, *a2h;
    __nv_bfloat16 *whi1, *wlo1, *whi2, *wlo2, *whi3, *wlo3;
    cudaGetSymbolAddress((void**)&act0, g_act0);
    cudaGetSymbolAddress((void**)&act1, g_act1);
    cudaGetSymbolAddress((void**)&act2, g_act2);
    cudaGetSymbolAddress((void**)&act3, g_act3);
    cudaGetSymbolAddress((void**)&a0h, g_a0h);
    cudaGetSymbolAddress((void**)&a1h, g_a1h);
    cudaGetSymbolAddress((void**)&a2h, g_a2h);
    cudaGetSymbolAddress((void**)&whi1, g_whi1);
    cudaGetSymbolAddress((void**)&wlo1, g_wlo1);
    cudaGetSymbolAddress((void**)&whi2, g_whi2);
    cudaGetSymbolAddress((void**)&wlo2, g_wlo2);
    cudaGetSymbolAddress((void**)&whi3, g_whi3);
    cudaGetSymbolAddress((void**)&wlo3, g_wlo3);
    cudaGetSymbolAddress((void**)&part, g_part);
    cudaGetSymbolAddress((void**)&st1, g_st1);
    cudaGetSymbolAddress((void**)&st2, g_st2);
    cudaGetSymbolAddress((void**)&st3, g_st3);

    // dyn smem: align 1024 + A hi 2x16KB + B 2 stages * (BN*256)
    const int smem128 = 1024 + 32768 + 2 * 128 * 256;  // 99328
    const int smem64  = 1024 + 32768 + 2 * 64 * 256;   // 66560
    cudaFuncSetAttribute(conv_mma<64, 256, 128>,
                         cudaFuncAttributeMaxDynamicSharedMemorySize, smem128);
    cudaFuncSetAttribute(conv_mma<256, 128, 128>,
                         cudaFuncAttributeMaxDynamicSharedMemorySize, smem128);
    cudaFuncSetAttribute(conv_mma<128, 64, 64>,
                         cudaFuncAttributeMaxDynamicSharedMemorySize, smem64);

    // Launch order: conv1 is the 4th launch (ncu capture slot).
    transpose_kernel<<<dim3(32, 2, 256), dim3(32, 8)>>>(data1, data2, act0);
    make_wimg<<<(256 * 192 + 255) / 256, 256>>>(w1, whi1, wlo1, 256, 64, 3);
    transform_split<<<dim3(NNODES * 64 / 4 / 256, 256), 256>>>(
        act0, st1, a0h, 64, 0);

    conv_mma<64, 256, 128><<<dim3(16, BATCH, 2), 256, smem128>>>(
        a0h, idx1, idx2, whi1, wlo1, b1, act1, part);
    zero_rows<<<256, 256>>>(act1, act2, act3);
    finalize_stats<<<1, 256>>>(part, st1, 256, 16);
    transform_split<<<dim3(NNODES * 256 / 4 / 256, 256), 256>>>(
        act1, st1, a1h, 256, 1);
    make_wimg<<<(128 * 768 + 255) / 256, 256>>>(w2, whi2, wlo2, 128, 256, 12);

    conv_mma<256, 128, 128><<<dim3(8, BATCH, 2), 256, smem128>>>(
        a1h, idx1, idx2, whi2, wlo2, b2, act2, part);
    finalize_stats<<<1, 256>>>(part, st2, 128, 8);
    transform_split<<<dim3(NNODES * 128 / 4 / 256, 256), 256>>>(
        act2, st2, a2h, 128, 1);
    make_wimg<<<(64 * 384 + 255) / 256, 256>>>(w3, whi3, wlo3, 64, 128, 6);

    conv_mma<128, 64, 64><<<dim3(8, BATCH, 2), 128, smem64>>>(
        a2h, idx1, idx2, whi3, wlo3, b3, act3, part);
    finalize_stats<<<1, 256>>>(part, st3, 64, 8);

    final_kernel<<<BATCH, 256>>>(act3, st3, wfc1, bfc1, wfc2, bfc2, out);
}

// round 15
// speedup vs baseline: 6.9923x; 1.1065x over previous
#include <cuda_runtime.h>
#include <cuda_bf16.h>
#include <math.h>
#include <stdint.h>

#define BATCH 128
#define NNODES 1024
#define NTRI 1023
#define T3 3069

typedef unsigned long long u64;

// bf16 activations: a0h = bf16(input), a1h/a2h = raw conv out, then LN'd in place
__device__ __nv_bfloat16 g_a0h[(size_t)2*BATCH*NNODES*64];
__device__ __nv_bfloat16 g_a1h[(size_t)2*BATCH*NNODES*256];
__device__ __nv_bfloat16 g_a2h[(size_t)2*BATCH*NNODES*128];
__device__ float g_act3[(size_t)2*BATCH*NNODES*64];   // f32 (final head)
// Weight images: bf16 hi/lo, per (och64,kt) 64x64 SW128-swizzled tiles
__device__ __nv_bfloat16 g_whi1[4*3*4096],  g_wlo1[4*3*4096];   // O=256,CK=192
__device__ __nv_bfloat16 g_whi2[2*12*4096], g_wlo2[2*12*4096];  // O=128,CK=768
__device__ __nv_bfloat16 g_whi3[1*6*4096],  g_wlo3[1*6*4096];   // O=64, CK=384
__device__ float g_part[2*BATCH*32*2];
__device__ float g_st1[2*BATCH*2];
__device__ float g_st2[2*BATCH*2];
__device__ float g_st3[2*BATCH*2];

// ---- helpers ----------------------------------------------------------------
__device__ __forceinline__ uint32_t smem_u32(const void* p) {
    uint32_t a;
    asm("{ .reg .u64 t; cvta.to.shared.u64 t, %1; cvt.u32.u64 %0, t; }"
        : "=r"(a) : "l"(p));
    return a;
}
#define CP16(dst, src) \
    asm volatile("cp.async.cg.shared.global [%0], [%1], 16;" :: "r"(dst), "l"(src))
#define CPCOMMIT() asm volatile("cp.async.commit_group;" ::: "memory")

__device__ __forceinline__ void ldsm4(uint32_t* r, uint32_t addr) {
    asm volatile("ldmatrix.sync.aligned.m8n8.x4.shared.b16 {%0,%1,%2,%3}, [%4];"
        : "=r"(r[0]), "=r"(r[1]), "=r"(r[2]), "=r"(r[3]) : "r"(addr));
}
__device__ __forceinline__ void mma_bf16(float* c, const uint32_t* a,
                                         uint32_t b0, uint32_t b1) {
    asm volatile(
        "mma.sync.aligned.m16n8k16.row.col.f32.bf16.bf16.f32 "
        "{%0,%1,%2,%3}, {%4,%5,%6,%7}, {%8,%9}, {%0,%1,%2,%3};"
        : "+f"(c[0]), "+f"(c[1]), "+f"(c[2]), "+f"(c[3])
        : "r"(a[0]), "r"(a[1]), "r"(a[2]), "r"(a[3]), "r"(b0), "r"(b1));
}
__device__ __forceinline__ uint32_t pack_bf16x2(float lo, float hi) {
    uint32_t r;
    asm("cvt.rn.bf16x2.f32 %0, %1, %2;" : "=r"(r) : "f"(hi), "f"(lo));
    return r;
}

// ---------------------------------------------------------------------------
// Transpose raw input [b][C=64][N=1024] -> a0h [tower*128+b][N][64] (bf16)
// ---------------------------------------------------------------------------
__global__ __launch_bounds__(256) void transpose_kernel(
    const float* __restrict__ d1, const float* __restrict__ d2,
    __nv_bfloat16* __restrict__ a0h)
{
    __shared__ float tile[32][33];
    int tb = blockIdx.z;
    int tower = tb / BATCH, b = tb % BATCH;
    const float* src = (tower ? d2 : d1) + (size_t)b * 64 * NNODES;
    __nv_bfloat16* dst = a0h + (size_t)tb * NNODES * 64;
    int n0 = blockIdx.x * 32, c0 = blockIdx.y * 32;
    for (int i = threadIdx.y; i < 32; i += 8)
        tile[i][threadIdx.x] = src[(size_t)(c0 + i) * NNODES + n0 + threadIdx.x];
    __syncthreads();
    for (int i = threadIdx.y; i < 32; i += 8)
        dst[(size_t)(n0 + i) * 64 + c0 + threadIdx.x] =
            __float2bfloat16(tile[threadIdx.x][i]);
}

// ---------------------------------------------------------------------------
// Build bf16 hi/lo weight images, SW128-swizzled 64x64 tiles.
// ---------------------------------------------------------------------------
__global__ void make_wimg(const float* __restrict__ w,
                          __nv_bfloat16* __restrict__ hi,
                          __nv_bfloat16* __restrict__ lo,
                          int O, int C, int NT)
{
    int i = blockIdx.x * 256 + threadIdx.x;
    if (i >= O * 3 * C) return;
    int tile = i >> 12, e = i & 4095;
    int row = e >> 6, col = e & 63;
    int och = tile / NT, kt = tile % NT;
    int o = och * 64 + row;
    int ck = kt * 64 + col;
    int k = ck / C, c = ck - k * C;
    float x = w[(o * C + c) * 3 + k];
    __nv_bfloat16 h = __float2bfloat16(x);
    __nv_bfloat16 l = __float2bfloat16(x - __bfloat162float(h));
    int boff = row * 128 + col * 2;
    int sw = boff ^ ((boff >> 3) & 0x70);
    hi[((size_t)tile << 12) + (sw >> 1)] = h;
    lo[((size_t)tile << 12) + (sw >> 1)] = l;
}

// ---------------------------------------------------------------------------
// Zero node-0 rows of a1h/a2h (bf16) and act3 (f32)
// ---------------------------------------------------------------------------
__global__ void zero_rows(__nv_bfloat16* a1, __nv_bfloat16* a2, float* a3)
{
    int tb = blockIdx.x;
    for (int i = threadIdx.x; i < 256; i += blockDim.x)
        a1[(size_t)tb * NNODES * 256 + i] = __float2bfloat16(0.f);
    for (int i = threadIdx.x; i < 128; i += blockDim.x)
        a2[(size_t)tb * NNODES * 128 + i] = __float2bfloat16(0.f);
    for (int i = threadIdx.x; i <  64; i += blockDim.x)
        a3[(size_t)tb * NNODES *  64 + i] = 0.f;
}

// ---------------------------------------------------------------------------
// In-place LN + leakyReLU on bf16 activations. 8 bf16 (16B) per thread.
// grid = (NNODES*O/8/256, 2*BATCH)
// ---------------------------------------------------------------------------
__global__ __launch_bounds__(256) void transform_inplace(
    __nv_bfloat16* __restrict__ act, const float* __restrict__ stats, int O)
{
    int tb = blockIdx.y;
    float mean = stats[tb * 2], inv = stats[tb * 2 + 1];
    size_t base8 = (size_t)tb * NNODES * O / 8;
    uint4* a = reinterpret_cast<uint4*>(act) + base8;
    int i = blockIdx.x * 256 + threadIdx.x;
    uint4 v = a[i];
    uint32_t* w = reinterpret_cast<uint32_t*>(&v);
#pragma unroll
    for (int j = 0; j < 4; j++) {
        float lo = __uint_as_float(w[j] << 16);
        float hi = __uint_as_float(w[j] & 0xFFFF0000u);
        lo = (lo - mean) * inv; lo = lo > 0.f ? lo : 0.01f * lo;
        hi = (hi - mean) * inv; hi = hi > 0.f ? hi : 0.01f * hi;
        w[j] = pack_bf16x2(lo, hi);
    }
    a[i] = v;
}

// ---------------------------------------------------------------------------
// mma.sync gather-conv, 2-term split: D = Ah*Bh + Ah*Bl.
// Warp tile 64x32, block tile 128 x BN, 2 blocks/SM.
// OUTBF: epilogue stores raw bf16 (pre-LN) instead of f32.
// ---------------------------------------------------------------------------
template<int C, int O, int BN, bool OUTBF>
__global__ __launch_bounds__(2 * BN, 2) void conv_mma(
    const __nv_bfloat16* __restrict__ aHiG,
    const int* __restrict__ idxA, const int* __restrict__ idxB,
    const __nv_bfloat16* __restrict__ whi, const __nv_bfloat16* __restrict__ wlo,
    const float* __restrict__ bias,
    void* __restrict__ actout, float* __restrict__ part)
{
    constexpr int TM = 128;
    constexpr int CK = 3 * C;
    constexpr int KT = 64;
    constexpr int NT = CK / KT;
    constexpr int OCHB = O / BN;
    constexpr int NSUB = BN / 64;
    constexpr int NTH = 2 * BN;
    constexpr int NGC = BN / 32;
    constexpr uint32_t BSTG = (uint32_t)BN * 256u;  // hi + lo

    extern __shared__ char dsm_raw[];
    char* dsm = (char*)(((uintptr_t)dsm_raw + 1023) & ~(uintptr_t)1023);
    __shared__ int nodes[TM * 3];
    __shared__ float red[16];

    const int tid = threadIdx.x, lane = tid & 31, warp = tid >> 5;
    const int mg = warp / NGC, ng = warp % NGC;
    const int ochb = blockIdx.x % OCHB;
    const int m0 = (blockIdx.x / OCHB) * TM;
    const int tb = blockIdx.z * BATCH + blockIdx.y;
    const int* idx = (blockIdx.z ? idxB : idxA) + blockIdx.y * T3;

    for (int t = tid; t < TM * 3; t += NTH) {
        int tt = m0 * 3 + t;
        nodes[t] = (tt < T3) ? idx[tt] : 0;
    }
    __syncthreads();

    const uint32_t sb = smem_u32(dsm);
    // layout: A hi 2 stages @ [0, 32768); B stages @ 32768 (BSTG each)
    const __nv_bfloat16* aG = aHiG + (size_t)tb * NNODES * C;

    auto issue = [&](int kt, int s) {
        const int k = (kt * KT) / C;
        const int cbase = kt * KT - k * C;
        const uint32_t bb = sb + 32768u + (uint32_t)s * BSTG;
#pragma unroll 2
        for (int e = tid; e < NSUB * 1024; e += NTH) {
            int ss = e / (NSUB * 512);             // 0=hi, 1=lo
            int e2 = e - ss * NSUB * 512;
            int st = e2 >> 9, q = e2 & 511;
            const __nv_bfloat16* src =
                (ss ? wlo : whi) + (((size_t)((ochb * NSUB + st) * NT + kt)) << 12) + q * 8;
            CP16(bb + (uint32_t)ss * (BN * 128u) + (uint32_t)st * 8192u
                    + (uint32_t)q * 16u, src);
        }
        const uint32_t adst = sb + (uint32_t)s * 16384u;
#pragma unroll 4
        for (int e = tid; e < 1024; e += NTH) {
            int r = e >> 3, q = e & 7;
            const __nv_bfloat16* src =
                aG + (size_t)nodes[r * 3 + k] * C + cbase + q * 8;
            uint32_t off = ((uint32_t)(r * 128 + q * 16)) ^ (((uint32_t)(r & 7)) << 4);
            CP16(adst + off, src);
        }
        CPCOMMIT();
    };

    float acc[4][4][4];
#pragma unroll
    for (int mi = 0; mi < 4; mi++)
#pragma unroll
        for (int i = 0; i < 4; i++)
#pragma unroll
            for (int j = 0; j < 4; j++) acc[mi][i][j] = 0.f;

    const int arow0 = mg * 64 + (lane & 15);
    const uint32_t aswz = ((uint32_t)(arow0 & 7)) << 4;
    const uint32_t akh = ((lane >> 4) & 1) * 16;
    const int brow_in = lane & 7;
    const int bps = (lane >> 4) & 1;
    const uint32_t bkh = ((lane >> 3) & 1) * 16;
    const uint32_t bswz = ((uint32_t)brow_in) << 4;

    issue(0, 0);
    for (int kt = 0; kt < NT; kt++) {
        if (kt + 1 < NT) {
            issue(kt + 1, (kt + 1) & 1);
            asm volatile("cp.async.wait_group 1;" ::: "memory");
        } else {
            asm volatile("cp.async.wait_group 0;" ::: "memory");
        }
        __syncthreads();
        const int s = kt & 1;
        const uint32_t ahb = sb + (uint32_t)s * 16384u;
        const uint32_t bhb = sb + 32768u + (uint32_t)s * BSTG;
#pragma unroll
        for (int ks = 0; ks < 4; ks++) {
            const uint32_t akb = (uint32_t)(ks * 32) + akh;
            uint32_t Ah[4][4];
#pragma unroll
            for (int mi = 0; mi < 4; mi++) {
                uint32_t aoff = (uint32_t)(arow0 + mi * 16) * 128u + (akb ^ aswz);
                ldsm4(Ah[mi], ahb + aoff);
            }
            const uint32_t bkb = (uint32_t)(ks * 32) + bkh;
            uint32_t Bh[2][4], Bl[2][4];
#pragma unroll
            for (int p2 = 0; p2 < 2; p2++) {
                int r = ng * 32 + p2 * 16 + bps * 8 + brow_in;
                uint32_t boff = (uint32_t)(r >> 6) * 8192u
                              + (uint32_t)(r & 63) * 128u + (bkb ^ bswz);
                ldsm4(Bh[p2], bhb + boff);
                ldsm4(Bl[p2], bhb + (uint32_t)(BN * 128u) + boff);
            }
#pragma unroll
            for (int mi = 0; mi < 4; mi++)
#pragma unroll
                for (int p2 = 0; p2 < 2; p2++) {
                    mma_bf16(acc[mi][p2 * 2],     Ah[mi], Bh[p2][0], Bh[p2][1]);
                    mma_bf16(acc[mi][p2 * 2 + 1], Ah[mi], Bh[p2][2], Bh[p2][3]);
                }
#pragma unroll
            for (int mi = 0; mi < 4; mi++)
#pragma unroll
                for (int p2 = 0; p2 < 2; p2++) {
                    mma_bf16(acc[mi][p2 * 2],     Ah[mi], Bl[p2][0], Bl[p2][1]);
                    mma_bf16(acc[mi][p2 * 2 + 1], Ah[mi], Bl[p2][2], Bl[p2][3]);
                }
        }
        __syncthreads();
    }

    // Epilogue: D fragments -> gmem (+bias) + fused stats
    float ls = 0.f, lss = 0.f;
    float* aoutF = (float*)actout + (size_t)tb * NNODES * O;
    __nv_bfloat16* aoutB = (__nv_bfloat16*)actout + (size_t)tb * NNODES * O;
#pragma unroll
    for (int mi = 0; mi < 4; mi++) {
        const int r0 = m0 + mg * 64 + mi * 16 + (lane >> 2);
#pragma unroll
        for (int nt = 0; nt < 4; nt++) {
            int col = ochb * BN + ng * 32 + nt * 8 + 2 * (lane & 3);
            float2 bv = *reinterpret_cast<const float2*>(bias + col);
            if (r0 < NTRI) {
                float vx = acc[mi][nt][0] + bv.x, vy = acc[mi][nt][1] + bv.y;
                if (OUTBF) {
                    *reinterpret_cast<uint32_t*>(aoutB + (size_t)(r0 + 1) * O + col)
                        = pack_bf16x2(vx, vy);
                } else {
                    float2 v; v.x = vx; v.y = vy;
                    *reinterpret_cast<float2*>(aoutF + (size_t)(r0 + 1) * O + col) = v;
                }
                ls += vx + vy;
                lss = fmaf(vx, vx, lss); lss = fmaf(vy, vy, lss);
            }
            if (r0 + 8 < NTRI) {
                float vx = acc[mi][nt][2] + bv.x, vy = acc[mi][nt][3] + bv.y;
                if (OUTBF) {
                    *reinterpret_cast<uint32_t*>(aoutB + (size_t)(r0 + 9) * O + col)
                        = pack_bf16x2(vx, vy);
                } else {
                    float2 v; v.x = vx; v.y = vy;
                    *reinterpret_cast<float2*>(aoutF + (size_t)(r0 + 9) * O + col) = v;
                }
                ls += vx + vy;
                lss = fmaf(vx, vx, lss); lss = fmaf(vy, vy, lss);
            }
        }
    }
#pragma unroll
    for (int off = 16; off > 0; off >>= 1) {
        ls  += __shfl_xor_sync(0xffffffffu, ls,  off);
        lss += __shfl_xor_sync(0xffffffffu, lss, off);
    }
    if (lane == 0) { red[warp] = ls; red[8 + warp] = lss; }
    __syncthreads();
    if (tid == 0) {
        float s = 0.f, ss = 0.f;
#pragma unroll
        for (int wv = 0; wv < NTH / 32; wv++) { s += red[wv]; ss += red[8 + wv]; }
        float* pp = part + ((size_t)tb * 32 + blockIdx.x) * 2;
        pp[0] = s; pp[1] = ss;
    }
}

// ---------------------------------------------------------------------------
// Finalize stats: reduce nparts partials per (tower,b)
// ---------------------------------------------------------------------------
__global__ __launch_bounds__(256) void finalize_stats(
    const float* __restrict__ part, float* __restrict__ stats, int O, int nparts)
{
    int tb = threadIdx.x;
    double s = 0.0, ss = 0.0;
    for (int i = 0; i < nparts; i++) {
        s += (double)part[((size_t)tb * 32 + i) * 2];
        ss += (double)part[((size_t)tb * 32 + i) * 2 + 1];
    }
    double n = 1024.0 * O;
    double mean = s / n;
    double var = (ss - s * s / n) / (n - 1.0);
    if (var < 0.0) var = 0.0;
    stats[tb * 2] = (float)mean;
    stats[tb * 2 + 1] = (float)(1.0 / (sqrt(var) + 1e-5));
}

// ---------------------------------------------------------------------------
// Final head: LN(act3) -> max-pool -> FC1(lrelu) -> FC2 -> sigmoid(diff)
// ---------------------------------------------------------------------------
__global__ __launch_bounds__(256) void final_kernel(
    const float* __restrict__ act3, const float* __restrict__ stats3,
    const float* __restrict__ wfc1, const float* __restrict__ bfc1,
    const float* __restrict__ wfc2, const float* __restrict__ bfc2,
    float* __restrict__ out)
{
    int b = blockIdx.x;
    int tid = threadIdx.x;
    __shared__ float mx[4][64];
    __shared__ float h[32];
    __shared__ float yy[2];

    for (int tower = 0; tower < 2; tower++) {
        int tb = tower * BATCH + b;
        float mean = stats3[tb * 2], inv = stats3[tb * 2 + 1];
        const float* a = act3 + (size_t)tb * NNODES * 64;
        int c = tid & 63, grp = tid >> 6;
        float m = -1e30f;
        for (int n = grp; n < NNODES; n += 4) {
            float v = (a[(size_t)n * 64 + c] - mean) * inv;
            m = fmaxf(m, v);
        }
        mx[grp][c] = m;
        __syncthreads();
        if (tid < 64) {
            mx[0][tid] = fmaxf(fmaxf(mx[0][tid], mx[1][tid]),
                               fmaxf(mx[2][tid], mx[3][tid]));
        }
        __syncthreads();
        if (tid < 32) {
            float sAcc = bfc1[tid];
            for (int c2 = 0; c2 < 64; c2++) sAcc = fmaf(mx[0][c2], wfc1[tid * 64 + c2], sAcc);
            h[tid] = sAcc > 0.f ? sAcc : 0.01f * sAcc;
        }
        __syncthreads();
        if (tid == 0) {
            float sAcc = bfc2[0];
            for (int i = 0; i < 32; i++) sAcc = fmaf(h[i], wfc2[i], sAcc);
            yy[tower] = sAcc;
        }
        __syncthreads();
    }
    if (tid == 0) {
        float d = yy[0] - yy[1];
        out[b] = 1.f / (1.f + expf(-d));
    }
}

// ---------------------------------------------------------------------------
extern "C" void kernel_launch(void* const* d_in, const int* in_sizes, int n_in,
                              void* d_out, int out_size)
{
    const float* data1 = (const float*)d_in[0];
    const int*   idx1  = (const int*)d_in[1];
    const float* data2 = (const float*)d_in[2];
    const int*   idx2  = (const int*)d_in[3];
    const float* w1 = (const float*)d_in[4];
    const float* b1 = (const float*)d_in[5];
    const float* w2 = (const float*)d_in[6];
    const float* b2 = (const float*)d_in[7];
    const float* w3 = (const float*)d_in[8];
    const float* b3 = (const float*)d_in[9];
    const float* wfc1 = (const float*)d_in[10];
    const float* bfc1 = (const float*)d_in[11];
    const float* wfc2 = (const float*)d_in[12];
    const float* bfc2 = (const float*)d_in[13];
    float* out = (float*)d_out;

    float *act3, *part, *st1, *st2, *st3;
    __nv_bfloat16 *a0h, *a1h, *a2h;
    __nv_bfloat16 *whi1, *wlo1, *whi2, *wlo2, *whi3, *wlo3;
    cudaGetSymbolAddress((void**)&act3, g_act3);
    cudaGetSymbolAddress((void**)&a0h, g_a0h);
    cudaGetSymbolAddress((void**)&a1h, g_a1h);
    cudaGetSymbolAddress((void**)&a2h, g_a2h);
    cudaGetSymbolAddress((void**)&whi1, g_whi1);
    cudaGetSymbolAddress((void**)&wlo1, g_wlo1);
    cudaGetSymbolAddress((void**)&whi2, g_whi2);
    cudaGetSymbolAddress((void**)&wlo2, g_wlo2);
    cudaGetSymbolAddress((void**)&whi3, g_whi3);
    cudaGetSymbolAddress((void**)&wlo3, g_wlo3);
    cudaGetSymbolAddress((void**)&part, g_part);
    cudaGetSymbolAddress((void**)&st1, g_st1);
    cudaGetSymbolAddress((void**)&st2, g_st2);
    cudaGetSymbolAddress((void**)&st3, g_st3);

    // dyn smem: align 1024 + A hi 2x16KB + B 2 stages * (BN*256)
    const int smem128 = 1024 + 32768 + 2 * 128 * 256;  // 99328
    const int smem64  = 1024 + 32768 + 2 * 64 * 256;   // 66560
    cudaFuncSetAttribute(conv_mma<64, 256, 128, true>,
                         cudaFuncAttributeMaxDynamicSharedMemorySize, smem128);
    cudaFuncSetAttribute(conv_mma<256, 128, 128, true>,
                         cudaFuncAttributeMaxDynamicSharedMemorySize, smem128);
    cudaFuncSetAttribute(conv_mma<128, 64, 64, false>,
                         cudaFuncAttributeMaxDynamicSharedMemorySize, smem64);

    // Launch order: conv1 is the 4th launch (ncu capture slot).
    transpose_kernel<<<dim3(32, 2, 256), dim3(32, 8)>>>(data1, data2, a0h);
    make_wimg<<<(256 * 192 + 255) / 256, 256>>>(w1, whi1, wlo1, 256, 64, 3);
    zero_rows<<<256, 256>>>(a1h, a2h, act3);

    conv_mma<64, 256, 128, true><<<dim3(16, BATCH, 2), 256, smem128>>>(
        a0h, idx1, idx2, whi1, wlo1, b1, a1h, part);
    finalize_stats<<<1, 256>>>(part, st1, 256, 16);
    transform_inplace<<<dim3(NNODES * 256 / 8 / 256, 256), 256>>>(a1h, st1, 256);
    make_wimg<<<(128 * 768 + 255) / 256, 256>>>(w2, whi2, wlo2, 128, 256, 12);

    conv_mma<256, 128, 128, true><<<dim3(8, BATCH, 2), 256, smem128>>>(
        a1h, idx1, idx2, whi2, wlo2, b2, a2h, part);
    finalize_stats<<<1, 256>>>(part, st2, 128, 8);
    transform_inplace<<<dim3(NNODES * 128 / 8 / 256, 256), 256>>>(a2h, st2, 128);
    make_wimg<<<(64 * 384 + 255) / 256, 256>>>(w3, whi3, wlo3, 64, 128, 6);

    conv_mma<128, 64, 64, false><<<dim3(8, BATCH, 2), 128, smem64>>>(
        a2h, idx1, idx2, whi3, wlo3, b3, act3, part);
    finalize_stats<<<1, 256>>>(part, st3, 64, 8);

    final_kernel<<<BATCH, 256>>>(act3, st3, wfc1, bfc1, wfc2, bfc2, out);
}

// round 16
// speedup vs baseline: 7.1287x; 1.0195x over previous
#include <cuda_runtime.h>
#include <cuda_bf16.h>
#include <math.h>
#include <stdint.h>

#define BATCH 128
#define NNODES 1024
#define NTRI 1023
#define T3 3069

typedef unsigned long long u64;

// bf16 activations: a0h = bf16(input); a1h/a2h = RAW conv outputs (LN applied
// in-fragment by the consuming conv). act3 = f32 (final head).
__device__ __nv_bfloat16 g_a0h[(size_t)2*BATCH*NNODES*64];
__device__ __nv_bfloat16 g_a1h[(size_t)2*BATCH*NNODES*256];
__device__ __nv_bfloat16 g_a2h[(size_t)2*BATCH*NNODES*128];
__device__ float g_act3[(size_t)2*BATCH*NNODES*64];
// Weight images: bf16 hi/lo, per (och64,kt) 64x64 SW128-swizzled tiles
__device__ __nv_bfloat16 g_whi1[4*3*4096],  g_wlo1[4*3*4096];   // O=256,CK=192
__device__ __nv_bfloat16 g_whi2[2*12*4096], g_wlo2[2*12*4096];  // O=128,CK=768
__device__ __nv_bfloat16 g_whi3[1*6*4096],  g_wlo3[1*6*4096];   // O=64, CK=384
__device__ float g_part[2*BATCH*32*2];
__device__ float g_st1[2*BATCH*2];
__device__ float g_st2[2*BATCH*2];
__device__ float g_st3[2*BATCH*2];

// ---- helpers ----------------------------------------------------------------
__device__ __forceinline__ uint32_t smem_u32(const void* p) {
    uint32_t a;
    asm("{ .reg .u64 t; cvta.to.shared.u64 t, %1; cvt.u32.u64 %0, t; }"
        : "=r"(a) : "l"(p));
    return a;
}
#define CP16(dst, src) \
    asm volatile("cp.async.cg.shared.global [%0], [%1], 16;" :: "r"(dst), "l"(src))
#define CPCOMMIT() asm volatile("cp.async.commit_group;" ::: "memory")

__device__ __forceinline__ void ldsm4(uint32_t* r, uint32_t addr) {
    asm volatile("ldmatrix.sync.aligned.m8n8.x4.shared.b16 {%0,%1,%2,%3}, [%4];"
        : "=r"(r[0]), "=r"(r[1]), "=r"(r[2]), "=r"(r[3]) : "r"(addr));
}
__device__ __forceinline__ void mma_bf16(float* c, const uint32_t* a,
                                         uint32_t b0, uint32_t b1) {
    asm volatile(
        "mma.sync.aligned.m16n8k16.row.col.f32.bf16.bf16.f32 "
        "{%0,%1,%2,%3}, {%4,%5,%6,%7}, {%8,%9}, {%0,%1,%2,%3};"
        : "+f"(c[0]), "+f"(c[1]), "+f"(c[2]), "+f"(c[3])
        : "r"(a[0]), "r"(a[1]), "r"(a[2]), "r"(a[3]), "r"(b0), "r"(b1));
}
__device__ __forceinline__ uint32_t pack_bf16x2(float lo, float hi) {
    uint32_t r;
    asm("cvt.rn.bf16x2.f32 %0, %1, %2;" : "=r"(r) : "f"(hi), "f"(lo));
    return r;
}
// In-fragment LN + leakyReLU on packed bf16x2: lrelu(x*inv - mean*inv)
__device__ __forceinline__ uint32_t ln_frag(uint32_t x, uint32_t inv2,
                                            uint32_t nmi2, uint32_t c01) {
    uint32_t t, u;
    asm("fma.rn.bf16x2 %0, %1, %2, %3;" : "=r"(t) : "r"(x), "r"(inv2), "r"(nmi2));
    asm("mul.bf16x2 %0, %1, %2;" : "=r"(u) : "r"(t), "r"(c01));
    asm("max.bf16x2 %0, %1, %2;" : "=r"(t) : "r"(t), "r"(u));
    return t;
}

// ---------------------------------------------------------------------------
// Transpose raw input [b][C=64][N=1024] -> a0h [tower*128+b][N][64] (bf16)
// ---------------------------------------------------------------------------
__global__ __launch_bounds__(256) void transpose_kernel(
    const float* __restrict__ d1, const float* __restrict__ d2,
    __nv_bfloat16* __restrict__ a0h)
{
    __shared__ float tile[32][33];
    int tb = blockIdx.z;
    int tower = tb / BATCH, b = tb % BATCH;
    const float* src = (tower ? d2 : d1) + (size_t)b * 64 * NNODES;
    __nv_bfloat16* dst = a0h + (size_t)tb * NNODES * 64;
    int n0 = blockIdx.x * 32, c0 = blockIdx.y * 32;
    for (int i = threadIdx.y; i < 32; i += 8)
        tile[i][threadIdx.x] = src[(size_t)(c0 + i) * NNODES + n0 + threadIdx.x];
    __syncthreads();
    for (int i = threadIdx.y; i < 32; i += 8)
        dst[(size_t)(n0 + i) * 64 + c0 + threadIdx.x] =
            __float2bfloat16(tile[threadIdx.x][i]);
}

// ---------------------------------------------------------------------------
// Build bf16 hi/lo weight images, SW128-swizzled 64x64 tiles.
// ---------------------------------------------------------------------------
__global__ void make_wimg(const float* __restrict__ w,
                          __nv_bfloat16* __restrict__ hi,
                          __nv_bfloat16* __restrict__ lo,
                          int O, int C, int NT)
{
    int i = blockIdx.x * 256 + threadIdx.x;
    if (i >= O * 3 * C) return;
    int tile = i >> 12, e = i & 4095;
    int row = e >> 6, col = e & 63;
    int och = tile / NT, kt = tile % NT;
    int o = och * 64 + row;
    int ck = kt * 64 + col;
    int k = ck / C, c = ck - k * C;
    float x = w[(o * C + c) * 3 + k];
    __nv_bfloat16 h = __float2bfloat16(x);
    __nv_bfloat16 l = __float2bfloat16(x - __bfloat162float(h));
    int boff = row * 128 + col * 2;
    int sw = boff ^ ((boff >> 3) & 0x70);
    hi[((size_t)tile << 12) + (sw >> 1)] = h;
    lo[((size_t)tile << 12) + (sw >> 1)] = l;
}

// ---------------------------------------------------------------------------
// Zero node-0 rows of a1h/a2h (bf16 raw) and act3 (f32)
// ---------------------------------------------------------------------------
__global__ void zero_rows(__nv_bfloat16* a1, __nv_bfloat16* a2, float* a3)
{
    int tb = blockIdx.x;
    for (int i = threadIdx.x; i < 256; i += blockDim.x)
        a1[(size_t)tb * NNODES * 256 + i] = __float2bfloat16(0.f);
    for (int i = threadIdx.x; i < 128; i += blockDim.x)
        a2[(size_t)tb * NNODES * 128 + i] = __float2bfloat16(0.f);
    for (int i = threadIdx.x; i <  64; i += blockDim.x)
        a3[(size_t)tb * NNODES *  64 + i] = 0.f;
}

// ---------------------------------------------------------------------------
// mma.sync gather-conv, 2-term split: D = Ah*Bh + Ah*Bl.
// Warp tile 64x32, block tile 128 x BN, 2 blocks/SM.
// LN: transform raw A fragments in-register after ldsm (lrelu((x-mean)*inv)).
// OUTBF: epilogue stores raw bf16 instead of f32.
// ---------------------------------------------------------------------------
template<int C, int O, int BN, bool OUTBF, bool LN>
__global__ __launch_bounds__(2 * BN, 2) void conv_mma(
    const __nv_bfloat16* __restrict__ aHiG,
    const int* __restrict__ idxA, const int* __restrict__ idxB,
    const __nv_bfloat16* __restrict__ whi, const __nv_bfloat16* __restrict__ wlo,
    const float* __restrict__ bias, const float* __restrict__ stats,
    void* __restrict__ actout, float* __restrict__ part)
{
    constexpr int TM = 128;
    constexpr int CK = 3 * C;
    constexpr int KT = 64;
    constexpr int NT = CK / KT;
    constexpr int OCHB = O / BN;
    constexpr int NSUB = BN / 64;
    constexpr int NTH = 2 * BN;
    constexpr int NGC = BN / 32;
    constexpr uint32_t BSTG = (uint32_t)BN * 256u;  // hi + lo

    extern __shared__ char dsm_raw[];
    char* dsm = (char*)(((uintptr_t)dsm_raw + 1023) & ~(uintptr_t)1023);
    __shared__ int nodes[TM * 3];
    __shared__ float red[16];

    const int tid = threadIdx.x, lane = tid & 31, warp = tid >> 5;
    const int mg = warp / NGC, ng = warp % NGC;
    const int ochb = blockIdx.x % OCHB;
    const int m0 = (blockIdx.x / OCHB) * TM;
    const int tb = blockIdx.z * BATCH + blockIdx.y;
    const int* idx = (blockIdx.z ? idxB : idxA) + blockIdx.y * T3;

    // LN constants (packed bf16x2)
    uint32_t inv2 = 0, nmi2 = 0, c01 = 0;
    if (LN) {
        float mean = stats[tb * 2], inv = stats[tb * 2 + 1];
        inv2 = pack_bf16x2(inv, inv);
        float nmi = -mean * inv;
        nmi2 = pack_bf16x2(nmi, nmi);
        c01 = pack_bf16x2(0.01f, 0.01f);
    }

    for (int t = tid; t < TM * 3; t += NTH) {
        int tt = m0 * 3 + t;
        nodes[t] = (tt < T3) ? idx[tt] : 0;
    }
    __syncthreads();

    const uint32_t sb = smem_u32(dsm);
    // layout: A hi 2 stages @ [0, 32768); B stages @ 32768 (BSTG each)
    const __nv_bfloat16* aG = aHiG + (size_t)tb * NNODES * C;

    auto issue = [&](int kt, int s) {
        const int k = (kt * KT) / C;
        const int cbase = kt * KT - k * C;
        const uint32_t bb = sb + 32768u + (uint32_t)s * BSTG;
#pragma unroll 2
        for (int e = tid; e < NSUB * 1024; e += NTH) {
            int ss = e / (NSUB * 512);             // 0=hi, 1=lo
            int e2 = e - ss * NSUB * 512;
            int st = e2 >> 9, q = e2 & 511;
            const __nv_bfloat16* src =
                (ss ? wlo : whi) + (((size_t)((ochb * NSUB + st) * NT + kt)) << 12) + q * 8;
            CP16(bb + (uint32_t)ss * (BN * 128u) + (uint32_t)st * 8192u
                    + (uint32_t)q * 16u, src);
        }
        const uint32_t adst = sb + (uint32_t)s * 16384u;
#pragma unroll 4
        for (int e = tid; e < 1024; e += NTH) {
            int r = e >> 3, q = e & 7;
            const __nv_bfloat16* src =
                aG + (size_t)nodes[r * 3 + k] * C + cbase + q * 8;
            uint32_t off = ((uint32_t)(r * 128 + q * 16)) ^ (((uint32_t)(r & 7)) << 4);
            CP16(adst + off, src);
        }
        CPCOMMIT();
    };

    float acc[4][4][4];
#pragma unroll
    for (int mi = 0; mi < 4; mi++)
#pragma unroll
        for (int i = 0; i < 4; i++)
#pragma unroll
            for (int j = 0; j < 4; j++) acc[mi][i][j] = 0.f;

    const int arow0 = mg * 64 + (lane & 15);
    const uint32_t aswz = ((uint32_t)(arow0 & 7)) << 4;
    const uint32_t akh = ((lane >> 4) & 1) * 16;
    const int brow_in = lane & 7;
    const int bps = (lane >> 4) & 1;
    const uint32_t bkh = ((lane >> 3) & 1) * 16;
    const uint32_t bswz = ((uint32_t)brow_in) << 4;

    issue(0, 0);
    for (int kt = 0; kt < NT; kt++) {
        if (kt + 1 < NT) {
            issue(kt + 1, (kt + 1) & 1);
            asm volatile("cp.async.wait_group 1;" ::: "memory");
        } else {
            asm volatile("cp.async.wait_group 0;" ::: "memory");
        }
        __syncthreads();
        const int s = kt & 1;
        const uint32_t ahb = sb + (uint32_t)s * 16384u;
        const uint32_t bhb = sb + 32768u + (uint32_t)s * BSTG;
#pragma unroll
        for (int ks = 0; ks < 4; ks++) {
            const uint32_t akb = (uint32_t)(ks * 32) + akh;
            uint32_t Ah[4][4];
#pragma unroll
            for (int mi = 0; mi < 4; mi++) {
                uint32_t aoff = (uint32_t)(arow0 + mi * 16) * 128u + (akb ^ aswz);
                ldsm4(Ah[mi], ahb + aoff);
                if (LN) {
#pragma unroll
                    for (int rr = 0; rr < 4; rr++)
                        Ah[mi][rr] = ln_frag(Ah[mi][rr], inv2, nmi2, c01);
                }
            }
            const uint32_t bkb = (uint32_t)(ks * 32) + bkh;
            uint32_t Bh[2][4], Bl[2][4];
#pragma unroll
            for (int p2 = 0; p2 < 2; p2++) {
                int r = ng * 32 + p2 * 16 + bps * 8 + brow_in;
                uint32_t boff = (uint32_t)(r >> 6) * 8192u
                              + (uint32_t)(r & 63) * 128u + (bkb ^ bswz);
                ldsm4(Bh[p2], bhb + boff);
                ldsm4(Bl[p2], bhb + (uint32_t)(BN * 128u) + boff);
            }
#pragma unroll
            for (int mi = 0; mi < 4; mi++)
#pragma unroll
                for (int p2 = 0; p2 < 2; p2++) {
                    mma_bf16(acc[mi][p2 * 2],     Ah[mi], Bh[p2][0], Bh[p2][1]);
                    mma_bf16(acc[mi][p2 * 2 + 1], Ah[mi], Bh[p2][2], Bh[p2][3]);
                }
#pragma unroll
            for (int mi = 0; mi < 4; mi++)
#pragma unroll
                for (int p2 = 0; p2 < 2; p2++) {
                    mma_bf16(acc[mi][p2 * 2],     Ah[mi], Bl[p2][0], Bl[p2][1]);
                    mma_bf16(acc[mi][p2 * 2 + 1], Ah[mi], Bl[p2][2], Bl[p2][3]);
                }
        }
        __syncthreads();
    }

    // Epilogue: D fragments -> gmem (+bias) + fused stats
    float ls = 0.f, lss = 0.f;
    float* aoutF = (float*)actout + (size_t)tb * NNODES * O;
    __nv_bfloat16* aoutB = (__nv_bfloat16*)actout + (size_t)tb * NNODES * O;
#pragma unroll
    for (int mi = 0; mi < 4; mi++) {
        const int r0 = m0 + mg * 64 + mi * 16 + (lane >> 2);
#pragma unroll
        for (int nt = 0; nt < 4; nt++) {
            int col = ochb * BN + ng * 32 + nt * 8 + 2 * (lane & 3);
            float2 bv = *reinterpret_cast<const float2*>(bias + col);
            if (r0 < NTRI) {
                float vx = acc[mi][nt][0] + bv.x, vy = acc[mi][nt][1] + bv.y;
                if (OUTBF) {
                    *reinterpret_cast<uint32_t*>(aoutB + (size_t)(r0 + 1) * O + col)
                        = pack_bf16x2(vx, vy);
                } else {
                    float2 v; v.x = vx; v.y = vy;
                    *reinterpret_cast<float2*>(aoutF + (size_t)(r0 + 1) * O + col) = v;
                }
                ls += vx + vy;
                lss = fmaf(vx, vx, lss); lss = fmaf(vy, vy, lss);
            }
            if (r0 + 8 < NTRI) {
                float vx = acc[mi][nt][2] + bv.x, vy = acc[mi][nt][3] + bv.y;
                if (OUTBF) {
                    *reinterpret_cast<uint32_t*>(aoutB + (size_t)(r0 + 9) * O + col)
                        = pack_bf16x2(vx, vy);
                } else {
                    float2 v; v.x = vx; v.y = vy;
                    *reinterpret_cast<float2*>(aoutF + (size_t)(r0 + 9) * O + col) = v;
                }
                ls += vx + vy;
                lss = fmaf(vx, vx, lss); lss = fmaf(vy, vy, lss);
            }
        }
    }
#pragma unroll
    for (int off = 16; off > 0; off >>= 1) {
        ls  += __shfl_xor_sync(0xffffffffu, ls,  off);
        lss += __shfl_xor_sync(0xffffffffu, lss, off);
    }
    if (lane == 0) { red[warp] = ls; red[8 + warp] = lss; }
    __syncthreads();
    if (tid == 0) {
        float s = 0.f, ss = 0.f;
#pragma unroll
        for (int wv = 0; wv < NTH / 32; wv++) { s += red[wv]; ss += red[8 + wv]; }
        float* pp = part + ((size_t)tb * 32 + blockIdx.x) * 2;
        pp[0] = s; pp[1] = ss;
    }
}

// ---------------------------------------------------------------------------
// Finalize stats: reduce nparts partials per (tower,b)
// ---------------------------------------------------------------------------
__global__ __launch_bounds__(256) void finalize_stats(
    const float* __restrict__ part, float* __restrict__ stats, int O, int nparts)
{
    int tb = threadIdx.x;
    double s = 0.0, ss = 0.0;
    for (int i = 0; i < nparts; i++) {
        s += (double)part[((size_t)tb * 32 + i) * 2];
        ss += (double)part[((size_t)tb * 32 + i) * 2 + 1];
    }
    double n = 1024.0 * O;
    double mean = s / n;
    double var = (ss - s * s / n) / (n - 1.0);
    if (var < 0.0) var = 0.0;
    stats[tb * 2] = (float)mean;
    stats[tb * 2 + 1] = (float)(1.0 / (sqrt(var) + 1e-5));
}

// ---------------------------------------------------------------------------
// Final head: LN(act3) -> max-pool -> FC1(lrelu) -> FC2 -> sigmoid(diff)
// ---------------------------------------------------------------------------
__global__ __launch_bounds__(256) void final_kernel(
    const float* __restrict__ act3, const float* __restrict__ stats3,
    const float* __restrict__ wfc1, const float* __restrict__ bfc1,
    const float* __restrict__ wfc2, const float* __restrict__ bfc2,
    float* __restrict__ out)
{
    int b = blockIdx.x;
    int tid = threadIdx.x;
    __shared__ float mx[4][64];
    __shared__ float h[32];
    __shared__ float yy[2];

    for (int tower = 0; tower < 2; tower++) {
        int tb = tower * BATCH + b;
        float mean = stats3[tb * 2], inv = stats3[tb * 2 + 1];
        const float* a = act3 + (size_t)tb * NNODES * 64;
        int c = tid & 63, grp = tid >> 6;
        float m = -1e30f;
        for (int n = grp; n < NNODES; n += 4) {
            float v = (a[(size_t)n * 64 + c] - mean) * inv;
            m = fmaxf(m, v);
        }
        mx[grp][c] = m;
        __syncthreads();
        if (tid < 64) {
            mx[0][tid] = fmaxf(fmaxf(mx[0][tid], mx[1][tid]),
                               fmaxf(mx[2][tid], mx[3][tid]));
        }
        __syncthreads();
        if (tid < 32) {
            float sAcc = bfc1[tid];
            for (int c2 = 0; c2 < 64; c2++) sAcc = fmaf(mx[0][c2], wfc1[tid * 64 + c2], sAcc);
            h[tid] = sAcc > 0.f ? sAcc : 0.01f * sAcc;
        }
        __syncthreads();
        if (tid == 0) {
            float sAcc = bfc2[0];
            for (int i = 0; i < 32; i++) sAcc = fmaf(h[i], wfc2[i], sAcc);
            yy[tower] = sAcc;
        }
        __syncthreads();
    }
    if (tid == 0) {
        float d = yy[0] - yy[1];
        out[b] = 1.f / (1.f + expf(-d));
    }
}

// ---------------------------------------------------------------------------
extern "C" void kernel_launch(void* const* d_in, const int* in_sizes, int n_in,
                              void* d_out, int out_size)
{
    const float* data1 = (const float*)d_in[0];
    const int*   idx1  = (const int*)d_in[1];
    const float* data2 = (const float*)d_in[2];
    const int*   idx2  = (const int*)d_in[3];
    const float* w1 = (const float*)d_in[4];
    const float* b1 = (const float*)d_in[5];
    const float* w2 = (const float*)d_in[6];
    const float* b2 = (const float*)d_in[7];
    const float* w3 = (const float*)d_in[8];
    const float* b3 = (const float*)d_in[9];
    const float* wfc1 = (const float*)d_in[10];
    const float* bfc1 = (const float*)d_in[11];
    const float* wfc2 = (const float*)d_in[12];
    const float* bfc2 = (const float*)d_in[13];
    float* out = (float*)d_out;

    float *act3, *part, *st1, *st2, *st3;
    __nv_bfloat16 *a0h, *a1h, *a2h;
    __nv_bfloat16 *whi1, *wlo1, *whi2, *wlo2, *whi3, *wlo3;
    cudaGetSymbolAddress((void**)&act3, g_act3);
    cudaGetSymbolAddress((void**)&a0h, g_a0h);
    cudaGetSymbolAddress((void**)&a1h, g_a1h);
    cudaGetSymbolAddress((void**)&a2h, g_a2h);
    cudaGetSymbolAddress((void**)&whi1, g_whi1);
    cudaGetSymbolAddress((void**)&wlo1, g_wlo1);
    cudaGetSymbolAddress((void**)&whi2, g_whi2);
    cudaGetSymbolAddress((void**)&wlo2, g_wlo2);
    cudaGetSymbolAddress((void**)&whi3, g_whi3);
    cudaGetSymbolAddress((void**)&wlo3, g_wlo3);
    cudaGetSymbolAddress((void**)&part, g_part);
    cudaGetSymbolAddress((void**)&st1, g_st1);
    cudaGetSymbolAddress((void**)&st2, g_st2);
    cudaGetSymbolAddress((void**)&st3, g_st3);

    // dyn smem: align 1024 + A hi 2x16KB + B 2 stages * (BN*256)
    const int smem128 = 1024 + 32768 + 2 * 128 * 256;  // 99328
    const int smem64  = 1024 + 32768 + 2 * 64 * 256;   // 66560
    cudaFuncSetAttribute(conv_mma<64, 256, 128, true, false>,
                         cudaFuncAttributeMaxDynamicSharedMemorySize, smem128);
    cudaFuncSetAttribute(conv_mma<256, 128, 128, true, true>,
                         cudaFuncAttributeMaxDynamicSharedMemorySize, smem128);
    cudaFuncSetAttribute(conv_mma<128, 64, 64, false, true>,
                         cudaFuncAttributeMaxDynamicSharedMemorySize, smem64);

    // Launch order: conv1 is the 4th launch (ncu capture slot).
    transpose_kernel<<<dim3(32, 2, 256), dim3(32, 8)>>>(data1, data2, a0h);
    make_wimg<<<(256 * 192 + 255) / 256, 256>>>(w1, whi1, wlo1, 256, 64, 3);
    zero_rows<<<256, 256>>>(a1h, a2h, act3);

    conv_mma<64, 256, 128, true, false><<<dim3(16, BATCH, 2), 256, smem128>>>(
        a0h, idx1, idx2, whi1, wlo1, b1, st1 /*unused*/, a1h, part);
    finalize_stats<<<1, 256>>>(part, st1, 256, 16);
    make_wimg<<<(128 * 768 + 255) / 256, 256>>>(w2, whi2, wlo2, 128, 256, 12);

    conv_mma<256, 128, 128, true, true><<<dim3(8, BATCH, 2), 256, smem128>>>(
        a1h, idx1, idx2, whi2, wlo2, b2, st1, a2h, part);
    finalize_stats<<<1, 256>>>(part, st2, 128, 8);
    make_wimg<<<(64 * 384 + 255) / 256, 256>>>(w3, whi3, wlo3, 64, 128, 6);

    conv_mma<128, 64, 64, false, true><<<dim3(8, BATCH, 2), 128, smem64>>>(
        a2h, idx1, idx2, whi3, wlo3, b3, st2, act3, part);
    finalize_stats<<<1, 256>>>(part, st3, 64, 8);

    final_kernel<<<BATCH, 256>>>(act3, st3, wfc1, bfc1, wfc2, bfc2, out);
}

// round 17
// speedup vs baseline: 7.7420x; 1.0860x over previous
#include <cuda_runtime.h>
#include <cuda_bf16.h>
#include <math.h>
#include <stdint.h>

#define BATCH 128
#define NNODES 1024
#define NTRI 1023
#define T3 3069

typedef unsigned long long u64;

// bf16 activations: a0h = bf16(input); a1h/a2h = RAW conv outputs (LN applied
// in-fragment by the consuming conv).
__device__ __nv_bfloat16 g_a0h[(size_t)2*BATCH*NNODES*64];
__device__ __nv_bfloat16 g_a1h[(size_t)2*BATCH*NNODES*256];
__device__ __nv_bfloat16 g_a2h[(size_t)2*BATCH*NNODES*128];
__device__ float g_maxp[2*BATCH*8*64];   // per-(tb, m-tile) raw col maxes
// Weight images: bf16 hi/lo, per (och64,kt) 64x64 SW128-swizzled tiles
__device__ __nv_bfloat16 g_whi1[4*3*4096],  g_wlo1[4*3*4096];   // O=256,CK=192
__device__ __nv_bfloat16 g_whi2[2*12*4096], g_wlo2[2*12*4096];  // O=128,CK=768
__device__ __nv_bfloat16 g_whi3[1*6*4096],  g_wlo3[1*6*4096];   // O=64, CK=384
__device__ float g_part[2*BATCH*32*2];
__device__ float g_st1[2*BATCH*2];
__device__ float g_st2[2*BATCH*2];
__device__ float g_st3[2*BATCH*2];

// ---- helpers ----------------------------------------------------------------
__device__ __forceinline__ uint32_t smem_u32(const void* p) {
    uint32_t a;
    asm("{ .reg .u64 t; cvta.to.shared.u64 t, %1; cvt.u32.u64 %0, t; }"
        : "=r"(a) : "l"(p));
    return a;
}
#define CP16(dst, src) \
    asm volatile("cp.async.cg.shared.global [%0], [%1], 16;" :: "r"(dst), "l"(src))
#define CPCOMMIT() asm volatile("cp.async.commit_group;" ::: "memory")

__device__ __forceinline__ void ldsm4(uint32_t* r, uint32_t addr) {
    asm volatile("ldmatrix.sync.aligned.m8n8.x4.shared.b16 {%0,%1,%2,%3}, [%4];"
        : "=r"(r[0]), "=r"(r[1]), "=r"(r[2]), "=r"(r[3]) : "r"(addr));
}
__device__ __forceinline__ void mma_bf16(float* c, const uint32_t* a,
                                         uint32_t b0, uint32_t b1) {
    asm volatile(
        "mma.sync.aligned.m16n8k16.row.col.f32.bf16.bf16.f32 "
        "{%0,%1,%2,%3}, {%4,%5,%6,%7}, {%8,%9}, {%0,%1,%2,%3};"
        : "+f"(c[0]), "+f"(c[1]), "+f"(c[2]), "+f"(c[3])
        : "r"(a[0]), "r"(a[1]), "r"(a[2]), "r"(a[3]), "r"(b0), "r"(b1));
}
__device__ __forceinline__ uint32_t pack_bf16x2(float lo, float hi) {
    uint32_t r;
    asm("cvt.rn.bf16x2.f32 %0, %1, %2;" : "=r"(r) : "f"(hi), "f"(lo));
    return r;
}
// In-fragment LN + leakyReLU on packed bf16x2: lrelu(x*inv - mean*inv)
__device__ __forceinline__ uint32_t ln_frag(uint32_t x, uint32_t inv2,
                                            uint32_t nmi2, uint32_t c01) {
    uint32_t t, u;
    asm("fma.rn.bf16x2 %0, %1, %2, %3;" : "=r"(t) : "r"(x), "r"(inv2), "r"(nmi2));
    asm("mul.bf16x2 %0, %1, %2;" : "=r"(u) : "r"(t), "r"(c01));
    asm("max.bf16x2 %0, %1, %2;" : "=r"(t) : "r"(t), "r"(u));
    return t;
}

// ---------------------------------------------------------------------------
// Transpose raw input [b][C=64][N=1024] -> a0h [tower*128+b][N][64] (bf16)
// ---------------------------------------------------------------------------
__global__ __launch_bounds__(256) void transpose_kernel(
    const float* __restrict__ d1, const float* __restrict__ d2,
    __nv_bfloat16* __restrict__ a0h)
{
    __shared__ float tile[32][33];
    int tb = blockIdx.z;
    int tower = tb / BATCH, b = tb % BATCH;
    const float* src = (tower ? d2 : d1) + (size_t)b * 64 * NNODES;
    __nv_bfloat16* dst = a0h + (size_t)tb * NNODES * 64;
    int n0 = blockIdx.x * 32, c0 = blockIdx.y * 32;
    for (int i = threadIdx.y; i < 32; i += 8)
        tile[i][threadIdx.x] = src[(size_t)(c0 + i) * NNODES + n0 + threadIdx.x];
    __syncthreads();
    for (int i = threadIdx.y; i < 32; i += 8)
        dst[(size_t)(n0 + i) * 64 + c0 + threadIdx.x] =
            __float2bfloat16(tile[threadIdx.x][i]);
}

// ---------------------------------------------------------------------------
// Build bf16 hi/lo weight images, SW128-swizzled 64x64 tiles.
// ---------------------------------------------------------------------------
__global__ void make_wimg(const float* __restrict__ w,
                          __nv_bfloat16* __restrict__ hi,
                          __nv_bfloat16* __restrict__ lo,
                          int O, int C, int NT)
{
    int i = blockIdx.x * 256 + threadIdx.x;
    if (i >= O * 3 * C) return;
    int tile = i >> 12, e = i & 4095;
    int row = e >> 6, col = e & 63;
    int och = tile / NT, kt = tile % NT;
    int o = och * 64 + row;
    int ck = kt * 64 + col;
    int k = ck / C, c = ck - k * C;
    float x = w[(o * C + c) * 3 + k];
    __nv_bfloat16 h = __float2bfloat16(x);
    __nv_bfloat16 l = __float2bfloat16(x - __bfloat162float(h));
    int boff = row * 128 + col * 2;
    int sw = boff ^ ((boff >> 3) & 0x70);
    hi[((size_t)tile << 12) + (sw >> 1)] = h;
    lo[((size_t)tile << 12) + (sw >> 1)] = l;
}

// ---------------------------------------------------------------------------
// Zero node-0 rows of a1h/a2h (bf16 raw)
// ---------------------------------------------------------------------------
__global__ void zero_rows(__nv_bfloat16* a1, __nv_bfloat16* a2)
{
    int tb = blockIdx.x;
    for (int i = threadIdx.x; i < 256; i += blockDim.x)
        a1[(size_t)tb * NNODES * 256 + i] = __float2bfloat16(0.f);
    for (int i = threadIdx.x; i < 128; i += blockDim.x)
        a2[(size_t)tb * NNODES * 128 + i] = __float2bfloat16(0.f);
}

// ---------------------------------------------------------------------------
// mma.sync gather-conv, 2-term split: D = Ah*Bh + Ah*Bl.
// Warp tile 64x32, block tile 128 x BN, 2 blocks/SM.
// LN: transform raw A fragments in-register after ldsm.
// OUTMODE: 1 = store raw bf16 acts; 2 = per-column max-pool partials.
// ---------------------------------------------------------------------------
template<int C, int O, int BN, int OUTMODE, bool LN>
__global__ __launch_bounds__(2 * BN, 2) void conv_mma(
    const __nv_bfloat16* __restrict__ aHiG,
    const int* __restrict__ idxA, const int* __restrict__ idxB,
    const __nv_bfloat16* __restrict__ whi, const __nv_bfloat16* __restrict__ wlo,
    const float* __restrict__ bias, const float* __restrict__ stats,
    void* __restrict__ actout, float* __restrict__ part)
{
    constexpr int TM = 128;
    constexpr int CK = 3 * C;
    constexpr int KT = 64;
    constexpr int NT = CK / KT;
    constexpr int OCHB = O / BN;
    constexpr int NSUB = BN / 64;
    constexpr int NTH = 2 * BN;
    constexpr int NGC = BN / 32;
    constexpr uint32_t BSTG = (uint32_t)BN * 256u;  // hi + lo

    extern __shared__ char dsm_raw[];
    char* dsm = (char*)(((uintptr_t)dsm_raw + 1023) & ~(uintptr_t)1023);
    __shared__ int nodes[TM * 3];
    __shared__ float red[16];
    __shared__ float mxs[4][32];   // OUTMODE==2 only (4 warps)

    const int tid = threadIdx.x, lane = tid & 31, warp = tid >> 5;
    const int mg = warp / NGC, ng = warp % NGC;
    const int ochb = blockIdx.x % OCHB;
    const int m0 = (blockIdx.x / OCHB) * TM;
    const int tb = blockIdx.z * BATCH + blockIdx.y;
    const int* idx = (blockIdx.z ? idxB : idxA) + blockIdx.y * T3;

    // LN constants (packed bf16x2)
    uint32_t inv2 = 0, nmi2 = 0, c01 = 0;
    if (LN) {
        float mean = stats[tb * 2], inv = stats[tb * 2 + 1];
        inv2 = pack_bf16x2(inv, inv);
        float nmi = -mean * inv;
        nmi2 = pack_bf16x2(nmi, nmi);
        c01 = pack_bf16x2(0.01f, 0.01f);
    }

    for (int t = tid; t < TM * 3; t += NTH) {
        int tt = m0 * 3 + t;
        nodes[t] = (tt < T3) ? idx[tt] : 0;
    }
    __syncthreads();

    const uint32_t sb = smem_u32(dsm);
    // layout: A hi 2 stages @ [0, 32768); B stages @ 32768 (BSTG each)
    const __nv_bfloat16* aG = aHiG + (size_t)tb * NNODES * C;

    auto issue = [&](int kt, int s) {
        const int k = (kt * KT) / C;
        const int cbase = kt * KT - k * C;
        const uint32_t bb = sb + 32768u + (uint32_t)s * BSTG;
#pragma unroll 2
        for (int e = tid; e < NSUB * 1024; e += NTH) {
            int ss = e / (NSUB * 512);             // 0=hi, 1=lo
            int e2 = e - ss * NSUB * 512;
            int st = e2 >> 9, q = e2 & 511;
            const __nv_bfloat16* src =
                (ss ? wlo : whi) + (((size_t)((ochb * NSUB + st) * NT + kt)) << 12) + q * 8;
            CP16(bb + (uint32_t)ss * (BN * 128u) + (uint32_t)st * 8192u
                    + (uint32_t)q * 16u, src);
        }
        const uint32_t adst = sb + (uint32_t)s * 16384u;
#pragma unroll 4
        for (int e = tid; e < 1024; e += NTH) {
            int r = e >> 3, q = e & 7;
            const __nv_bfloat16* src =
                aG + (size_t)nodes[r * 3 + k] * C + cbase + q * 8;
            uint32_t off = ((uint32_t)(r * 128 + q * 16)) ^ (((uint32_t)(r & 7)) << 4);
            CP16(adst + off, src);
        }
        CPCOMMIT();
    };

    float acc[4][4][4];
#pragma unroll
    for (int mi = 0; mi < 4; mi++)
#pragma unroll
        for (int i = 0; i < 4; i++)
#pragma unroll
            for (int j = 0; j < 4; j++) acc[mi][i][j] = 0.f;

    const int arow0 = mg * 64 + (lane & 15);
    const uint32_t aswz = ((uint32_t)(arow0 & 7)) << 4;
    const uint32_t akh = ((lane >> 4) & 1) * 16;
    const int brow_in = lane & 7;
    const int bps = (lane >> 4) & 1;
    const uint32_t bkh = ((lane >> 3) & 1) * 16;
    const uint32_t bswz = ((uint32_t)brow_in) << 4;

    issue(0, 0);
    for (int kt = 0; kt < NT; kt++) {
        if (kt + 1 < NT) {
            issue(kt + 1, (kt + 1) & 1);
            asm volatile("cp.async.wait_group 1;" ::: "memory");
        } else {
            asm volatile("cp.async.wait_group 0;" ::: "memory");
        }
        __syncthreads();
        const int s = kt & 1;
        const uint32_t ahb = sb + (uint32_t)s * 16384u;
        const uint32_t bhb = sb + 32768u + (uint32_t)s * BSTG;
#pragma unroll
        for (int ks = 0; ks < 4; ks++) {
            const uint32_t akb = (uint32_t)(ks * 32) + akh;
            uint32_t Ah[4][4];
#pragma unroll
            for (int mi = 0; mi < 4; mi++) {
                uint32_t aoff = (uint32_t)(arow0 + mi * 16) * 128u + (akb ^ aswz);
                ldsm4(Ah[mi], ahb + aoff);
                if (LN) {
#pragma unroll
                    for (int rr = 0; rr < 4; rr++)
                        Ah[mi][rr] = ln_frag(Ah[mi][rr], inv2, nmi2, c01);
                }
            }
            const uint32_t bkb = (uint32_t)(ks * 32) + bkh;
            uint32_t Bh[2][4], Bl[2][4];
#pragma unroll
            for (int p2 = 0; p2 < 2; p2++) {
                int r = ng * 32 + p2 * 16 + bps * 8 + brow_in;
                uint32_t boff = (uint32_t)(r >> 6) * 8192u
                              + (uint32_t)(r & 63) * 128u + (bkb ^ bswz);
                ldsm4(Bh[p2], bhb + boff);
                ldsm4(Bl[p2], bhb + (uint32_t)(BN * 128u) + boff);
            }
#pragma unroll
            for (int mi = 0; mi < 4; mi++)
#pragma unroll
                for (int p2 = 0; p2 < 2; p2++) {
                    mma_bf16(acc[mi][p2 * 2],     Ah[mi], Bh[p2][0], Bh[p2][1]);
                    mma_bf16(acc[mi][p2 * 2 + 1], Ah[mi], Bh[p2][2], Bh[p2][3]);
                }
#pragma unroll
            for (int mi = 0; mi < 4; mi++)
#pragma unroll
                for (int p2 = 0; p2 < 2; p2++) {
                    mma_bf16(acc[mi][p2 * 2],     Ah[mi], Bl[p2][0], Bl[p2][1]);
                    mma_bf16(acc[mi][p2 * 2 + 1], Ah[mi], Bl[p2][2], Bl[p2][3]);
                }
        }
        __syncthreads();
    }

    // Epilogue: bias + fused stats; OUTMODE 1 -> bf16 store, 2 -> col maxes
    float ls = 0.f, lss = 0.f;
    __nv_bfloat16* aoutB = (__nv_bfloat16*)actout + (size_t)tb * NNODES * O;
    float mc[4][2];
    if (OUTMODE == 2)
#pragma unroll
        for (int nt = 0; nt < 4; nt++) { mc[nt][0] = -1e30f; mc[nt][1] = -1e30f; }
#pragma unroll
    for (int mi = 0; mi < 4; mi++) {
        const int r0 = m0 + mg * 64 + mi * 16 + (lane >> 2);
#pragma unroll
        for (int nt = 0; nt < 4; nt++) {
            int col = ochb * BN + ng * 32 + nt * 8 + 2 * (lane & 3);
            float2 bv = *reinterpret_cast<const float2*>(bias + col);
            if (r0 < NTRI) {
                float vx = acc[mi][nt][0] + bv.x, vy = acc[mi][nt][1] + bv.y;
                if (OUTMODE == 1) {
                    *reinterpret_cast<uint32_t*>(aoutB + (size_t)(r0 + 1) * O + col)
                        = pack_bf16x2(vx, vy);
                } else {
                    mc[nt][0] = fmaxf(mc[nt][0], vx);
                    mc[nt][1] = fmaxf(mc[nt][1], vy);
                }
                ls += vx + vy;
                lss = fmaf(vx, vx, lss); lss = fmaf(vy, vy, lss);
            }
            if (r0 + 8 < NTRI) {
                float vx = acc[mi][nt][2] + bv.x, vy = acc[mi][nt][3] + bv.y;
                if (OUTMODE == 1) {
                    *reinterpret_cast<uint32_t*>(aoutB + (size_t)(r0 + 9) * O + col)
                        = pack_bf16x2(vx, vy);
                } else {
                    mc[nt][0] = fmaxf(mc[nt][0], vx);
                    mc[nt][1] = fmaxf(mc[nt][1], vy);
                }
                ls += vx + vy;
                lss = fmaf(vx, vx, lss); lss = fmaf(vy, vy, lss);
            }
        }
    }
    if (OUTMODE == 2) {
        // butterfly max over row lanes (bits 2..4 of lane)
#pragma unroll
        for (int off = 4; off <= 16; off <<= 1)
#pragma unroll
            for (int nt = 0; nt < 4; nt++) {
                mc[nt][0] = fmaxf(mc[nt][0], __shfl_xor_sync(0xffffffffu, mc[nt][0], off));
                mc[nt][1] = fmaxf(mc[nt][1], __shfl_xor_sync(0xffffffffu, mc[nt][1], off));
            }
        if (lane < 4) {
#pragma unroll
            for (int nt = 0; nt < 4; nt++) {
                mxs[warp][nt * 8 + 2 * lane] = mc[nt][0];
                mxs[warp][nt * 8 + 2 * lane + 1] = mc[nt][1];
            }
        }
    }
#pragma unroll
    for (int off = 16; off > 0; off >>= 1) {
        ls  += __shfl_xor_sync(0xffffffffu, ls,  off);
        lss += __shfl_xor_sync(0xffffffffu, lss, off);
    }
    if (lane == 0) { red[warp] = ls; red[8 + warp] = lss; }
    __syncthreads();
    if (OUTMODE == 2 && tid < 64) {
        int ngc = tid >> 5, cc = tid & 31;
        float m = fmaxf(mxs[ngc][cc], mxs[2 + ngc][cc]);   // warps {ng, ng+2}
        ((float*)actout)[((size_t)tb * 8 + blockIdx.x) * 64 + tid] = m;
    }
    if (tid == 0) {
        float s = 0.f, ss = 0.f;
#pragma unroll
        for (int wv = 0; wv < NTH / 32; wv++) { s += red[wv]; ss += red[8 + wv]; }
        float* pp = part + ((size_t)tb * 32 + blockIdx.x) * 2;
        pp[0] = s; pp[1] = ss;
    }
}

// ---------------------------------------------------------------------------
// Finalize stats: reduce nparts partials per (tower,b)
// ---------------------------------------------------------------------------
__global__ __launch_bounds__(256) void finalize_stats(
    const float* __restrict__ part, float* __restrict__ stats, int O, int nparts)
{
    int tb = threadIdx.x;
    double s = 0.0, ss = 0.0;
    for (int i = 0; i < nparts; i++) {
        s += (double)part[((size_t)tb * 32 + i) * 2];
        ss += (double)part[((size_t)tb * 32 + i) * 2 + 1];
    }
    double n = 1024.0 * O;
    double mean = s / n;
    double var = (ss - s * s / n) / (n - 1.0);
    if (var < 0.0) var = 0.0;
    stats[tb * 2] = (float)mean;
    stats[tb * 2 + 1] = (float)(1.0 / (sqrt(var) + 1e-5));
}

// ---------------------------------------------------------------------------
// Final head: LN(max partials, incl. zero node) -> FC1(lrelu) -> FC2 ->
//             sigmoid(diff). One block per batch element.
// ---------------------------------------------------------------------------
__global__ __launch_bounds__(64) void final_kernel(
    const float* __restrict__ maxp, const float* __restrict__ stats3,
    const float* __restrict__ wfc1, const float* __restrict__ bfc1,
    const float* __restrict__ wfc2, const float* __restrict__ bfc2,
    float* __restrict__ out)
{
    int b = blockIdx.x;
    int tid = threadIdx.x;
    __shared__ float mx[64];
    __shared__ float h[32];
    __shared__ float yy[2];

    for (int tower = 0; tower < 2; tower++) {
        int tb = tower * BATCH + b;
        float mean = stats3[tb * 2], inv = stats3[tb * 2 + 1];
        {
            float m = 0.f;   // zero node contributes raw 0
#pragma unroll
            for (int t = 0; t < 8; t++)
                m = fmaxf(m, maxp[((size_t)tb * 8 + t) * 64 + tid]);
            mx[tid] = (m - mean) * inv;
        }
        __syncthreads();
        if (tid < 32) {
            float sAcc = bfc1[tid];
            for (int c2 = 0; c2 < 64; c2++) sAcc = fmaf(mx[c2], wfc1[tid * 64 + c2], sAcc);
            h[tid] = sAcc > 0.f ? sAcc : 0.01f * sAcc;
        }
        __syncthreads();
        if (tid == 0) {
            float sAcc = bfc2[0];
            for (int i = 0; i < 32; i++) sAcc = fmaf(h[i], wfc2[i], sAcc);
            yy[tower] = sAcc;
        }
        __syncthreads();
    }
    if (tid == 0) {
        float d = yy[0] - yy[1];
        out[b] = 1.f / (1.f + expf(-d));
    }
}

// ---------------------------------------------------------------------------
extern "C" void kernel_launch(void* const* d_in, const int* in_sizes, int n_in,
                              void* d_out, int out_size)
{
    const float* data1 = (const float*)d_in[0];
    const int*   idx1  = (const int*)d_in[1];
    const float* data2 = (const float*)d_in[2];
    const int*   idx2  = (const int*)d_in[3];
    const float* w1 = (const float*)d_in[4];
    const float* b1 = (const float*)d_in[5];
    const float* w2 = (const float*)d_in[6];
    const float* b2 = (const float*)d_in[7];
    const float* w3 = (const float*)d_in[8];
    const float* b3 = (const float*)d_in[9];
    const float* wfc1 = (const float*)d_in[10];
    const float* bfc1 = (const float*)d_in[11];
    const float* wfc2 = (const float*)d_in[12];
    const float* bfc2 = (const float*)d_in[13];
    float* out = (float*)d_out;

    float *maxp, *part, *st1, *st2, *st3;
    __nv_bfloat16 *a0h, *a1h, *a2h;
    __nv_bfloat16 *whi1, *wlo1, *whi2, *wlo2, *whi3, *wlo3;
    cudaGetSymbolAddress((void**)&maxp, g_maxp);
    cudaGetSymbolAddress((void**)&a0h, g_a0h);
    cudaGetSymbolAddress((void**)&a1h, g_a1h);
    cudaGetSymbolAddress((void**)&a2h, g_a2h);
    cudaGetSymbolAddress((void**)&whi1, g_whi1);
    cudaGetSymbolAddress((void**)&wlo1, g_wlo1);
    cudaGetSymbolAddress((void**)&whi2, g_whi2);
    cudaGetSymbolAddress((void**)&wlo2, g_wlo2);
    cudaGetSymbolAddress((void**)&whi3, g_whi3);
    cudaGetSymbolAddress((void**)&wlo3, g_wlo3);
    cudaGetSymbolAddress((void**)&part, g_part);
    cudaGetSymbolAddress((void**)&st1, g_st1);
    cudaGetSymbolAddress((void**)&st2, g_st2);
    cudaGetSymbolAddress((void**)&st3, g_st3);

    // dyn smem: align 1024 + A hi 2x16KB + B 2 stages * (BN*256)
    const int smem128 = 1024 + 32768 + 2 * 128 * 256;  // 99328
    const int smem64  = 1024 + 32768 + 2 * 64 * 256;   // 66560
    cudaFuncSetAttribute(conv_mma<64, 256, 128, 1, false>,
                         cudaFuncAttributeMaxDynamicSharedMemorySize, smem128);
    cudaFuncSetAttribute(conv_mma<256, 128, 128, 1, true>,
                         cudaFuncAttributeMaxDynamicSharedMemorySize, smem128);
    cudaFuncSetAttribute(conv_mma<128, 64, 64, 2, true>,
                         cudaFuncAttributeMaxDynamicSharedMemorySize, smem64);

    // Launch order: conv1 is the 4th launch (ncu capture slot).
    transpose_kernel<<<dim3(32, 2, 256), dim3(32, 8)>>>(data1, data2, a0h);
    make_wimg<<<(256 * 192 + 255) / 256, 256>>>(w1, whi1, wlo1, 256, 64, 3);
    zero_rows<<<256, 256>>>(a1h, a2h);

    conv_mma<64, 256, 128, 1, false><<<dim3(16, BATCH, 2), 256, smem128>>>(
        a0h, idx1, idx2, whi1, wlo1, b1, st1 /*unused*/, a1h, part);
    finalize_stats<<<1, 256>>>(part, st1, 256, 16);
    make_wimg<<<(128 * 768 + 255) / 256, 256>>>(w2, whi2, wlo2, 128, 256, 12);

    conv_mma<256, 128, 128, 1, true><<<dim3(8, BATCH, 2), 256, smem128>>>(
        a1h, idx1, idx2, whi2, wlo2, b2, st1, a2h, part);
    finalize_stats<<<1, 256>>>(part, st2, 128, 8);
    make_wimg<<<(64 * 384 + 255) / 256, 256>>>(w3, whi3, wlo3, 64, 128, 6);

    conv_mma<128, 64, 64, 2, true><<<dim3(8, BATCH, 2), 128, smem64>>>(
        a2h, idx1, idx2, whi3, wlo3, b3, st2, maxp, part);
    finalize_stats<<<1, 256>>>(part, st3, 64, 8);

    final_kernel<<<BATCH, 64>>>(maxp, st3, wfc1, bfc1, wfc2, bfc2, out);
}